// round 3
// baseline (speedup 1.0000x reference)
#include <cuda_runtime.h>
#include <cuda_bf16.h>
#include <math.h>

#define NB 8
#define NTOK 4096
#define NC 256
#define NH 8
#define CHD 32
#define IMG 64
#define QLD 768   // qkv row stride (3*C)
#define KVCH 16   // kv token chunks

// ---------------- scratch (device globals; no allocation allowed) -------------
__device__ __nv_bfloat16 g_xgh[NB * NTOK * NC];      // bf16 BN+hardswish
__device__ float g_qkv[NB * NTOK * 3 * NC];
__device__ float g_cmax[NB * NH * CHD];
__device__ float g_csum[NB * NH * CHD];
__device__ float g_kvp[KVCH * NB * NH * CHD * CHD];
__device__ __nv_bfloat16 g_preh[NB * NTOK * NC];     // bf16 pre-proj
__device__ __nv_bfloat16 g_wqh[QLD * NC];            // bf16 qkv_w
__device__ __nv_bfloat16 g_wph[NC * NC];             // bf16 proj_w

// ---------------- K0: convert weights to bf16 ----------------------------------
__global__ __launch_bounds__(256) void k_cvtw(const float* __restrict__ wq,
                                              const float* __restrict__ wp) {
    int i = blockIdx.x * 256 + threadIdx.x;
    if (i < QLD * NC) g_wqh[i] = __float2bfloat16_rn(wq[i]);
    if (i < NC * NC)  g_wph[i] = __float2bfloat16_rn(wp[i]);
}

// ---------------- K1: BatchNorm(eval) + Hardswish -> bf16 ----------------------
__global__ __launch_bounds__(256) void k_bnhsw(const float* __restrict__ x,
                                               const float* __restrict__ gamma,
                                               const float* __restrict__ beta) {
    int i = blockIdx.x * blockDim.x + threadIdx.x;   // float4 index
    float4 v = ((const float4*)x)[i];
    int c0 = (i & 63) * 4;
    const float inv = rsqrtf(1.0f + 1e-5f);
    float* f = (float*)&v;
    __nv_bfloat16 o[4];
#pragma unroll
    for (int j = 0; j < 4; j++) {
        float xb = f[j] * (gamma[c0 + j] * inv) + beta[c0 + j];
        o[j] = __float2bfloat16_rn(xb * fminf(fmaxf(xb + 3.0f, 0.0f), 6.0f) * (1.0f / 6.0f));
    }
    *(uint2*)&g_xgh[(size_t)i * 4] = *(uint2*)o;
}

// ---------------- bf16 tensor-core GEMM  C[m,j] = sum_k A[m,k] W[j,k] (+bias) --
// A:[M,K], W:[Nd,K] bf16 row-major, K%64==0. 128x128x64 tiles, mma.m16n8k16.
#define BM 128
#define BN 128
#define BK 64
#define SSTH 72   // smem row stride (bf16): 144B -> 16B-aligned + LDSM conflict-free

__device__ __forceinline__ void cpa16(void* dst, const void* src) {
    unsigned d = (unsigned)__cvta_generic_to_shared(dst);
    asm volatile("cp.async.cg.shared.global [%0], [%1], 16;\n" :: "r"(d), "l"(src));
}
__device__ __forceinline__ void cp_commit() { asm volatile("cp.async.commit_group;\n"); }

__device__ __forceinline__ void ldsm4(unsigned* r, const __nv_bfloat16* p) {
    unsigned a = (unsigned)__cvta_generic_to_shared(p);
    asm volatile("ldmatrix.sync.aligned.m8n8.x4.shared.b16 {%0,%1,%2,%3}, [%4];"
                 : "=r"(r[0]), "=r"(r[1]), "=r"(r[2]), "=r"(r[3]) : "r"(a));
}

__device__ __forceinline__ void mma16(float* c, const unsigned* a, const unsigned* b) {
    asm volatile(
        "mma.sync.aligned.m16n8k16.row.col.f32.bf16.bf16.f32 "
        "{%0,%1,%2,%3}, {%4,%5,%6,%7}, {%8,%9}, {%0,%1,%2,%3};"
        : "+f"(c[0]), "+f"(c[1]), "+f"(c[2]), "+f"(c[3])
        : "r"(a[0]), "r"(a[1]), "r"(a[2]), "r"(a[3]), "r"(b[0]), "r"(b[1]));
}

extern __shared__ __align__(16) __nv_bfloat16 smem_h[];

__global__ __launch_bounds__(256) void k_gemm_bf(const __nv_bfloat16* __restrict__ A,
                                                 const __nv_bfloat16* __restrict__ W,
                                                 float* __restrict__ C,
                                                 int M, int Nd, int K,
                                                 const float* __restrict__ bias) {
    __nv_bfloat16* Asb[2] = {smem_h, smem_h + 2 * BM * SSTH};
    __nv_bfloat16* Bsb[2] = {smem_h + BM * SSTH, smem_h + 3 * BM * SSTH};

    int tid = threadIdx.x;
    int m0 = blockIdx.y * BM, n0 = blockIdx.x * BN;
    int warp = tid >> 5, lane = tid & 31;
    int g = lane >> 2, t = lane & 3;
    int wm = (warp >> 2) * 64;     // warp M offset (2 rows of warps)
    int wn = (warp & 3) * 32;      // warp N offset (4 cols of warps)

    float acc[4][4][4];
#pragma unroll
    for (int mt = 0; mt < 4; mt++)
#pragma unroll
        for (int nt = 0; nt < 4; nt++)
#pragma unroll
            for (int r = 0; r < 4; r++) acc[mt][nt][r] = 0.0f;

    const int nch = K >> 6;

    auto issue = [&](int k0, __nv_bfloat16* as, __nv_bfloat16* bs) {
#pragma unroll
        for (int j = 0; j < 4; j++) {
            int ci = tid + 256 * j;       // 0..1023
            int row = ci >> 3;            // 0..127
            int kc = (ci & 7) << 3;       // 0,8,...,56 (bf16 elems)
            cpa16(as + row * SSTH + kc, A + (size_t)(m0 + row) * K + k0 + kc);
            cpa16(bs + row * SSTH + kc, W + (size_t)(n0 + row) * K + k0 + kc);
        }
    };

    issue(0, Asb[0], Bsb[0]);
    cp_commit();

    // ldmatrix lane addressing
    int arow = lane & 15, acol = (lane >> 4) << 3;       // A: row, k-offset
    int brow = (lane & 7) + ((lane >> 4) << 3);          // B: n-offset within 16
    int bcol = ((lane >> 3) & 1) << 3;                   // B: k-offset

    for (int c = 0; c < nch; c++) {
        if (c + 1 < nch) {
            issue((c + 1) * BK, Asb[(c + 1) & 1], Bsb[(c + 1) & 1]);
            cp_commit();
            asm volatile("cp.async.wait_group 1;\n");
        } else {
            asm volatile("cp.async.wait_group 0;\n");
        }
        __syncthreads();

        const __nv_bfloat16* as = Asb[c & 1];
        const __nv_bfloat16* bs = Bsb[c & 1];
#pragma unroll
        for (int ks = 0; ks < 4; ks++) {
            int kb = ks * 16;
            unsigned af[4][4], bfr[2][4];
#pragma unroll
            for (int mt = 0; mt < 4; mt++)
                ldsm4(af[mt], as + (wm + mt * 16 + arow) * SSTH + kb + acol);
#pragma unroll
            for (int nb = 0; nb < 2; nb++)
                ldsm4(bfr[nb], bs + (wn + nb * 16 + brow) * SSTH + kb + bcol);
#pragma unroll
            for (int mt = 0; mt < 4; mt++)
#pragma unroll
                for (int nt = 0; nt < 4; nt++)
                    mma16(acc[mt][nt], af[mt], bfr[nt >> 1] + (nt & 1) * 2);
        }
        __syncthreads();
    }

    // epilogue
#pragma unroll
    for (int mt = 0; mt < 4; mt++) {
#pragma unroll
        for (int nt = 0; nt < 4; nt++) {
            int col = n0 + wn + nt * 8 + 2 * t;
            float b0 = bias ? bias[col] : 0.0f;
            float b1 = bias ? bias[col + 1] : 0.0f;
            int row0 = m0 + wm + mt * 16 + g;
            float2 o0 = make_float2(acc[mt][nt][0] + b0, acc[mt][nt][1] + b1);
            float2 o1 = make_float2(acc[mt][nt][2] + b0, acc[mt][nt][3] + b1);
            *(float2*)&C[(size_t)row0 * Nd + col] = o0;
            *(float2*)&C[(size_t)(row0 + 8) * Nd + col] = o1;
        }
    }
}

// ---------------- K3a: softmax stats (max, sum exp) per (b,h,ch) --------------
__global__ __launch_bounds__(1024) void k_softstats() {
    int bh = blockIdx.x;
    int b = bh >> 3, head = bh & 7;
    int c = threadIdx.x & 31, grp = threadIdx.x >> 5;
    const float* kb = g_qkv + (size_t)b * NTOK * QLD + 256 + head * 32 + c;

    __shared__ float red[32][33];
    __shared__ float s_cmax[32];

    float m = -1e30f;
    for (int i = 0; i < 128; i++)
        m = fmaxf(m, kb[(size_t)(grp * 128 + i) * QLD]);
    red[grp][c] = m;
    __syncthreads();
    if (threadIdx.x < 32) {
        float mm = red[0][threadIdx.x];
#pragma unroll
        for (int gg = 1; gg < 32; gg++) mm = fmaxf(mm, red[gg][threadIdx.x]);
        s_cmax[threadIdx.x] = mm;
        g_cmax[bh * 32 + threadIdx.x] = mm;
    }
    __syncthreads();
    float cm = s_cmax[c];
    float s = 0.0f;
    for (int i = 0; i < 128; i++)
        s += __expf(kb[(size_t)(grp * 128 + i) * QLD] - cm);
    red[grp][c] = s;
    __syncthreads();
    if (threadIdx.x < 32) {
        float ss = 0.0f;
#pragma unroll
        for (int gg = 0; gg < 32; gg++) ss += red[gg][threadIdx.x];
        g_csum[bh * 32 + threadIdx.x] = ss;
    }
}

// ---------------- K3b: kv = softmax(k)^T v, chunked partials -------------------
__global__ __launch_bounds__(256) void k_kv() {
    int chunk = blockIdx.x;            // 0..KVCH-1 (256 tokens each)
    int bh = blockIdx.y;
    int b = bh >> 3, head = bh & 7;

    __shared__ __align__(16) float ks[128][32];
    __shared__ __align__(16) float vs[128][32];

    int tid = threadIdx.x;
    int lc = tid & 31, lr = tid >> 5;
    float cm = g_cmax[bh * 32 + lc];
    float rs = 1.0f / g_csum[bh * 32 + lc];

    const float* base = g_qkv + (size_t)(b * NTOK + chunk * (NTOK / KVCH)) * QLD + head * 32;

    int cc = tid >> 3;
    int cq = (tid & 7) << 2;
    float a0 = 0.f, a1 = 0.f, a2 = 0.f, a3 = 0.f;

    for (int tch = 0; tch < (NTOK / KVCH) / 128; tch++) {
        const float* tb = base + (size_t)tch * 128 * QLD;
#pragma unroll
        for (int r = lr; r < 128; r += 8) {
            size_t off = (size_t)r * QLD;
            ks[r][lc] = __expf(tb[off + 256 + lc] - cm) * rs;
            vs[r][lc] = tb[off + 512 + lc];
        }
        __syncthreads();
#pragma unroll 8
        for (int n = 0; n < 128; n++) {
            float kv = ks[n][cc];
            float4 vv = *(const float4*)&vs[n][cq];
            a0 += kv * vv.x; a1 += kv * vv.y; a2 += kv * vv.z; a3 += kv * vv.w;
        }
        __syncthreads();
    }
    float4 o = make_float4(a0, a1, a2, a3);
    *(float4*)&g_kvp[((size_t)chunk * 64 + bh) * 1024 + cc * 32 + cq] = o;
}

// ---------------- K4: depthwise conv + crpe + eff -> pre (bf16) ---------------
template <int KSZ>
__device__ __forceinline__ void conv_row(const float* __restrict__ qbase,
                                         const float* __restrict__ vbase,
                                         const float* __restrict__ wrow,
                                         float biasv, const float* kvcol,
                                         int b, int head, int y, int lane) {
    const int P = KSZ / 2;
    const float scale = 0.1767766952966369f;  // 32^-0.5
    for (int x = 0; x < IMG; x++) {
        int n = y * IMG + x;
        float q = qbase[(size_t)n * QLD];
        float acc = biasv;
#pragma unroll
        for (int dy = 0; dy < KSZ; dy++) {
            int yy = y + dy - P;
            if ((unsigned)yy < (unsigned)IMG) {
#pragma unroll
                for (int dx = 0; dx < KSZ; dx++) {
                    int xx = x + dx - P;
                    if ((unsigned)xx < (unsigned)IMG)
                        acc += vbase[(size_t)(yy * IMG + xx) * QLD] * wrow[dy * KSZ + dx];
                }
            }
        }
        float e = 0.0f;
#pragma unroll
        for (int kk = 0; kk < 32; kk++)
            e += __shfl_sync(0xffffffffu, q, kk) * kvcol[kk];
        g_preh[(size_t)(b * NTOK + n) * NC + head * 32 + lane] =
            __float2bfloat16_rn(scale * e + q * acc);
    }
}

__global__ __launch_bounds__(256) void k_conv_att(const float* __restrict__ w3,
                                                  const float* __restrict__ b3,
                                                  const float* __restrict__ w5,
                                                  const float* __restrict__ b5,
                                                  const float* __restrict__ w7,
                                                  const float* __restrict__ b7) {
    int yt = blockIdx.x;
    int head = blockIdx.y;
    int b = blockIdx.z;
    int lane = threadIdx.x & 31, w = threadIdx.x >> 5;
    int bh = b * 8 + head;

    __shared__ float kv_s[1024];
    __shared__ float w_s[32 * 49];
    __shared__ float bias_s[32];

    for (int i = threadIdx.x; i < 1024; i += 256) {
        float s = 0.0f;
#pragma unroll
        for (int ch = 0; ch < KVCH; ch++) s += g_kvp[((size_t)ch * 64 + bh) * 1024 + i];
        kv_s[i] = s;
    }

    int chb;
    const float* wp;
    const float* bp;
    if (head < 2)      { wp = w3; bp = b3; chb = head * 32; }
    else if (head < 5) { wp = w5; bp = b5; chb = head * 32 - 64; }
    else               { wp = w7; bp = b7; chb = head * 32 - 160; }
    int ntap = (head < 2) ? 9 : (head < 5) ? 25 : 49;
    for (int i = threadIdx.x; i < 32 * ntap; i += 256)
        w_s[i] = wp[chb * ntap + i];
    if (threadIdx.x < 32) bias_s[threadIdx.x] = bp[chb + threadIdx.x];
    __syncthreads();

    float kvcol[32];
#pragma unroll
    for (int kk = 0; kk < 32; kk++) kvcol[kk] = kv_s[kk * 32 + lane];

    const float* qbase = g_qkv + (size_t)b * NTOK * QLD + head * 32 + lane;
    const float* vbase = qbase + 512;
    const float* wrow = w_s + lane * ntap;
    float biasv = bias_s[lane];
    int y = yt * 8 + w;

    if (head < 2)      conv_row<3>(qbase, vbase, wrow, biasv, kvcol, b, head, y, lane);
    else if (head < 5) conv_row<5>(qbase, vbase, wrow, biasv, kvcol, b, head, y, lane);
    else               conv_row<7>(qbase, vbase, wrow, biasv, kvcol, b, head, y, lane);
}

// ---------------- launch -------------------------------------------------------
extern "C" void kernel_launch(void* const* d_in, const int* in_sizes, int n_in,
                              void* d_out, int out_size) {
    const float* x      = (const float*)d_in[0];
    const float* qkv_w  = (const float*)d_in[1];
    const float* proj_w = (const float*)d_in[2];
    const float* proj_b = (const float*)d_in[3];
    const float* gamma  = (const float*)d_in[4];
    const float* beta   = (const float*)d_in[5];
    const float* w3     = (const float*)d_in[6];
    const float* b3     = (const float*)d_in[7];
    const float* w5     = (const float*)d_in[8];
    const float* b5     = (const float*)d_in[9];
    const float* w7     = (const float*)d_in[10];
    const float* b7     = (const float*)d_in[11];
    float* out = (float*)d_out;

    void *p_xg, *p_qkv, *p_pre, *p_wq, *p_wp;
    cudaGetSymbolAddress(&p_xg, g_xgh);
    cudaGetSymbolAddress(&p_qkv, g_qkv);
    cudaGetSymbolAddress(&p_pre, g_preh);
    cudaGetSymbolAddress(&p_wq, g_wqh);
    cudaGetSymbolAddress(&p_wp, g_wph);

    static int smem_set = 0;
    const int SMEM_BYTES = 4 * BM * SSTH * 2;   // 73728
    if (!smem_set) {
        cudaFuncSetAttribute(k_gemm_bf, cudaFuncAttributeMaxDynamicSharedMemorySize,
                             SMEM_BYTES);
        smem_set = 1;
    }

    // 0. weights -> bf16
    k_cvtw<<<(QLD * NC + 255) / 256, 256>>>(qkv_w, proj_w);

    // 1. BN + hardswish -> bf16
    k_bnhsw<<<(NB * NTOK * NC / 4) / 256, 256>>>(x, gamma, beta);

    // 2. qkv = xg @ qkv_w^T   [32768 x 768], K=256  (bf16 tensor cores)
    k_gemm_bf<<<dim3(QLD / BN, NB * NTOK / BM), 256, SMEM_BYTES>>>(
        (const __nv_bfloat16*)p_xg, (const __nv_bfloat16*)p_wq, (float*)p_qkv,
        NB * NTOK, QLD, NC, nullptr);

    // 3. softmax stats + kv
    k_softstats<<<64, 1024>>>();
    k_kv<<<dim3(KVCH, 64), 256>>>();

    // 4. conv + crpe + eff -> pre (bf16)
    k_conv_att<<<dim3(8, 8, 8), 256>>>(w3, b3, w5, b5, w7, b7);

    // 5. out = pre @ proj_w^T + proj_b   [32768 x 256], K=256  (bf16 tensor cores)
    k_gemm_bf<<<dim3(NC / BN, NB * NTOK / BM), 256, SMEM_BYTES>>>(
        (const __nv_bfloat16*)p_pre, (const __nv_bfloat16*)p_wp, out,
        NB * NTOK, NC, NC, proj_b);
}

// round 6
// speedup vs baseline: 1.5262x; 1.5262x over previous
#include <cuda_runtime.h>
#include <math.h>

#define NB 8
#define NTOK 4096
#define NC 256
#define NH 8
#define CHD 32
#define IMG 64
#define QLD 768   // qkv row stride (3*C)
#define KVCH 16   // kv token chunks (256 tokens each)

// ---------------- scratch (device globals; no allocation allowed) -------------
__device__ float g_xg[NB * NTOK * NC];           // tf32-rounded BN+hardswish
__device__ float g_qkv[NB * NTOK * 3 * NC];
__device__ float g_csump[KVCH * NB * NH * CHD];  // per-chunk sum(exp(k))
__device__ float g_kvp[KVCH * NB * NH * CHD * CHD];
__device__ float g_pre[NB * NTOK * NC];          // tf32-rounded pre-proj
__device__ float g_wq[QLD * NC];                 // tf32-rounded qkv_w
__device__ float g_wp[NC * NC];                  // tf32-rounded proj_w

__device__ __forceinline__ float tf32r(float x) {
    unsigned u;
    asm("cvt.rna.tf32.f32 %0, %1;" : "=r"(u) : "f"(x));
    return __uint_as_float(u);
}

// ---------------- K0: round weights to tf32 ------------------------------------
__global__ __launch_bounds__(256) void k_cvtw(const float* __restrict__ wq,
                                              const float* __restrict__ wp) {
    int i = blockIdx.x * 256 + threadIdx.x;
    if (i < QLD * NC) g_wq[i] = tf32r(wq[i]);
    if (i < NC * NC)  g_wp[i] = tf32r(wp[i]);
}

// ---------------- K1: BatchNorm(eval) + Hardswish (tf32-rounded out) -----------
__global__ __launch_bounds__(256) void k_bnhsw(const float* __restrict__ x,
                                               const float* __restrict__ gamma,
                                               const float* __restrict__ beta) {
    int i = blockIdx.x * blockDim.x + threadIdx.x;   // float4 index
    float4 v = ((const float4*)x)[i];
    int c0 = (i & 63) * 4;
    const float inv = rsqrtf(1.0f + 1e-5f);
    float* f = (float*)&v;
#pragma unroll
    for (int j = 0; j < 4; j++) {
        float xb = f[j] * (gamma[c0 + j] * inv) + beta[c0 + j];
        f[j] = tf32r(xb * fminf(fmaxf(xb + 3.0f, 0.0f), 6.0f) * (1.0f / 6.0f));
    }
    ((float4*)g_xg)[i] = v;
}

// ---------------- tensor-core TF32 GEMM  C[m,j] = sum_k A[m,k] W[j,k] (+bias) --
#define BM 128
#define BN 128
#define BK 32
#define SST 36    // smem row stride (floats): 16B-aligned + LDSM conflict-free

__device__ __forceinline__ void cpa16(float* dst, const float* src) {
    unsigned d = (unsigned)__cvta_generic_to_shared(dst);
    asm volatile("cp.async.cg.shared.global [%0], [%1], 16;\n" :: "r"(d), "l"(src));
}
__device__ __forceinline__ void cp_commit() { asm volatile("cp.async.commit_group;\n"); }

__device__ __forceinline__ void ldsm4(unsigned* r, const float* p) {
    unsigned a = (unsigned)__cvta_generic_to_shared(p);
    asm volatile("ldmatrix.sync.aligned.m8n8.x4.shared.b16 {%0,%1,%2,%3}, [%4];"
                 : "=r"(r[0]), "=r"(r[1]), "=r"(r[2]), "=r"(r[3]) : "r"(a));
}

__device__ __forceinline__ void mma8(float* c, const unsigned* a, const unsigned* b) {
    asm volatile(
        "mma.sync.aligned.m16n8k8.row.col.f32.tf32.tf32.f32 "
        "{%0,%1,%2,%3}, {%4,%5,%6,%7}, {%8,%9}, {%0,%1,%2,%3};"
        : "+f"(c[0]), "+f"(c[1]), "+f"(c[2]), "+f"(c[3])
        : "r"(a[0]), "r"(a[1]), "r"(a[2]), "r"(a[3]), "r"(b[0]), "r"(b[1]));
}

extern __shared__ __align__(16) float smem_g[];

__global__ __launch_bounds__(256, 2) void k_gemm_tc(const float* __restrict__ A,
                                                    const float* __restrict__ W,
                                                    float* __restrict__ C,
                                                    int M, int Nd, int K,
                                                    const float* __restrict__ bias) {
    float* Asb[2] = {smem_g, smem_g + 2 * BM * SST};
    float* Bsb[2] = {smem_g + BM * SST, smem_g + 3 * BM * SST};

    int tid = threadIdx.x;
    int m0 = blockIdx.y * BM, n0 = blockIdx.x * BN;
    int warp = tid >> 5, lane = tid & 31;
    int g = lane >> 2, t = lane & 3;
    int wm = (warp >> 2) * 64;
    int wn = (warp & 3) * 32;

    // ldmatrix lane addressing (tf32 4-float rows as b16x2)
    int al_row = lane & 15;              // A row within 16-row tile
    int al_col = (lane >> 4) << 2;       // A k-offset (0 or 4 floats)
    int bl_row = (lane & 7) + ((lane >> 4) << 3);   // B n-offset within 16
    int bl_col = ((lane >> 3) & 1) << 2;            // B k-offset (0 or 4)

    float acc[4][4][4];
#pragma unroll
    for (int mt = 0; mt < 4; mt++)
#pragma unroll
        for (int nt = 0; nt < 4; nt++)
#pragma unroll
            for (int r = 0; r < 4; r++) acc[mt][nt][r] = 0.0f;

    const int nch = K >> 5;

    // 128 rows x 8 float4-chunks = 1024 chunks per tile; 4 per thread
    auto issue = [&](int k0, float* as, float* bs) {
#pragma unroll
        for (int j = 0; j < 4; j++) {
            int ci = tid + 256 * j;         // 0..1023
            int row = ci >> 3;              // 0..127
            int kc = (ci & 7) << 2;         // 0,4,...,28
            cpa16(as + row * SST + kc, A + (size_t)(m0 + row) * K + k0 + kc);
            cpa16(bs + row * SST + kc, W + (size_t)(n0 + row) * K + k0 + kc);
        }
    };

    issue(0, Asb[0], Bsb[0]);
    cp_commit();

    for (int c = 0; c < nch; c++) {
        if (c + 1 < nch) {
            issue((c + 1) * BK, Asb[(c + 1) & 1], Bsb[(c + 1) & 1]);
            cp_commit();
            asm volatile("cp.async.wait_group 1;\n");
        } else {
            asm volatile("cp.async.wait_group 0;\n");
        }
        __syncthreads();

        const float* as = Asb[c & 1];
        const float* bs = Bsb[c & 1];
#pragma unroll
        for (int ks = 0; ks < 4; ks++) {
            int kb = ks * 8;
            unsigned af[4][4], bfr[2][4];
#pragma unroll
            for (int mt = 0; mt < 4; mt++)
                ldsm4(af[mt], as + (wm + mt * 16 + al_row) * SST + kb + al_col);
#pragma unroll
            for (int p = 0; p < 2; p++)
                ldsm4(bfr[p], bs + (wn + p * 16 + bl_row) * SST + kb + bl_col);
#pragma unroll
            for (int mt = 0; mt < 4; mt++)
#pragma unroll
                for (int nt = 0; nt < 4; nt++)
                    mma8(acc[mt][nt], af[mt], bfr[nt >> 1] + (nt & 1) * 2);
        }
        __syncthreads();
    }

    // epilogue
#pragma unroll
    for (int mt = 0; mt < 4; mt++) {
#pragma unroll
        for (int nt = 0; nt < 4; nt++) {
            int col = n0 + wn + nt * 8 + 2 * t;
            float b0 = bias ? bias[col] : 0.0f;
            float b1 = bias ? bias[col + 1] : 0.0f;
            int row0 = m0 + wm + mt * 16 + g;
            float2 o0 = make_float2(acc[mt][nt][0] + b0, acc[mt][nt][1] + b1);
            float2 o1 = make_float2(acc[mt][nt][2] + b0, acc[mt][nt][3] + b1);
            *(float2*)&C[(size_t)row0 * Nd + col] = o0;
            *(float2*)&C[(size_t)(row0 + 8) * Nd + col] = o1;
        }
    }
}

// ---------------- K3: kv = exp(k)^T v (unnormalized) + sum(exp(k)), chunked ----
__global__ __launch_bounds__(256) void k_kv() {
    int chunk = blockIdx.x;            // 0..KVCH-1 (256 tokens each)
    int bh = blockIdx.y;
    int b = bh >> 3, head = bh & 7;

    __shared__ __align__(16) float ks[128][32];
    __shared__ __align__(16) float vs[128][32];
    __shared__ float red[8][33];

    int tid = threadIdx.x;
    int lc = tid & 31, lr = tid >> 5;

    const float* base = g_qkv + (size_t)(b * NTOK + chunk * (NTOK / KVCH)) * QLD + head * 32;

    int cc = tid >> 3;
    int cq = (tid & 7) << 2;
    float a0 = 0.f, a1 = 0.f, a2 = 0.f, a3 = 0.f;
    float s_exp = 0.0f;

    for (int tch = 0; tch < (NTOK / KVCH) / 128; tch++) {
        const float* tb = base + (size_t)tch * 128 * QLD;
#pragma unroll
        for (int r = lr; r < 128; r += 8) {
            size_t off = (size_t)r * QLD;
            float e = __expf(tb[off + 256 + lc]);   // |k| small: no max needed
            ks[r][lc] = e;
            s_exp += e;
            vs[r][lc] = tb[off + 512 + lc];
        }
        __syncthreads();
#pragma unroll 8
        for (int n = 0; n < 128; n++) {
            float kv = ks[n][cc];
            float4 vv = *(const float4*)&vs[n][cq];
            a0 += kv * vv.x; a1 += kv * vv.y; a2 += kv * vv.z; a3 += kv * vv.w;
        }
        __syncthreads();
    }
    float4 o = make_float4(a0, a1, a2, a3);
    *(float4*)&g_kvp[((size_t)chunk * 64 + bh) * 1024 + cc * 32 + cq] = o;

    red[lr][lc] = s_exp;
    __syncthreads();
    if (tid < 32) {
        float ss = 0.0f;
#pragma unroll
        for (int gg = 0; gg < 8; gg++) ss += red[gg][tid];
        g_csump[((size_t)chunk * 64 + bh) * 32 + tid] = ss;
    }
}

// ---------------- K4: depthwise conv (sliding window) + crpe + eff -> pre ------
template <int KSZ>
__device__ __forceinline__ void conv_head(const float* __restrict__ qbase,
                                          const float* __restrict__ vbase,
                                          const float* __restrict__ wsrc,
                                          float biasv, const float* kvcol,
                                          int b, int head, int y, int lane) {
    const int P = KSZ / 2;
    const float scale = 0.1767766952966369f;  // 32^-0.5

    float wreg[KSZ * KSZ];
#pragma unroll
    for (int i = 0; i < KSZ * KSZ; i++) wreg[i] = wsrc[i];

    float win[KSZ][KSZ];
#pragma unroll
    for (int dy = 0; dy < KSZ; dy++)
#pragma unroll
        for (int j = 0; j < KSZ; j++) win[dy][j] = 0.0f;

    // preload columns 0..P-1 (slot == col)
#pragma unroll
    for (int xx = 0; xx < P; xx++) {
#pragma unroll
        for (int dy = 0; dy < KSZ; dy++) {
            int yy = y + dy - P;
            win[dy][xx] = ((unsigned)yy < (unsigned)IMG)
                              ? vbase[(size_t)(yy * IMG + xx) * QLD] : 0.0f;
        }
    }

    for (int xb = 0; xb < IMG; xb += KSZ) {
#pragma unroll
        for (int xi = 0; xi < KSZ; xi++) {
            int x = xb + xi;
            if (x < IMG) {                       // IMG % KSZ != 0: guard the tail
                // load new column x+P into slot (xi+P)%KSZ
                const int slot_new = (xi + P) % KSZ;
                int xn = x + P;
                if (xn < IMG) {
#pragma unroll
                    for (int dy = 0; dy < KSZ; dy++) {
                        int yy = y + dy - P;
                        win[dy][slot_new] = ((unsigned)yy < (unsigned)IMG)
                            ? vbase[(size_t)(yy * IMG + xn) * QLD] : 0.0f;
                    }
                } else {
#pragma unroll
                    for (int dy = 0; dy < KSZ; dy++) win[dy][slot_new] = 0.0f;
                }

                int n = y * IMG + x;
                float q = qbase[(size_t)n * QLD];
                float acc = biasv;
#pragma unroll
                for (int dy = 0; dy < KSZ; dy++)
#pragma unroll
                    for (int dx = 0; dx < KSZ; dx++) {
                        const int slot = (xi + dx + 2 * KSZ - P) % KSZ;
                        acc += win[dy][slot] * wreg[dy * KSZ + dx];
                    }
                float e = 0.0f;
#pragma unroll
                for (int kk = 0; kk < 32; kk++)
                    e += __shfl_sync(0xffffffffu, q, kk) * kvcol[kk];
                g_pre[(size_t)(b * NTOK + n) * NC + head * 32 + lane] =
                    tf32r(scale * e + q * acc);
            }
        }
    }
}

__global__ __launch_bounds__(256) void k_conv_att(const float* __restrict__ w3,
                                                  const float* __restrict__ b3,
                                                  const float* __restrict__ w5,
                                                  const float* __restrict__ b5,
                                                  const float* __restrict__ w7,
                                                  const float* __restrict__ b7) {
    int yt = blockIdx.x;
    int head = blockIdx.y;
    int b = blockIdx.z;
    int lane = threadIdx.x & 31, w = threadIdx.x >> 5;
    int bh = b * 8 + head;
    int tid = threadIdx.x;

    __shared__ float kv_s[1024];
    __shared__ float c_s[32];
    __shared__ float bias_s[32];

    if (tid < 32) {
        float s = 0.0f;
#pragma unroll
        for (int ch = 0; ch < KVCH; ch++)
            s += g_csump[((size_t)ch * 64 + bh) * 32 + tid];
        c_s[tid] = 1.0f / s;
    }
    __syncthreads();

    for (int i = tid; i < 1024; i += 256) {
        float s = 0.0f;
#pragma unroll
        for (int ch = 0; ch < KVCH; ch++) s += g_kvp[((size_t)ch * 64 + bh) * 1024 + i];
        kv_s[i] = s * c_s[i >> 5];
    }

    int chb;
    const float* wp;
    const float* bp;
    if (head < 2)      { wp = w3; bp = b3; chb = head * 32; }
    else if (head < 5) { wp = w5; bp = b5; chb = head * 32 - 64; }
    else               { wp = w7; bp = b7; chb = head * 32 - 160; }
    int ntap = (head < 2) ? 9 : (head < 5) ? 25 : 49;
    if (tid < 32) bias_s[tid] = bp[chb + tid];
    __syncthreads();

    float kvcol[32];
#pragma unroll
    for (int kk = 0; kk < 32; kk++) kvcol[kk] = kv_s[kk * 32 + lane];

    const float* qbase = g_qkv + (size_t)b * NTOK * QLD + head * 32 + lane;
    const float* vbase = qbase + 512;
    const float* wsrc = wp + (size_t)(chb + lane) * ntap;
    float biasv = bias_s[lane];
    int y = yt * 8 + w;

    if (head < 2)      conv_head<3>(qbase, vbase, wsrc, biasv, kvcol, b, head, y, lane);
    else if (head < 5) conv_head<5>(qbase, vbase, wsrc, biasv, kvcol, b, head, y, lane);
    else               conv_head<7>(qbase, vbase, wsrc, biasv, kvcol, b, head, y, lane);
}

// ---------------- launch -------------------------------------------------------
extern "C" void kernel_launch(void* const* d_in, const int* in_sizes, int n_in,
                              void* d_out, int out_size) {
    const float* x      = (const float*)d_in[0];
    const float* qkv_w  = (const float*)d_in[1];
    const float* proj_w = (const float*)d_in[2];
    const float* proj_b = (const float*)d_in[3];
    const float* gamma  = (const float*)d_in[4];
    const float* beta   = (const float*)d_in[5];
    const float* w3     = (const float*)d_in[6];
    const float* b3     = (const float*)d_in[7];
    const float* w5     = (const float*)d_in[8];
    const float* b5     = (const float*)d_in[9];
    const float* w7     = (const float*)d_in[10];
    const float* b7     = (const float*)d_in[11];
    float* out = (float*)d_out;

    void *p_xg, *p_qkv, *p_pre, *p_wq, *p_wp;
    cudaGetSymbolAddress(&p_xg, g_xg);
    cudaGetSymbolAddress(&p_qkv, g_qkv);
    cudaGetSymbolAddress(&p_pre, g_pre);
    cudaGetSymbolAddress(&p_wq, g_wq);
    cudaGetSymbolAddress(&p_wp, g_wp);

    static int smem_set = 0;
    const int SMEM_BYTES = 4 * BM * SST * 4;   // 73728
    if (!smem_set) {
        cudaFuncSetAttribute(k_gemm_tc, cudaFuncAttributeMaxDynamicSharedMemorySize,
                             SMEM_BYTES);
        smem_set = 1;
    }

    // 0. round weights
    k_cvtw<<<(QLD * NC + 255) / 256, 256>>>(qkv_w, proj_w);

    // 1. BN + hardswish (tf32 out)
    k_bnhsw<<<(NB * NTOK * NC / 4) / 256, 256>>>(x, gamma, beta);

    // 2. qkv = xg @ qkv_w^T   [32768 x 768], K=256
    k_gemm_tc<<<dim3(QLD / BN, NB * NTOK / BM), 256, SMEM_BYTES>>>(
        (const float*)p_xg, (const float*)p_wq, (float*)p_qkv,
        NB * NTOK, QLD, NC, nullptr);

    // 3. kv + sum(exp(k)) fused, 16 chunks
    k_kv<<<dim3(KVCH, 64), 256>>>();

    // 4. conv + crpe + eff -> pre (tf32 out)
    k_conv_att<<<dim3(8, 8, 8), 256>>>(w3, b3, w5, b5, w7, b7);

    // 5. out = pre @ proj_w^T + proj_b   [32768 x 256]
    k_gemm_tc<<<dim3(NC / BN, NB * NTOK / BM), 256, SMEM_BYTES>>>(
        (const float*)p_pre, (const float*)p_wp, out,
        NB * NTOK, NC, NC, proj_b);
}

// round 7
// speedup vs baseline: 1.6185x; 1.0605x over previous
#include <cuda_runtime.h>
#include <math.h>

#define NB 8
#define NTOK 4096
#define NC 256
#define NH 8
#define CHD 32
#define IMG 64
#define QLD 768   // qkv row stride (3*C)
#define KVCH 16   // kv token chunks (256 tokens each)

// ---------------- scratch (device globals; no allocation allowed) -------------
__device__ float g_xg[NB * NTOK * NC];           // tf32-rounded BN+hardswish
__device__ float g_qkv[NB * NTOK * 3 * NC];
__device__ float g_csump[KVCH * NB * NH * CHD];  // per-chunk sum(exp(k))
__device__ float g_kvp[KVCH * NB * NH * CHD * CHD];
__device__ float g_pre[NB * NTOK * NC];          // tf32-rounded pre-proj
__device__ float g_wq[QLD * NC];                 // tf32-rounded qkv_w
__device__ float g_wp[NC * NC];                  // tf32-rounded proj_w

__device__ __forceinline__ float tf32r(float x) {
    unsigned u;
    asm("cvt.rna.tf32.f32 %0, %1;" : "=r"(u) : "f"(x));
    return __uint_as_float(u);
}

// ---------------- K0: round weights to tf32 ------------------------------------
__global__ __launch_bounds__(256) void k_cvtw(const float* __restrict__ wq,
                                              const float* __restrict__ wp) {
    int i = blockIdx.x * 256 + threadIdx.x;
    if (i < QLD * NC) g_wq[i] = tf32r(wq[i]);
    if (i < NC * NC)  g_wp[i] = tf32r(wp[i]);
}

// ---------------- K1: BatchNorm(eval) + Hardswish (tf32-rounded out) -----------
__global__ __launch_bounds__(256) void k_bnhsw(const float* __restrict__ x,
                                               const float* __restrict__ gamma,
                                               const float* __restrict__ beta) {
    int i = blockIdx.x * blockDim.x + threadIdx.x;   // float4 index
    float4 v = ((const float4*)x)[i];
    int c0 = (i & 63) * 4;
    const float inv = rsqrtf(1.0f + 1e-5f);
    float* f = (float*)&v;
#pragma unroll
    for (int j = 0; j < 4; j++) {
        float xb = f[j] * (gamma[c0 + j] * inv) + beta[c0 + j];
        f[j] = tf32r(xb * fminf(fmaxf(xb + 3.0f, 0.0f), 6.0f) * (1.0f / 6.0f));
    }
    ((float4*)g_xg)[i] = v;
}

// ---------------- tensor-core TF32 GEMM, 3-stage pipeline ----------------------
#define BM 128
#define BN 128
#define BK 32
#define SST 36    // smem row stride (floats): 16B-aligned + LDSM conflict-free
#define NSTG 3

__device__ __forceinline__ void cpa16(float* dst, const float* src) {
    unsigned d = (unsigned)__cvta_generic_to_shared(dst);
    asm volatile("cp.async.cg.shared.global [%0], [%1], 16;\n" :: "r"(d), "l"(src));
}
__device__ __forceinline__ void cp_commit() { asm volatile("cp.async.commit_group;\n"); }

__device__ __forceinline__ void ldsm4(unsigned* r, const float* p) {
    unsigned a = (unsigned)__cvta_generic_to_shared(p);
    asm volatile("ldmatrix.sync.aligned.m8n8.x4.shared.b16 {%0,%1,%2,%3}, [%4];"
                 : "=r"(r[0]), "=r"(r[1]), "=r"(r[2]), "=r"(r[3]) : "r"(a));
}

__device__ __forceinline__ void mma8(float* c, const unsigned* a, const unsigned* b) {
    asm volatile(
        "mma.sync.aligned.m16n8k8.row.col.f32.tf32.tf32.f32 "
        "{%0,%1,%2,%3}, {%4,%5,%6,%7}, {%8,%9}, {%0,%1,%2,%3};"
        : "+f"(c[0]), "+f"(c[1]), "+f"(c[2]), "+f"(c[3])
        : "r"(a[0]), "r"(a[1]), "r"(a[2]), "r"(a[3]), "r"(b[0]), "r"(b[1]));
}

extern __shared__ __align__(16) float smem_g[];

__global__ __launch_bounds__(256, 2) void k_gemm_tc(const float* __restrict__ A,
                                                    const float* __restrict__ W,
                                                    float* __restrict__ C,
                                                    int M, int Nd, int K,
                                                    const float* __restrict__ bias) {
    // 3 stages, each: A tile (BM*SST) followed by B tile (BM*SST)
    int tid = threadIdx.x;
    int m0 = blockIdx.y * BM, n0 = blockIdx.x * BN;
    int warp = tid >> 5, lane = tid & 31;
    int g = lane >> 2, t = lane & 3;
    int wm = (warp >> 2) * 64;
    int wn = (warp & 3) * 32;

    // ldmatrix lane addressing (tf32 4-float rows as b16x2)
    int al_row = lane & 15;
    int al_col = (lane >> 4) << 2;
    int bl_row = (lane & 7) + ((lane >> 4) << 3);
    int bl_col = ((lane >> 3) & 1) << 2;

    float acc[4][4][4];
#pragma unroll
    for (int mt = 0; mt < 4; mt++)
#pragma unroll
        for (int nt = 0; nt < 4; nt++)
#pragma unroll
            for (int r = 0; r < 4; r++) acc[mt][nt][r] = 0.0f;

    const int nch = K >> 5;

    // 128 rows x 8 float4-chunks = 1024 chunks per tile; 4 per thread
    auto issue = [&](int c, int stage) {
        if (c < nch) {
            float* as = smem_g + stage * (2 * BM * SST);
            float* bs = as + BM * SST;
            int k0 = c * BK;
#pragma unroll
            for (int j = 0; j < 4; j++) {
                int ci = tid + 256 * j;
                int row = ci >> 3;
                int kc = (ci & 7) << 2;
                cpa16(as + row * SST + kc, A + (size_t)(m0 + row) * K + k0 + kc);
                cpa16(bs + row * SST + kc, W + (size_t)(n0 + row) * K + k0 + kc);
            }
        }
        cp_commit();   // always commit: group index == chunk index
    };

    issue(0, 0);
    issue(1, 1);

    for (int c = 0; c < nch; c++) {
        asm volatile("cp.async.wait_group 1;\n");   // group c complete
        __syncthreads();
        issue(c + 2, (c + 2) % NSTG);               // prefetch 2 ahead

        const float* as = smem_g + (c % NSTG) * (2 * BM * SST);
        const float* bs = as + BM * SST;
#pragma unroll
        for (int ks = 0; ks < 4; ks++) {
            int kb = ks * 8;
            unsigned af[4][4], bfr[2][4];
#pragma unroll
            for (int mt = 0; mt < 4; mt++)
                ldsm4(af[mt], as + (wm + mt * 16 + al_row) * SST + kb + al_col);
#pragma unroll
            for (int p = 0; p < 2; p++)
                ldsm4(bfr[p], bs + (wn + p * 16 + bl_row) * SST + kb + bl_col);
#pragma unroll
            for (int mt = 0; mt < 4; mt++)
#pragma unroll
                for (int nt = 0; nt < 4; nt++)
                    mma8(acc[mt][nt], af[mt], bfr[nt >> 1] + (nt & 1) * 2);
        }
    }

    // epilogue
#pragma unroll
    for (int mt = 0; mt < 4; mt++) {
#pragma unroll
        for (int nt = 0; nt < 4; nt++) {
            int col = n0 + wn + nt * 8 + 2 * t;
            float b0 = bias ? bias[col] : 0.0f;
            float b1 = bias ? bias[col + 1] : 0.0f;
            int row0 = m0 + wm + mt * 16 + g;
            float2 o0 = make_float2(acc[mt][nt][0] + b0, acc[mt][nt][1] + b1);
            float2 o1 = make_float2(acc[mt][nt][2] + b0, acc[mt][nt][3] + b1);
            *(float2*)&C[(size_t)row0 * Nd + col] = o0;
            *(float2*)&C[(size_t)(row0 + 8) * Nd + col] = o1;
        }
    }
}

// ---------------- K3: kv = exp(k)^T v + sum(exp(k)), register-tiled 4x4 --------
__global__ __launch_bounds__(256) void k_kv() {
    int chunk = blockIdx.x;            // 0..KVCH-1 (256 tokens each)
    int bh = blockIdx.y;
    int b = bh >> 3, head = bh & 7;

    __shared__ __align__(16) float ks[128][32];
    __shared__ __align__(16) float vs[128][32];

    int tid = threadIdx.x;
    int lc = tid & 31, lr = tid >> 5;
    int grp = tid >> 6;                // 4 groups of 64 threads
    int t64 = tid & 63;
    int kq = (t64 >> 3) << 2;          // k-channel base: 0,4,...,28
    int vq = (t64 & 7) << 2;           // v-channel base: 0,4,...,28

    const float* base = g_qkv + (size_t)(b * NTOK + chunk * (NTOK / KVCH)) * QLD + head * 32;

    float acc[4][4];
#pragma unroll
    for (int i = 0; i < 4; i++)
#pragma unroll
        for (int j = 0; j < 4; j++) acc[i][j] = 0.0f;
    float s_exp = 0.0f;

    for (int tch = 0; tch < (NTOK / KVCH) / 128; tch++) {
        const float* tb = base + (size_t)tch * 128 * QLD;
#pragma unroll
        for (int r = lr; r < 128; r += 8) {
            size_t off = (size_t)r * QLD;
            float e = __expf(tb[off + 256 + lc]);   // |k| small: no max needed
            ks[r][lc] = e;
            s_exp += e;
            vs[r][lc] = tb[off + 512 + lc];
        }
        __syncthreads();

        int rbeg = grp * 32;
#pragma unroll 4
        for (int r = rbeg; r < rbeg + 32; r++) {
            float4 kk = *(const float4*)&ks[r][kq];
            float4 vv = *(const float4*)&vs[r][vq];
            acc[0][0] += kk.x * vv.x; acc[0][1] += kk.x * vv.y;
            acc[0][2] += kk.x * vv.z; acc[0][3] += kk.x * vv.w;
            acc[1][0] += kk.y * vv.x; acc[1][1] += kk.y * vv.y;
            acc[1][2] += kk.y * vv.z; acc[1][3] += kk.y * vv.w;
            acc[2][0] += kk.z * vv.x; acc[2][1] += kk.z * vv.y;
            acc[2][2] += kk.z * vv.z; acc[2][3] += kk.z * vv.w;
            acc[3][0] += kk.w * vv.x; acc[3][1] += kk.w * vv.y;
            acc[3][2] += kk.w * vv.z; acc[3][3] += kk.w * vv.w;
        }
        __syncthreads();
    }

    // cross-group reduction: alias freed tiles (after last syncthreads)
    float* red   = &ks[0][0];     // 4 groups x 1024 partials
    float* red_s = &vs[0][0];     // 8 x 33 sexp partials
#pragma unroll
    for (int ki = 0; ki < 4; ki++)
#pragma unroll
        for (int vi = 0; vi < 4; vi++)
            red[grp * 1024 + (kq + ki) * 32 + vq + vi] = acc[ki][vi];
    red_s[lr * 33 + lc] = s_exp;
    __syncthreads();

    for (int i = tid; i < 1024; i += 256) {
        float s = red[i] + red[1024 + i] + red[2048 + i] + red[3072 + i];
        g_kvp[((size_t)chunk * 64 + bh) * 1024 + i] = s;
    }
    if (tid < 32) {
        float ss = 0.0f;
#pragma unroll
        for (int gg = 0; gg < 8; gg++) ss += red_s[gg * 33 + tid];
        g_csump[((size_t)chunk * 64 + bh) * 32 + tid] = ss;
    }
}

// ---------------- K4: depthwise conv (sliding window) + crpe + eff -> pre ------
template <int KSZ>
__device__ __forceinline__ void conv_head(const float* __restrict__ qbase,
                                          const float* __restrict__ vbase,
                                          const float* __restrict__ wsrc,
                                          float biasv, const float* kvcol,
                                          int b, int head, int y, int lane) {
    const int P = KSZ / 2;
    const float scale = 0.1767766952966369f;  // 32^-0.5

    float wreg[KSZ * KSZ];
#pragma unroll
    for (int i = 0; i < KSZ * KSZ; i++) wreg[i] = wsrc[i];

    float win[KSZ][KSZ];
#pragma unroll
    for (int dy = 0; dy < KSZ; dy++)
#pragma unroll
        for (int j = 0; j < KSZ; j++) win[dy][j] = 0.0f;

    // preload columns 0..P-1 (slot == col)
#pragma unroll
    for (int xx = 0; xx < P; xx++) {
#pragma unroll
        for (int dy = 0; dy < KSZ; dy++) {
            int yy = y + dy - P;
            win[dy][xx] = ((unsigned)yy < (unsigned)IMG)
                              ? vbase[(size_t)(yy * IMG + xx) * QLD] : 0.0f;
        }
    }

    for (int xb = 0; xb < IMG; xb += KSZ) {
#pragma unroll
        for (int xi = 0; xi < KSZ; xi++) {
            int x = xb + xi;
            if (x < IMG) {                       // IMG % KSZ != 0: guard the tail
                const int slot_new = (xi + P) % KSZ;
                int xn = x + P;
                if (xn < IMG) {
#pragma unroll
                    for (int dy = 0; dy < KSZ; dy++) {
                        int yy = y + dy - P;
                        win[dy][slot_new] = ((unsigned)yy < (unsigned)IMG)
                            ? vbase[(size_t)(yy * IMG + xn) * QLD] : 0.0f;
                    }
                } else {
#pragma unroll
                    for (int dy = 0; dy < KSZ; dy++) win[dy][slot_new] = 0.0f;
                }

                int n = y * IMG + x;
                float q = qbase[(size_t)n * QLD];
                float acc = biasv;
#pragma unroll
                for (int dy = 0; dy < KSZ; dy++)
#pragma unroll
                    for (int dx = 0; dx < KSZ; dx++) {
                        const int slot = (xi + dx + 2 * KSZ - P) % KSZ;
                        acc += win[dy][slot] * wreg[dy * KSZ + dx];
                    }
                float e = 0.0f;
#pragma unroll
                for (int kk = 0; kk < 32; kk++)
                    e += __shfl_sync(0xffffffffu, q, kk) * kvcol[kk];
                g_pre[(size_t)(b * NTOK + n) * NC + head * 32 + lane] =
                    tf32r(scale * e + q * acc);
            }
        }
    }
}

__global__ __launch_bounds__(256) void k_conv_att(const float* __restrict__ w3,
                                                  const float* __restrict__ b3,
                                                  const float* __restrict__ w5,
                                                  const float* __restrict__ b5,
                                                  const float* __restrict__ w7,
                                                  const float* __restrict__ b7) {
    int yt = blockIdx.x;
    int head = blockIdx.y;
    int b = blockIdx.z;
    int lane = threadIdx.x & 31, w = threadIdx.x >> 5;
    int bh = b * 8 + head;
    int tid = threadIdx.x;

    __shared__ float kv_s[1024];
    __shared__ float c_s[32];
    __shared__ float bias_s[32];

    if (tid < 32) {
        float s = 0.0f;
#pragma unroll
        for (int ch = 0; ch < KVCH; ch++)
            s += g_csump[((size_t)ch * 64 + bh) * 32 + tid];
        c_s[tid] = 1.0f / s;
    }
    __syncthreads();

    for (int i = tid; i < 1024; i += 256) {
        float s = 0.0f;
#pragma unroll
        for (int ch = 0; ch < KVCH; ch++) s += g_kvp[((size_t)ch * 64 + bh) * 1024 + i];
        kv_s[i] = s * c_s[i >> 5];
    }

    int chb;
    const float* wp;
    const float* bp;
    if (head < 2)      { wp = w3; bp = b3; chb = head * 32; }
    else if (head < 5) { wp = w5; bp = b5; chb = head * 32 - 64; }
    else               { wp = w7; bp = b7; chb = head * 32 - 160; }
    int ntap = (head < 2) ? 9 : (head < 5) ? 25 : 49;
    if (tid < 32) bias_s[tid] = bp[chb + tid];
    __syncthreads();

    float kvcol[32];
#pragma unroll
    for (int kk = 0; kk < 32; kk++) kvcol[kk] = kv_s[kk * 32 + lane];

    const float* qbase = g_qkv + (size_t)b * NTOK * QLD + head * 32 + lane;
    const float* vbase = qbase + 512;
    const float* wsrc = wp + (size_t)(chb + lane) * ntap;
    float biasv = bias_s[lane];
    int y = yt * 8 + w;

    if (head < 2)      conv_head<3>(qbase, vbase, wsrc, biasv, kvcol, b, head, y, lane);
    else if (head < 5) conv_head<5>(qbase, vbase, wsrc, biasv, kvcol, b, head, y, lane);
    else               conv_head<7>(qbase, vbase, wsrc, biasv, kvcol, b, head, y, lane);
}

// ---------------- launch -------------------------------------------------------
extern "C" void kernel_launch(void* const* d_in, const int* in_sizes, int n_in,
                              void* d_out, int out_size) {
    const float* x      = (const float*)d_in[0];
    const float* qkv_w  = (const float*)d_in[1];
    const float* proj_w = (const float*)d_in[2];
    const float* proj_b = (const float*)d_in[3];
    const float* gamma  = (const float*)d_in[4];
    const float* beta   = (const float*)d_in[5];
    const float* w3     = (const float*)d_in[6];
    const float* b3     = (const float*)d_in[7];
    const float* w5     = (const float*)d_in[8];
    const float* b5     = (const float*)d_in[9];
    const float* w7     = (const float*)d_in[10];
    const float* b7     = (const float*)d_in[11];
    float* out = (float*)d_out;

    void *p_xg, *p_qkv, *p_pre, *p_wq, *p_wp;
    cudaGetSymbolAddress(&p_xg, g_xg);
    cudaGetSymbolAddress(&p_qkv, g_qkv);
    cudaGetSymbolAddress(&p_pre, g_pre);
    cudaGetSymbolAddress(&p_wq, g_wq);
    cudaGetSymbolAddress(&p_wp, g_wp);

    static int smem_set = 0;
    const int SMEM_BYTES = NSTG * 2 * BM * SST * 4;   // 110592
    if (!smem_set) {
        cudaFuncSetAttribute(k_gemm_tc, cudaFuncAttributeMaxDynamicSharedMemorySize,
                             SMEM_BYTES);
        smem_set = 1;
    }

    // 0. round weights
    k_cvtw<<<(QLD * NC + 255) / 256, 256>>>(qkv_w, proj_w);

    // 1. BN + hardswish (tf32 out)
    k_bnhsw<<<(NB * NTOK * NC / 4) / 256, 256>>>(x, gamma, beta);

    // 2. qkv = xg @ qkv_w^T   [32768 x 768], K=256
    k_gemm_tc<<<dim3(QLD / BN, NB * NTOK / BM), 256, SMEM_BYTES>>>(
        (const float*)p_xg, (const float*)p_wq, (float*)p_qkv,
        NB * NTOK, QLD, NC, nullptr);

    // 3. kv + sum(exp(k)) fused, 16 chunks, register-tiled
    k_kv<<<dim3(KVCH, 64), 256>>>();

    // 4. conv + crpe + eff -> pre (tf32 out)
    k_conv_att<<<dim3(8, 8, 8), 256>>>(w3, b3, w5, b5, w7, b7);

    // 5. out = pre @ proj_w^T + proj_b   [32768 x 256]
    k_gemm_tc<<<dim3(NC / BN, NB * NTOK / BM), 256, SMEM_BYTES>>>(
        (const float*)p_pre, (const float*)p_wp, out,
        NB * NTOK, NC, NC, proj_b);
}

// round 8
// speedup vs baseline: 1.9273x; 1.1908x over previous
#include <cuda_runtime.h>
#include <cuda_fp16.h>
#include <math.h>

#define NB 8
#define NTOK 4096
#define NC 256
#define NH 8
#define CHD 32
#define IMG 64
#define QLD 768   // qkv row stride (3*C)
#define KVCH 16   // kv token chunks (256 tokens each)

// ---------------- scratch (device globals; no allocation allowed) -------------
__device__ __half g_xgh[NB * NTOK * NC];         // fp16 BN+hardswish
__device__ float g_qkv[NB * NTOK * 3 * NC];
__device__ float g_csump[KVCH * NB * NH * CHD];  // per-chunk sum(exp(k))
__device__ float g_kvp[KVCH * NB * NH * CHD * CHD];
__device__ __half g_preh[NB * NTOK * NC];        // fp16 pre-proj
__device__ __half g_wqh[QLD * NC];               // fp16 qkv_w
__device__ __half g_wph[NC * NC];                // fp16 proj_w

// ---------------- K0: convert weights to fp16 -----------------------------------
__global__ __launch_bounds__(256) void k_cvtw(const float* __restrict__ wq,
                                              const float* __restrict__ wp) {
    int i = blockIdx.x * 256 + threadIdx.x;
    if (i < QLD * NC) g_wqh[i] = __float2half_rn(wq[i]);
    if (i < NC * NC)  g_wph[i] = __float2half_rn(wp[i]);
}

// ---------------- K1: BatchNorm(eval) + Hardswish -> fp16 ----------------------
__global__ __launch_bounds__(256) void k_bnhsw(const float* __restrict__ x,
                                               const float* __restrict__ gamma,
                                               const float* __restrict__ beta) {
    int i = blockIdx.x * blockDim.x + threadIdx.x;   // float4 index
    float4 v = ((const float4*)x)[i];
    int c0 = (i & 63) * 4;
    const float inv = rsqrtf(1.0f + 1e-5f);
    float* f = (float*)&v;
    __half o[4];
#pragma unroll
    for (int j = 0; j < 4; j++) {
        float xb = f[j] * (gamma[c0 + j] * inv) + beta[c0 + j];
        o[j] = __float2half_rn(xb * fminf(fmaxf(xb + 3.0f, 0.0f), 6.0f) * (1.0f / 6.0f));
    }
    *(uint2*)&g_xgh[(size_t)i * 4] = *(uint2*)o;
}

// ---------------- fp16 tensor-core GEMM, 3-stage pipeline ----------------------
// C[m,j] = sum_k A[m,k] * W[j,k] (+bias), A/W fp16 row-major, fp32 accum.
#define BM 128
#define BN 128
#define BK 64     // halves per chunk (128 bytes per row)
#define SSTH 72   // smem row stride (halves): 144B -> 16B-aligned, LDSM conflict-free
#define NSTG 3

__device__ __forceinline__ void cpa16(void* dst, const void* src) {
    unsigned d = (unsigned)__cvta_generic_to_shared(dst);
    asm volatile("cp.async.cg.shared.global [%0], [%1], 16;\n" :: "r"(d), "l"(src));
}
__device__ __forceinline__ void cp_commit() { asm volatile("cp.async.commit_group;\n"); }

__device__ __forceinline__ void ldsm4(unsigned* r, const __half* p) {
    unsigned a = (unsigned)__cvta_generic_to_shared(p);
    asm volatile("ldmatrix.sync.aligned.m8n8.x4.shared.b16 {%0,%1,%2,%3}, [%4];"
                 : "=r"(r[0]), "=r"(r[1]), "=r"(r[2]), "=r"(r[3]) : "r"(a));
}

__device__ __forceinline__ void mma16(float* c, const unsigned* a, const unsigned* b) {
    asm volatile(
        "mma.sync.aligned.m16n8k16.row.col.f32.f16.f16.f32 "
        "{%0,%1,%2,%3}, {%4,%5,%6,%7}, {%8,%9}, {%0,%1,%2,%3};"
        : "+f"(c[0]), "+f"(c[1]), "+f"(c[2]), "+f"(c[3])
        : "r"(a[0]), "r"(a[1]), "r"(a[2]), "r"(a[3]), "r"(b[0]), "r"(b[1]));
}

extern __shared__ __align__(16) __half smem_h[];

__global__ __launch_bounds__(256, 2) void k_gemm_fp16(const __half* __restrict__ A,
                                                      const __half* __restrict__ W,
                                                      float* __restrict__ C,
                                                      int M, int Nd, int K,
                                                      const float* __restrict__ bias) {
    int tid = threadIdx.x;
    int m0 = blockIdx.y * BM, n0 = blockIdx.x * BN;
    int warp = tid >> 5, lane = tid & 31;
    int g = lane >> 2, t = lane & 3;
    int wm = (warp >> 2) * 64;     // 2 warp-rows
    int wn = (warp & 3) * 32;      // 4 warp-cols

    // ldmatrix lane addressing (verified in R3 bf16 run)
    int al_row = lane & 15;                 // A row within 16
    int al_col = (lane >> 4) << 3;          // A k-offset (0 or 8 halves)
    int bl_row = (lane & 7) + ((lane >> 4) << 3);   // B n-offset within 16
    int bl_col = ((lane >> 3) & 1) << 3;            // B k-offset (0 or 8)

    float acc[4][4][4];
#pragma unroll
    for (int mt = 0; mt < 4; mt++)
#pragma unroll
        for (int nt = 0; nt < 4; nt++)
#pragma unroll
            for (int r = 0; r < 4; r++) acc[mt][nt][r] = 0.0f;

    const int nch = K >> 6;   // chunks of 64 halves

    // 128 rows x 8 16B-chunks = 1024 per tile; 4 per thread each for A and B
    auto issue = [&](int c, int stage) {
        if (c < nch) {
            __half* as = smem_h + stage * (2 * BM * SSTH);
            __half* bs = as + BM * SSTH;
            int k0 = c * BK;
#pragma unroll
            for (int j = 0; j < 4; j++) {
                int ci = tid + 256 * j;
                int row = ci >> 3;              // 0..127
                int kc = (ci & 7) << 3;         // 0,8,...,56 halves
                cpa16(as + row * SSTH + kc, A + (size_t)(m0 + row) * K + k0 + kc);
                cpa16(bs + row * SSTH + kc, W + (size_t)(n0 + row) * K + k0 + kc);
            }
        }
        cp_commit();   // always commit: group index == chunk index
    };

    issue(0, 0);
    issue(1, 1);

    for (int c = 0; c < nch; c++) {
        asm volatile("cp.async.wait_group 1;\n");
        __syncthreads();
        issue(c + 2, (c + 2) % NSTG);

        const __half* as = smem_h + (c % NSTG) * (2 * BM * SSTH);
        const __half* bs = as + BM * SSTH;
#pragma unroll
        for (int ks = 0; ks < 4; ks++) {
            int kb = ks * 16;
            unsigned af[4][4], bfr[2][4];
#pragma unroll
            for (int mt = 0; mt < 4; mt++)
                ldsm4(af[mt], as + (wm + mt * 16 + al_row) * SSTH + kb + al_col);
#pragma unroll
            for (int p = 0; p < 2; p++)
                ldsm4(bfr[p], bs + (wn + p * 16 + bl_row) * SSTH + kb + bl_col);
#pragma unroll
            for (int mt = 0; mt < 4; mt++)
#pragma unroll
                for (int nt = 0; nt < 4; nt++)
                    mma16(acc[mt][nt], af[mt], bfr[nt >> 1] + (nt & 1) * 2);
        }
    }

    // epilogue
#pragma unroll
    for (int mt = 0; mt < 4; mt++) {
#pragma unroll
        for (int nt = 0; nt < 4; nt++) {
            int col = n0 + wn + nt * 8 + 2 * t;
            float b0 = bias ? bias[col] : 0.0f;
            float b1 = bias ? bias[col + 1] : 0.0f;
            int row0 = m0 + wm + mt * 16 + g;
            float2 o0 = make_float2(acc[mt][nt][0] + b0, acc[mt][nt][1] + b1);
            float2 o1 = make_float2(acc[mt][nt][2] + b0, acc[mt][nt][3] + b1);
            *(float2*)&C[(size_t)row0 * Nd + col] = o0;
            *(float2*)&C[(size_t)(row0 + 8) * Nd + col] = o1;
        }
    }
}

// ---------------- K3: kv = exp(k)^T v + sum(exp(k)), register-tiled 4x4 --------
__global__ __launch_bounds__(256) void k_kv() {
    int chunk = blockIdx.x;            // 0..KVCH-1 (256 tokens each)
    int bh = blockIdx.y;
    int b = bh >> 3, head = bh & 7;

    __shared__ __align__(16) float ks[128][32];
    __shared__ __align__(16) float vs[128][32];

    int tid = threadIdx.x;
    int lc = tid & 31, lr = tid >> 5;
    int grp = tid >> 6;                // 4 groups of 64 threads
    int t64 = tid & 63;
    int kq = (t64 >> 3) << 2;          // k-channel base
    int vq = (t64 & 7) << 2;           // v-channel base

    const float* base = g_qkv + (size_t)(b * NTOK + chunk * (NTOK / KVCH)) * QLD + head * 32;

    float acc[4][4];
#pragma unroll
    for (int i = 0; i < 4; i++)
#pragma unroll
        for (int j = 0; j < 4; j++) acc[i][j] = 0.0f;
    float s_exp = 0.0f;

    for (int tch = 0; tch < (NTOK / KVCH) / 128; tch++) {
        const float* tb = base + (size_t)tch * 128 * QLD;
#pragma unroll
        for (int r = lr; r < 128; r += 8) {
            size_t off = (size_t)r * QLD;
            float e = __expf(tb[off + 256 + lc]);   // |k| small: no max needed
            ks[r][lc] = e;
            s_exp += e;
            vs[r][lc] = tb[off + 512 + lc];
        }
        __syncthreads();

        int rbeg = grp * 32;
#pragma unroll 4
        for (int r = rbeg; r < rbeg + 32; r++) {
            float4 kk = *(const float4*)&ks[r][kq];
            float4 vv = *(const float4*)&vs[r][vq];
            acc[0][0] += kk.x * vv.x; acc[0][1] += kk.x * vv.y;
            acc[0][2] += kk.x * vv.z; acc[0][3] += kk.x * vv.w;
            acc[1][0] += kk.y * vv.x; acc[1][1] += kk.y * vv.y;
            acc[1][2] += kk.y * vv.z; acc[1][3] += kk.y * vv.w;
            acc[2][0] += kk.z * vv.x; acc[2][1] += kk.z * vv.y;
            acc[2][2] += kk.z * vv.z; acc[2][3] += kk.z * vv.w;
            acc[3][0] += kk.w * vv.x; acc[3][1] += kk.w * vv.y;
            acc[3][2] += kk.w * vv.z; acc[3][3] += kk.w * vv.w;
        }
        __syncthreads();
    }

    // cross-group reduction: alias freed tiles
    float* red   = &ks[0][0];
    float* red_s = &vs[0][0];
#pragma unroll
    for (int ki = 0; ki < 4; ki++)
#pragma unroll
        for (int vi = 0; vi < 4; vi++)
            red[grp * 1024 + (kq + ki) * 32 + vq + vi] = acc[ki][vi];
    red_s[lr * 33 + lc] = s_exp;
    __syncthreads();

    for (int i = tid; i < 1024; i += 256) {
        float s = red[i] + red[1024 + i] + red[2048 + i] + red[3072 + i];
        g_kvp[((size_t)chunk * 64 + bh) * 1024 + i] = s;
    }
    if (tid < 32) {
        float ss = 0.0f;
#pragma unroll
        for (int gg = 0; gg < 8; gg++) ss += red_s[gg * 33 + tid];
        g_csump[((size_t)chunk * 64 + bh) * 32 + tid] = ss;
    }
}

// ---------------- K4: depthwise conv (sliding window) + crpe + eff -> pre ------
template <int KSZ>
__device__ __forceinline__ void conv_head(const float* __restrict__ qbase,
                                          const float* __restrict__ vbase,
                                          const float* __restrict__ wsrc,
                                          float biasv, const float* kvcol,
                                          int b, int head, int y, int lane) {
    const int P = KSZ / 2;
    const float scale = 0.1767766952966369f;  // 32^-0.5

    float wreg[KSZ * KSZ];
#pragma unroll
    for (int i = 0; i < KSZ * KSZ; i++) wreg[i] = wsrc[i];

    float win[KSZ][KSZ];
#pragma unroll
    for (int dy = 0; dy < KSZ; dy++)
#pragma unroll
        for (int j = 0; j < KSZ; j++) win[dy][j] = 0.0f;

#pragma unroll
    for (int xx = 0; xx < P; xx++) {
#pragma unroll
        for (int dy = 0; dy < KSZ; dy++) {
            int yy = y + dy - P;
            win[dy][xx] = ((unsigned)yy < (unsigned)IMG)
                              ? vbase[(size_t)(yy * IMG + xx) * QLD] : 0.0f;
        }
    }

    for (int xb = 0; xb < IMG; xb += KSZ) {
#pragma unroll
        for (int xi = 0; xi < KSZ; xi++) {
            int x = xb + xi;
            if (x < IMG) {                       // IMG % KSZ != 0: guard the tail
                const int slot_new = (xi + P) % KSZ;
                int xn = x + P;
                if (xn < IMG) {
#pragma unroll
                    for (int dy = 0; dy < KSZ; dy++) {
                        int yy = y + dy - P;
                        win[dy][slot_new] = ((unsigned)yy < (unsigned)IMG)
                            ? vbase[(size_t)(yy * IMG + xn) * QLD] : 0.0f;
                    }
                } else {
#pragma unroll
                    for (int dy = 0; dy < KSZ; dy++) win[dy][slot_new] = 0.0f;
                }

                int n = y * IMG + x;
                float q = qbase[(size_t)n * QLD];
                float acc = biasv;
#pragma unroll
                for (int dy = 0; dy < KSZ; dy++)
#pragma unroll
                    for (int dx = 0; dx < KSZ; dx++) {
                        const int slot = (xi + dx + 2 * KSZ - P) % KSZ;
                        acc += win[dy][slot] * wreg[dy * KSZ + dx];
                    }
                float e = 0.0f;
#pragma unroll
                for (int kk = 0; kk < 32; kk++)
                    e += __shfl_sync(0xffffffffu, q, kk) * kvcol[kk];
                g_preh[(size_t)(b * NTOK + n) * NC + head * 32 + lane] =
                    __float2half_rn(scale * e + q * acc);
            }
        }
    }
}

__global__ __launch_bounds__(256) void k_conv_att(const float* __restrict__ w3,
                                                  const float* __restrict__ b3,
                                                  const float* __restrict__ w5,
                                                  const float* __restrict__ b5,
                                                  const float* __restrict__ w7,
                                                  const float* __restrict__ b7) {
    int yt = blockIdx.x;
    int head = blockIdx.y;
    int b = blockIdx.z;
    int lane = threadIdx.x & 31, w = threadIdx.x >> 5;
    int bh = b * 8 + head;
    int tid = threadIdx.x;

    __shared__ float kv_s[1024];
    __shared__ float c_s[32];
    __shared__ float bias_s[32];

    if (tid < 32) {
        float s = 0.0f;
#pragma unroll
        for (int ch = 0; ch < KVCH; ch++)
            s += g_csump[((size_t)ch * 64 + bh) * 32 + tid];
        c_s[tid] = 1.0f / s;
    }
    __syncthreads();

    for (int i = tid; i < 1024; i += 256) {
        float s = 0.0f;
#pragma unroll
        for (int ch = 0; ch < KVCH; ch++) s += g_kvp[((size_t)ch * 64 + bh) * 1024 + i];
        kv_s[i] = s * c_s[i >> 5];
    }

    int chb;
    const float* wp;
    const float* bp;
    if (head < 2)      { wp = w3; bp = b3; chb = head * 32; }
    else if (head < 5) { wp = w5; bp = b5; chb = head * 32 - 64; }
    else               { wp = w7; bp = b7; chb = head * 32 - 160; }
    int ntap = (head < 2) ? 9 : (head < 5) ? 25 : 49;
    if (tid < 32) bias_s[tid] = bp[chb + tid];
    __syncthreads();

    float kvcol[32];
#pragma unroll
    for (int kk = 0; kk < 32; kk++) kvcol[kk] = kv_s[kk * 32 + lane];

    const float* qbase = g_qkv + (size_t)b * NTOK * QLD + head * 32 + lane;
    const float* vbase = qbase + 512;
    const float* wsrc = wp + (size_t)(chb + lane) * ntap;
    float biasv = bias_s[lane];
    int y = yt * 8 + w;

    if (head < 2)      conv_head<3>(qbase, vbase, wsrc, biasv, kvcol, b, head, y, lane);
    else if (head < 5) conv_head<5>(qbase, vbase, wsrc, biasv, kvcol, b, head, y, lane);
    else               conv_head<7>(qbase, vbase, wsrc, biasv, kvcol, b, head, y, lane);
}

// ---------------- launch -------------------------------------------------------
extern "C" void kernel_launch(void* const* d_in, const int* in_sizes, int n_in,
                              void* d_out, int out_size) {
    const float* x      = (const float*)d_in[0];
    const float* qkv_w  = (const float*)d_in[1];
    const float* proj_w = (const float*)d_in[2];
    const float* proj_b = (const float*)d_in[3];
    const float* gamma  = (const float*)d_in[4];
    const float* beta   = (const float*)d_in[5];
    const float* w3     = (const float*)d_in[6];
    const float* b3     = (const float*)d_in[7];
    const float* w5     = (const float*)d_in[8];
    const float* b5     = (const float*)d_in[9];
    const float* w7     = (const float*)d_in[10];
    const float* b7     = (const float*)d_in[11];
    float* out = (float*)d_out;

    void *p_xg, *p_qkv, *p_pre, *p_wq, *p_wp;
    cudaGetSymbolAddress(&p_xg, g_xgh);
    cudaGetSymbolAddress(&p_qkv, g_qkv);
    cudaGetSymbolAddress(&p_pre, g_preh);
    cudaGetSymbolAddress(&p_wq, g_wqh);
    cudaGetSymbolAddress(&p_wp, g_wph);

    static int smem_set = 0;
    const int SMEM_BYTES = NSTG * 2 * BM * SSTH * 2;   // 110592
    if (!smem_set) {
        cudaFuncSetAttribute(k_gemm_fp16, cudaFuncAttributeMaxDynamicSharedMemorySize,
                             SMEM_BYTES);
        smem_set = 1;
    }

    // 0. weights -> fp16
    k_cvtw<<<(QLD * NC + 255) / 256, 256>>>(qkv_w, proj_w);

    // 1. BN + hardswish -> fp16
    k_bnhsw<<<(NB * NTOK * NC / 4) / 256, 256>>>(x, gamma, beta);

    // 2. qkv = xg @ qkv_w^T   [32768 x 768], K=256  (fp16 MMA, fp32 accum)
    k_gemm_fp16<<<dim3(QLD / BN, NB * NTOK / BM), 256, SMEM_BYTES>>>(
        (const __half*)p_xg, (const __half*)p_wq, (float*)p_qkv,
        NB * NTOK, QLD, NC, nullptr);

    // 3. kv + sum(exp(k)) fused, 16 chunks, register-tiled
    k_kv<<<dim3(KVCH, 64), 256>>>();

    // 4. conv + crpe + eff -> pre (fp16 out)
    k_conv_att<<<dim3(8, 8, 8), 256>>>(w3, b3, w5, b5, w7, b7);

    // 5. out = pre @ proj_w^T + proj_b   [32768 x 256]
    k_gemm_fp16<<<dim3(NC / BN, NB * NTOK / BM), 256, SMEM_BYTES>>>(
        (const __half*)p_pre, (const __half*)p_wp, out,
        NB * NTOK, NC, NC, proj_b);
}

// round 9
// speedup vs baseline: 2.2929x; 1.1897x over previous
#include <cuda_runtime.h>
#include <cuda_fp16.h>
#include <math.h>

#define NB 8
#define NTOK 4096
#define NC 256
#define NH 8
#define CHD 32
#define IMG 64
#define QLD 768   // qkv row stride (3*C), in elements
#define KVCH 16   // kv token chunks (256 tokens each)

// ---------------- scratch (device globals; no allocation allowed) -------------
__device__ __half g_xgh[NB * NTOK * NC];         // fp16 BN+hardswish
__device__ __half g_qkvh[NB * NTOK * 3 * NC];    // fp16 qkv
__device__ float g_csump[KVCH * NB * NH * CHD];  // per-chunk sum(exp(k))
__device__ float g_kvp[KVCH * NB * NH * CHD * CHD];
__device__ __half g_preh[NB * NTOK * NC];        // fp16 pre-proj
__device__ __half g_wqh[QLD * NC];               // fp16 qkv_w
__device__ __half g_wph[NC * NC];                // fp16 proj_w

// ---------------- K0: convert weights to fp16 -----------------------------------
__global__ __launch_bounds__(256) void k_cvtw(const float* __restrict__ wq,
                                              const float* __restrict__ wp) {
    int i = blockIdx.x * 256 + threadIdx.x;
    if (i < QLD * NC) g_wqh[i] = __float2half_rn(wq[i]);
    if (i < NC * NC)  g_wph[i] = __float2half_rn(wp[i]);
}

// ---------------- K1: BatchNorm(eval) + Hardswish -> fp16 ----------------------
__global__ __launch_bounds__(256) void k_bnhsw(const float* __restrict__ x,
                                               const float* __restrict__ gamma,
                                               const float* __restrict__ beta) {
    int i = blockIdx.x * blockDim.x + threadIdx.x;   // float4 index
    float4 v = ((const float4*)x)[i];
    int c0 = (i & 63) * 4;
    const float inv = rsqrtf(1.0f + 1e-5f);
    float* f = (float*)&v;
    __half o[4];
#pragma unroll
    for (int j = 0; j < 4; j++) {
        float xb = f[j] * (gamma[c0 + j] * inv) + beta[c0 + j];
        o[j] = __float2half_rn(xb * fminf(fmaxf(xb + 3.0f, 0.0f), 6.0f) * (1.0f / 6.0f));
    }
    *(uint2*)&g_xgh[(size_t)i * 4] = *(uint2*)o;
}

// ---------------- fp16 tensor-core GEMM, 3-stage pipeline ----------------------
// C[m,j] = sum_k A[m,k] * W[j,k] (+bias), A/W fp16 row-major, fp32 accum.
#define BM 128
#define BN 128
#define BK 64     // halves per chunk (128 bytes per row)
#define SSTH 72   // smem row stride (halves): 144B -> 16B-aligned, LDSM conflict-free
#define NSTG 3

__device__ __forceinline__ void cpa16(void* dst, const void* src) {
    unsigned d = (unsigned)__cvta_generic_to_shared(dst);
    asm volatile("cp.async.cg.shared.global [%0], [%1], 16;\n" :: "r"(d), "l"(src));
}
__device__ __forceinline__ void cp_commit() { asm volatile("cp.async.commit_group;\n"); }

__device__ __forceinline__ void ldsm4(unsigned* r, const __half* p) {
    unsigned a = (unsigned)__cvta_generic_to_shared(p);
    asm volatile("ldmatrix.sync.aligned.m8n8.x4.shared.b16 {%0,%1,%2,%3}, [%4];"
                 : "=r"(r[0]), "=r"(r[1]), "=r"(r[2]), "=r"(r[3]) : "r"(a));
}

__device__ __forceinline__ void mma16(float* c, const unsigned* a, const unsigned* b) {
    asm volatile(
        "mma.sync.aligned.m16n8k16.row.col.f32.f16.f16.f32 "
        "{%0,%1,%2,%3}, {%4,%5,%6,%7}, {%8,%9}, {%0,%1,%2,%3};"
        : "+f"(c[0]), "+f"(c[1]), "+f"(c[2]), "+f"(c[3])
        : "r"(a[0]), "r"(a[1]), "r"(a[2]), "r"(a[3]), "r"(b[0]), "r"(b[1]));
}

extern __shared__ __align__(16) __half smem_h[];

template <bool HOUT>
__global__ __launch_bounds__(256, 2) void k_gemm_fp16(const __half* __restrict__ A,
                                                      const __half* __restrict__ W,
                                                      void* __restrict__ Cv,
                                                      int M, int Nd, int K,
                                                      const float* __restrict__ bias) {
    int tid = threadIdx.x;
    int m0 = blockIdx.y * BM, n0 = blockIdx.x * BN;
    int warp = tid >> 5, lane = tid & 31;
    int g = lane >> 2, t = lane & 3;
    int wm = (warp >> 2) * 64;
    int wn = (warp & 3) * 32;

    int al_row = lane & 15;
    int al_col = (lane >> 4) << 3;
    int bl_row = (lane & 7) + ((lane >> 4) << 3);
    int bl_col = ((lane >> 3) & 1) << 3;

    float acc[4][4][4];
#pragma unroll
    for (int mt = 0; mt < 4; mt++)
#pragma unroll
        for (int nt = 0; nt < 4; nt++)
#pragma unroll
            for (int r = 0; r < 4; r++) acc[mt][nt][r] = 0.0f;

    const int nch = K >> 6;

    auto issue = [&](int c, int stage) {
        if (c < nch) {
            __half* as = smem_h + stage * (2 * BM * SSTH);
            __half* bs = as + BM * SSTH;
            int k0 = c * BK;
#pragma unroll
            for (int j = 0; j < 4; j++) {
                int ci = tid + 256 * j;
                int row = ci >> 3;
                int kc = (ci & 7) << 3;
                cpa16(as + row * SSTH + kc, A + (size_t)(m0 + row) * K + k0 + kc);
                cpa16(bs + row * SSTH + kc, W + (size_t)(n0 + row) * K + k0 + kc);
            }
        }
        cp_commit();
    };

    issue(0, 0);
    issue(1, 1);

    for (int c = 0; c < nch; c++) {
        asm volatile("cp.async.wait_group 1;\n");
        __syncthreads();
        issue(c + 2, (c + 2) % NSTG);

        const __half* as = smem_h + (c % NSTG) * (2 * BM * SSTH);
        const __half* bs = as + BM * SSTH;
#pragma unroll
        for (int ks = 0; ks < 4; ks++) {
            int kb = ks * 16;
            unsigned af[4][4], bfr[2][4];
#pragma unroll
            for (int mt = 0; mt < 4; mt++)
                ldsm4(af[mt], as + (wm + mt * 16 + al_row) * SSTH + kb + al_col);
#pragma unroll
            for (int p = 0; p < 2; p++)
                ldsm4(bfr[p], bs + (wn + p * 16 + bl_row) * SSTH + kb + bl_col);
#pragma unroll
            for (int mt = 0; mt < 4; mt++)
#pragma unroll
                for (int nt = 0; nt < 4; nt++)
                    mma16(acc[mt][nt], af[mt], bfr[nt >> 1] + (nt & 1) * 2);
        }
    }

    // epilogue
#pragma unroll
    for (int mt = 0; mt < 4; mt++) {
#pragma unroll
        for (int nt = 0; nt < 4; nt++) {
            int col = n0 + wn + nt * 8 + 2 * t;
            float b0 = bias ? bias[col] : 0.0f;
            float b1 = bias ? bias[col + 1] : 0.0f;
            int row0 = m0 + wm + mt * 16 + g;
            if (HOUT) {
                __half* Ch = (__half*)Cv;
                *(__half2*)&Ch[(size_t)row0 * Nd + col] =
                    __floats2half2_rn(acc[mt][nt][0] + b0, acc[mt][nt][1] + b1);
                *(__half2*)&Ch[(size_t)(row0 + 8) * Nd + col] =
                    __floats2half2_rn(acc[mt][nt][2] + b0, acc[mt][nt][3] + b1);
            } else {
                float* Cf = (float*)Cv;
                float2 o0 = make_float2(acc[mt][nt][0] + b0, acc[mt][nt][1] + b1);
                float2 o1 = make_float2(acc[mt][nt][2] + b0, acc[mt][nt][3] + b1);
                *(float2*)&Cf[(size_t)row0 * Nd + col] = o0;
                *(float2*)&Cf[(size_t)(row0 + 8) * Nd + col] = o1;
            }
        }
    }
}

// ---------------- K3: kv = exp(k)^T v + sum(exp(k)), register-tiled 4x4 --------
__global__ __launch_bounds__(256) void k_kv() {
    int chunk = blockIdx.x;            // 0..KVCH-1 (256 tokens each)
    int bh = blockIdx.y;
    int b = bh >> 3, head = bh & 7;

    __shared__ __align__(16) float ks[128][32];
    __shared__ __align__(16) float vs[128][32];

    int tid = threadIdx.x;
    int grp = tid >> 6;                // 4 groups of 64 threads
    int t64 = tid & 63;
    int kq = (t64 >> 3) << 2;          // k-channel base
    int vq = (t64 & 7) << 2;           // v-channel base
    int c2 = (tid & 15) << 1;          // fill: fixed channel pair per thread
    int jj = tid >> 4;                 // fill: row-group 0..15

    const __half* base = g_qkvh + (size_t)(b * NTOK + chunk * (NTOK / KVCH)) * QLD + head * 32;

    float acc[4][4];
#pragma unroll
    for (int i = 0; i < 4; i++)
#pragma unroll
        for (int j = 0; j < 4; j++) acc[i][j] = 0.0f;
    float sA = 0.0f, sB = 0.0f;        // sum(exp) for channels c2, c2+1

    for (int tch = 0; tch < (NTOK / KVCH) / 128; tch++) {
        const __half* tb = base + (size_t)tch * 128 * QLD;
#pragma unroll
        for (int it = 0; it < 8; it++) {
            int r = jj + it * 16;      // 0..127
            size_t off = (size_t)r * QLD + c2;
            float2 fk = __half22float2(*(const __half2*)&tb[off + 256]);
            float e0 = __expf(fk.x), e1 = __expf(fk.y);
            *(float2*)&ks[r][c2] = make_float2(e0, e1);
            sA += e0; sB += e1;
            float2 fv = __half22float2(*(const __half2*)&tb[off + 512]);
            *(float2*)&vs[r][c2] = fv;
        }
        __syncthreads();

        int rbeg = grp * 32;
#pragma unroll 4
        for (int r = rbeg; r < rbeg + 32; r++) {
            float4 kk = *(const float4*)&ks[r][kq];
            float4 vv = *(const float4*)&vs[r][vq];
            acc[0][0] += kk.x * vv.x; acc[0][1] += kk.x * vv.y;
            acc[0][2] += kk.x * vv.z; acc[0][3] += kk.x * vv.w;
            acc[1][0] += kk.y * vv.x; acc[1][1] += kk.y * vv.y;
            acc[1][2] += kk.y * vv.z; acc[1][3] += kk.y * vv.w;
            acc[2][0] += kk.z * vv.x; acc[2][1] += kk.z * vv.y;
            acc[2][2] += kk.z * vv.z; acc[2][3] += kk.z * vv.w;
            acc[3][0] += kk.w * vv.x; acc[3][1] += kk.w * vv.y;
            acc[3][2] += kk.w * vv.z; acc[3][3] += kk.w * vv.w;
        }
        __syncthreads();
    }

    // cross-group reduction: alias freed tiles
    float* red   = &ks[0][0];          // 4 groups x 1024 kv partials
    float* red_s = &vs[0][0];          // [32][17] sexp partials
#pragma unroll
    for (int ki = 0; ki < 4; ki++)
#pragma unroll
        for (int vi = 0; vi < 4; vi++)
            red[grp * 1024 + (kq + ki) * 32 + vq + vi] = acc[ki][vi];
    red_s[c2 * 17 + jj] = sA;
    red_s[(c2 + 1) * 17 + jj] = sB;
    __syncthreads();

    for (int i = tid; i < 1024; i += 256) {
        float s = red[i] + red[1024 + i] + red[2048 + i] + red[3072 + i];
        g_kvp[((size_t)chunk * 64 + bh) * 1024 + i] = s;
    }
    if (tid < 32) {
        float ss = 0.0f;
#pragma unroll
        for (int j = 0; j < 16; j++) ss += red_s[tid * 17 + j];
        g_csump[((size_t)chunk * 64 + bh) * 32 + tid] = ss;
    }
}

// ---------------- K4: depthwise conv (smem v tile) + crpe + eff -> pre ---------
extern __shared__ __align__(16) __half s_vt[];   // [nrows][64][32] halves

template <int KSZ>
__device__ __forceinline__ void conv_head(const __half* __restrict__ qb,
                                          const __half* __restrict__ vt,
                                          const float* __restrict__ wsrc,
                                          float biasv, const float* kvcol,
                                          int b, int head, int y, int lane) {
    const int P = KSZ / 2;
    const float scale = 0.1767766952966369f;  // 32^-0.5

    float wreg[KSZ * KSZ];
#pragma unroll
    for (int i = 0; i < KSZ * KSZ; i++) wreg[i] = wsrc[i];

    float win[KSZ][KSZ];
#pragma unroll
    for (int dy = 0; dy < KSZ; dy++)
#pragma unroll
        for (int j = 0; j < KSZ; j++) win[dy][j] = 0.0f;

    // vt points at tile row (w+0), this lane's channel; row dy at +dy*2048
#pragma unroll
    for (int xx = 0; xx < P; xx++) {
#pragma unroll
        for (int dy = 0; dy < KSZ; dy++)
            win[dy][xx] = __half2float(vt[dy * 2048 + xx * 32]);
    }

    for (int xb = 0; xb < IMG; xb += KSZ) {
#pragma unroll
        for (int xi = 0; xi < KSZ; xi++) {
            int x = xb + xi;
            if (x < IMG) {                       // IMG % KSZ != 0: guard the tail
                const int slot_new = (xi + P) % KSZ;
                int xn = x + P;
                if (xn < IMG) {
#pragma unroll
                    for (int dy = 0; dy < KSZ; dy++)
                        win[dy][slot_new] = __half2float(vt[dy * 2048 + xn * 32]);
                } else {
#pragma unroll
                    for (int dy = 0; dy < KSZ; dy++) win[dy][slot_new] = 0.0f;
                }

                int n = y * IMG + x;
                float q = __half2float(qb[(size_t)n * QLD]);
                float acc = biasv;
#pragma unroll
                for (int dy = 0; dy < KSZ; dy++)
#pragma unroll
                    for (int dx = 0; dx < KSZ; dx++) {
                        const int slot = (xi + dx + 2 * KSZ - P) % KSZ;
                        acc += win[dy][slot] * wreg[dy * KSZ + dx];
                    }
                float e = 0.0f;
#pragma unroll
                for (int kk = 0; kk < 32; kk++)
                    e += __shfl_sync(0xffffffffu, q, kk) * kvcol[kk];
                g_preh[(size_t)(b * NTOK + n) * NC + head * 32 + lane] =
                    __float2half_rn(scale * e + q * acc);
            }
        }
    }
}

__global__ __launch_bounds__(256, 2) void k_conv_att(const float* __restrict__ w3,
                                                     const float* __restrict__ b3,
                                                     const float* __restrict__ w5,
                                                     const float* __restrict__ b5,
                                                     const float* __restrict__ w7,
                                                     const float* __restrict__ b7) {
    int yt = blockIdx.x;
    int head = blockIdx.y;
    int b = blockIdx.z;
    int lane = threadIdx.x & 31, w = threadIdx.x >> 5;
    int bh = b * 8 + head;
    int tid = threadIdx.x;

    __shared__ float kv_s[1024];
    __shared__ float c_s[32];
    __shared__ float bias_s[32];

    int P = (head < 2) ? 1 : (head < 5) ? 2 : 3;
    int nrows = 8 + 2 * P;
    int y0 = yt * 8;

    // fill v halo tile (zero-padded outside image)
    const __half* vglob = g_qkvh + (size_t)b * NTOK * QLD + 512 + head * 32;
    for (int idx = tid; idx < nrows * 64 * 16; idx += 256) {
        int rr = idx >> 10;               // /(64*16)
        int rem = idx & 1023;
        int xx = rem >> 4;
        int cc2 = (rem & 15) << 1;
        int yy = y0 - P + rr;
        __half2 val = __float2half2_rn(0.0f);
        if ((unsigned)yy < (unsigned)IMG)
            val = *(const __half2*)&vglob[(size_t)(yy * IMG + xx) * QLD + cc2];
        *(__half2*)&s_vt[(rr * 64 + xx) * 32 + cc2] = val;
    }

    if (tid < 32) {
        float s = 0.0f;
#pragma unroll
        for (int ch = 0; ch < KVCH; ch++)
            s += g_csump[((size_t)ch * 64 + bh) * 32 + tid];
        c_s[tid] = 1.0f / s;
    }
    __syncthreads();

    for (int i = tid; i < 1024; i += 256) {
        float s = 0.0f;
#pragma unroll
        for (int ch = 0; ch < KVCH; ch++) s += g_kvp[((size_t)ch * 64 + bh) * 1024 + i];
        kv_s[i] = s * c_s[i >> 5];
    }

    int chb;
    const float* wp;
    const float* bp;
    if (head < 2)      { wp = w3; bp = b3; chb = head * 32; }
    else if (head < 5) { wp = w5; bp = b5; chb = head * 32 - 64; }
    else               { wp = w7; bp = b7; chb = head * 32 - 160; }
    int ntap = (head < 2) ? 9 : (head < 5) ? 25 : 49;
    if (tid < 32) bias_s[tid] = bp[chb + tid];
    __syncthreads();

    float kvcol[32];
#pragma unroll
    for (int kk = 0; kk < 32; kk++) kvcol[kk] = kv_s[kk * 32 + lane];

    const __half* qbase = g_qkvh + (size_t)b * NTOK * QLD + head * 32 + lane;
    const __half* vt = s_vt + (size_t)w * 2048 + lane;   // tile row w, this channel
    const float* wsrc = wp + (size_t)(chb + lane) * ntap;
    float biasv = bias_s[lane];
    int y = y0 + w;

    if (head < 2)      conv_head<3>(qbase, vt, wsrc, biasv, kvcol, b, head, y, lane);
    else if (head < 5) conv_head<5>(qbase, vt, wsrc, biasv, kvcol, b, head, y, lane);
    else               conv_head<7>(qbase, vt, wsrc, biasv, kvcol, b, head, y, lane);
}

// ---------------- launch -------------------------------------------------------
extern "C" void kernel_launch(void* const* d_in, const int* in_sizes, int n_in,
                              void* d_out, int out_size) {
    const float* x      = (const float*)d_in[0];
    const float* qkv_w  = (const float*)d_in[1];
    const float* proj_w = (const float*)d_in[2];
    const float* proj_b = (const float*)d_in[3];
    const float* gamma  = (const float*)d_in[4];
    const float* beta   = (const float*)d_in[5];
    const float* w3     = (const float*)d_in[6];
    const float* b3     = (const float*)d_in[7];
    const float* w5     = (const float*)d_in[8];
    const float* b5     = (const float*)d_in[9];
    const float* w7     = (const float*)d_in[10];
    const float* b7     = (const float*)d_in[11];
    float* out = (float*)d_out;

    void *p_xg, *p_qkv, *p_pre, *p_wq, *p_wp;
    cudaGetSymbolAddress(&p_xg, g_xgh);
    cudaGetSymbolAddress(&p_qkv, g_qkvh);
    cudaGetSymbolAddress(&p_pre, g_preh);
    cudaGetSymbolAddress(&p_wq, g_wqh);
    cudaGetSymbolAddress(&p_wp, g_wph);

    static int smem_set = 0;
    const int SMEM_BYTES = NSTG * 2 * BM * SSTH * 2;   // 110592
    const int SMEM_CONV = 14 * 64 * 32 * 2;            // 57344
    if (!smem_set) {
        cudaFuncSetAttribute(k_gemm_fp16<true>,
                             cudaFuncAttributeMaxDynamicSharedMemorySize, SMEM_BYTES);
        cudaFuncSetAttribute(k_gemm_fp16<false>,
                             cudaFuncAttributeMaxDynamicSharedMemorySize, SMEM_BYTES);
        cudaFuncSetAttribute(k_conv_att,
                             cudaFuncAttributeMaxDynamicSharedMemorySize, SMEM_CONV);
        smem_set = 1;
    }

    // 0. weights -> fp16
    k_cvtw<<<(QLD * NC + 255) / 256, 256>>>(qkv_w, proj_w);

    // 1. BN + hardswish -> fp16
    k_bnhsw<<<(NB * NTOK * NC / 4) / 256, 256>>>(x, gamma, beta);

    // 2. qkv = xg @ qkv_w^T   [32768 x 768], K=256  (fp16 MMA, fp16 out)
    k_gemm_fp16<true><<<dim3(QLD / BN, NB * NTOK / BM), 256, SMEM_BYTES>>>(
        (const __half*)p_xg, (const __half*)p_wq, p_qkv,
        NB * NTOK, QLD, NC, nullptr);

    // 3. kv + sum(exp(k)) fused, 16 chunks, register-tiled
    k_kv<<<dim3(KVCH, 64), 256>>>();

    // 4. conv (smem v tile) + crpe + eff -> pre (fp16 out)
    k_conv_att<<<dim3(8, 8, 8), 256, SMEM_CONV>>>(w3, b3, w5, b5, w7, b7);

    // 5. out = pre @ proj_w^T + proj_b   [32768 x 256]  (fp32 out)
    k_gemm_fp16<false><<<dim3(NC / BN, NB * NTOK / BM), 256, SMEM_BYTES>>>(
        (const __half*)p_pre, (const __half*)p_wp, out,
        NB * NTOK, NC, NC, proj_b);
}

// round 10
// speedup vs baseline: 2.7529x; 1.2006x over previous
#include <cuda_runtime.h>
#include <cuda_fp16.h>
#include <math.h>

#define NB 8
#define NTOK 4096
#define NC 256
#define NH 8
#define CHD 32
#define IMG 64
#define QLD 768   // qkv row stride (3*C), in elements
#define KVCH 16   // kv token chunks (256 tokens each)

// ---------------- scratch (device globals; no allocation allowed) -------------
__device__ __half g_xgh[NB * NTOK * NC];         // fp16 BN+hardswish
__device__ __half g_qkvh[NB * NTOK * 3 * NC];    // fp16 qkv
__device__ float g_csump[KVCH * NB * NH * CHD];  // per-chunk sum(exp(k))
__device__ float g_kvp[KVCH * NB * NH * CHD * CHD];
__device__ __half g_preh[NB * NTOK * NC];        // fp16 pre-proj
__device__ __half g_wqh[QLD * NC];               // fp16 qkv_w
__device__ __half g_wph[NC * NC];                // fp16 proj_w

// ---------------- K0: convert weights to fp16 -----------------------------------
__global__ __launch_bounds__(256) void k_cvtw(const float* __restrict__ wq,
                                              const float* __restrict__ wp) {
    int i = blockIdx.x * 256 + threadIdx.x;
    if (i < QLD * NC) g_wqh[i] = __float2half_rn(wq[i]);
    if (i < NC * NC)  g_wph[i] = __float2half_rn(wp[i]);
}

// ---------------- K1: BatchNorm(eval) + Hardswish -> fp16 ----------------------
__global__ __launch_bounds__(256) void k_bnhsw(const float* __restrict__ x,
                                               const float* __restrict__ gamma,
                                               const float* __restrict__ beta) {
    int i = blockIdx.x * blockDim.x + threadIdx.x;   // float4 index
    float4 v = ((const float4*)x)[i];
    int c0 = (i & 63) * 4;
    const float inv = rsqrtf(1.0f + 1e-5f);
    float* f = (float*)&v;
    __half o[4];
#pragma unroll
    for (int j = 0; j < 4; j++) {
        float xb = f[j] * (gamma[c0 + j] * inv) + beta[c0 + j];
        o[j] = __float2half_rn(xb * fminf(fmaxf(xb + 3.0f, 0.0f), 6.0f) * (1.0f / 6.0f));
    }
    *(uint2*)&g_xgh[(size_t)i * 4] = *(uint2*)o;
}

// ---------------- fp16 tensor-core GEMM, 3-stage pipeline ----------------------
#define BM 128
#define BN 128
#define BK 64     // halves per chunk (128 bytes per row)
#define SSTH 72   // smem row stride (halves): 144B -> 16B-aligned, LDSM conflict-free
#define NSTG 3

__device__ __forceinline__ void cpa16(void* dst, const void* src) {
    unsigned d = (unsigned)__cvta_generic_to_shared(dst);
    asm volatile("cp.async.cg.shared.global [%0], [%1], 16;\n" :: "r"(d), "l"(src));
}
__device__ __forceinline__ void cp_commit() { asm volatile("cp.async.commit_group;\n"); }

__device__ __forceinline__ void ldsm4(unsigned* r, const __half* p) {
    unsigned a = (unsigned)__cvta_generic_to_shared(p);
    asm volatile("ldmatrix.sync.aligned.m8n8.x4.shared.b16 {%0,%1,%2,%3}, [%4];"
                 : "=r"(r[0]), "=r"(r[1]), "=r"(r[2]), "=r"(r[3]) : "r"(a));
}

__device__ __forceinline__ void mma16(float* c, const unsigned* a, const unsigned* b) {
    asm volatile(
        "mma.sync.aligned.m16n8k16.row.col.f32.f16.f16.f32 "
        "{%0,%1,%2,%3}, {%4,%5,%6,%7}, {%8,%9}, {%0,%1,%2,%3};"
        : "+f"(c[0]), "+f"(c[1]), "+f"(c[2]), "+f"(c[3])
        : "r"(a[0]), "r"(a[1]), "r"(a[2]), "r"(a[3]), "r"(b[0]), "r"(b[1]));
}

extern __shared__ __align__(16) __half smem_h[];

template <bool HOUT>
__global__ __launch_bounds__(256, 2) void k_gemm_fp16(const __half* __restrict__ A,
                                                      const __half* __restrict__ W,
                                                      void* __restrict__ Cv,
                                                      int M, int Nd, int K,
                                                      const float* __restrict__ bias) {
    int tid = threadIdx.x;
    int m0 = blockIdx.y * BM, n0 = blockIdx.x * BN;
    int warp = tid >> 5, lane = tid & 31;
    int g = lane >> 2, t = lane & 3;
    int wm = (warp >> 2) * 64;
    int wn = (warp & 3) * 32;

    int al_row = lane & 15;
    int al_col = (lane >> 4) << 3;
    int bl_row = (lane & 7) + ((lane >> 4) << 3);
    int bl_col = ((lane >> 3) & 1) << 3;

    float acc[4][4][4];
#pragma unroll
    for (int mt = 0; mt < 4; mt++)
#pragma unroll
        for (int nt = 0; nt < 4; nt++)
#pragma unroll
            for (int r = 0; r < 4; r++) acc[mt][nt][r] = 0.0f;

    const int nch = K >> 6;

    auto issue = [&](int c, int stage) {
        if (c < nch) {
            __half* as = smem_h + stage * (2 * BM * SSTH);
            __half* bs = as + BM * SSTH;
            int k0 = c * BK;
#pragma unroll
            for (int j = 0; j < 4; j++) {
                int ci = tid + 256 * j;
                int row = ci >> 3;
                int kc = (ci & 7) << 3;
                cpa16(as + row * SSTH + kc, A + (size_t)(m0 + row) * K + k0 + kc);
                cpa16(bs + row * SSTH + kc, W + (size_t)(n0 + row) * K + k0 + kc);
            }
        }
        cp_commit();
    };

    issue(0, 0);
    issue(1, 1);

    for (int c = 0; c < nch; c++) {
        asm volatile("cp.async.wait_group 1;\n");
        __syncthreads();
        issue(c + 2, (c + 2) % NSTG);

        const __half* as = smem_h + (c % NSTG) * (2 * BM * SSTH);
        const __half* bs = as + BM * SSTH;
#pragma unroll
        for (int ks = 0; ks < 4; ks++) {
            int kb = ks * 16;
            unsigned af[4][4], bfr[2][4];
#pragma unroll
            for (int mt = 0; mt < 4; mt++)
                ldsm4(af[mt], as + (wm + mt * 16 + al_row) * SSTH + kb + al_col);
#pragma unroll
            for (int p = 0; p < 2; p++)
                ldsm4(bfr[p], bs + (wn + p * 16 + bl_row) * SSTH + kb + bl_col);
#pragma unroll
            for (int mt = 0; mt < 4; mt++)
#pragma unroll
                for (int nt = 0; nt < 4; nt++)
                    mma16(acc[mt][nt], af[mt], bfr[nt >> 1] + (nt & 1) * 2);
        }
    }

    // epilogue
#pragma unroll
    for (int mt = 0; mt < 4; mt++) {
#pragma unroll
        for (int nt = 0; nt < 4; nt++) {
            int col = n0 + wn + nt * 8 + 2 * t;
            float b0 = bias ? bias[col] : 0.0f;
            float b1 = bias ? bias[col + 1] : 0.0f;
            int row0 = m0 + wm + mt * 16 + g;
            if (HOUT) {
                __half* Ch = (__half*)Cv;
                *(__half2*)&Ch[(size_t)row0 * Nd + col] =
                    __floats2half2_rn(acc[mt][nt][0] + b0, acc[mt][nt][1] + b1);
                *(__half2*)&Ch[(size_t)(row0 + 8) * Nd + col] =
                    __floats2half2_rn(acc[mt][nt][2] + b0, acc[mt][nt][3] + b1);
            } else {
                float* Cf = (float*)Cv;
                float2 o0 = make_float2(acc[mt][nt][0] + b0, acc[mt][nt][1] + b1);
                float2 o1 = make_float2(acc[mt][nt][2] + b0, acc[mt][nt][3] + b1);
                *(float2*)&Cf[(size_t)row0 * Nd + col] = o0;
                *(float2*)&Cf[(size_t)(row0 + 8) * Nd + col] = o1;
            }
        }
    }
}

// ---------------- K3: kv = exp(k)^T v + sum(exp(k)), register-tiled 4x4 --------
__global__ __launch_bounds__(256) void k_kv() {
    int chunk = blockIdx.x;            // 0..KVCH-1 (256 tokens each)
    int bh = blockIdx.y;
    int b = bh >> 3, head = bh & 7;

    __shared__ __align__(16) float ks[128][32];
    __shared__ __align__(16) float vs[128][32];

    int tid = threadIdx.x;
    int grp = tid >> 6;                // 4 groups of 64 threads
    int t64 = tid & 63;
    int kq = (t64 >> 3) << 2;          // k-channel base
    int vq = (t64 & 7) << 2;           // v-channel base
    int c2 = (tid & 15) << 1;          // fill: fixed channel pair per thread
    int jj = tid >> 4;                 // fill: row-group 0..15

    const __half* base = g_qkvh + (size_t)(b * NTOK + chunk * (NTOK / KVCH)) * QLD + head * 32;

    float acc[4][4];
#pragma unroll
    for (int i = 0; i < 4; i++)
#pragma unroll
        for (int j = 0; j < 4; j++) acc[i][j] = 0.0f;
    float sA = 0.0f, sB = 0.0f;

    for (int tch = 0; tch < (NTOK / KVCH) / 128; tch++) {
        const __half* tb = base + (size_t)tch * 128 * QLD;
#pragma unroll
        for (int it = 0; it < 8; it++) {
            int r = jj + it * 16;
            size_t off = (size_t)r * QLD + c2;
            float2 fk = __half22float2(*(const __half2*)&tb[off + 256]);
            float e0 = __expf(fk.x), e1 = __expf(fk.y);
            *(float2*)&ks[r][c2] = make_float2(e0, e1);
            sA += e0; sB += e1;
            float2 fv = __half22float2(*(const __half2*)&tb[off + 512]);
            *(float2*)&vs[r][c2] = fv;
        }
        __syncthreads();

        int rbeg = grp * 32;
#pragma unroll 4
        for (int r = rbeg; r < rbeg + 32; r++) {
            float4 kk = *(const float4*)&ks[r][kq];
            float4 vv = *(const float4*)&vs[r][vq];
            acc[0][0] += kk.x * vv.x; acc[0][1] += kk.x * vv.y;
            acc[0][2] += kk.x * vv.z; acc[0][3] += kk.x * vv.w;
            acc[1][0] += kk.y * vv.x; acc[1][1] += kk.y * vv.y;
            acc[1][2] += kk.y * vv.z; acc[1][3] += kk.y * vv.w;
            acc[2][0] += kk.z * vv.x; acc[2][1] += kk.z * vv.y;
            acc[2][2] += kk.z * vv.z; acc[2][3] += kk.z * vv.w;
            acc[3][0] += kk.w * vv.x; acc[3][1] += kk.w * vv.y;
            acc[3][2] += kk.w * vv.z; acc[3][3] += kk.w * vv.w;
        }
        __syncthreads();
    }

    float* red   = &ks[0][0];
    float* red_s = &vs[0][0];
#pragma unroll
    for (int ki = 0; ki < 4; ki++)
#pragma unroll
        for (int vi = 0; vi < 4; vi++)
            red[grp * 1024 + (kq + ki) * 32 + vq + vi] = acc[ki][vi];
    red_s[c2 * 17 + jj] = sA;
    red_s[(c2 + 1) * 17 + jj] = sB;
    __syncthreads();

    for (int i = tid; i < 1024; i += 256) {
        float s = red[i] + red[1024 + i] + red[2048 + i] + red[3072 + i];
        g_kvp[((size_t)chunk * 64 + bh) * 1024 + i] = s;
    }
    if (tid < 32) {
        float ss = 0.0f;
#pragma unroll
        for (int j = 0; j < 16; j++) ss += red_s[tid * 17 + j];
        g_csump[((size_t)chunk * 64 + bh) * 32 + tid] = ss;
    }
}

// ---------------- K4: depthwise conv (smem v+q tiles) + crpe + eff -> pre ------
extern __shared__ __align__(16) __half s_vt[];   // [nrows][64][32] halves (dynamic)

template <int KSZ>
__device__ __forceinline__ void conv_head(const __half* __restrict__ qt,  // q_s + w*64*32
                                          const __half* __restrict__ vt,
                                          const float* __restrict__ wsrc,
                                          float biasv, const float* kvcol,
                                          int b, int head, int y, int lane) {
    const int P = KSZ / 2;
    const float scale = 0.1767766952966369f;  // 32^-0.5

    float wreg[KSZ * KSZ];
#pragma unroll
    for (int i = 0; i < KSZ * KSZ; i++) wreg[i] = wsrc[i];

    float win[KSZ][KSZ];
#pragma unroll
    for (int dy = 0; dy < KSZ; dy++)
#pragma unroll
        for (int j = 0; j < KSZ; j++) win[dy][j] = 0.0f;

#pragma unroll
    for (int xx = 0; xx < P; xx++) {
#pragma unroll
        for (int dy = 0; dy < KSZ; dy++)
            win[dy][xx] = __half2float(vt[dy * 2048 + xx * 32]);
    }

    for (int xb = 0; xb < IMG; xb += KSZ) {
#pragma unroll
        for (int xi = 0; xi < KSZ; xi++) {
            int x = xb + xi;
            if (x < IMG) {                       // IMG % KSZ != 0: guard the tail
                const int slot_new = (xi + P) % KSZ;
                int xn = x + P;
                if (xn < IMG) {
#pragma unroll
                    for (int dy = 0; dy < KSZ; dy++)
                        win[dy][slot_new] = __half2float(vt[dy * 2048 + xn * 32]);
                } else {
#pragma unroll
                    for (int dy = 0; dy < KSZ; dy++) win[dy][slot_new] = 0.0f;
                }

                // conv accumulate
                float acc = biasv;
#pragma unroll
                for (int dy = 0; dy < KSZ; dy++)
#pragma unroll
                    for (int dx = 0; dx < KSZ; dx++) {
                        const int slot = (xi + dx + 2 * KSZ - P) % KSZ;
                        acc += win[dy][slot] * wreg[dy * KSZ + dx];
                    }

                // eff via smem-broadcast q (no shuffles)
                const __half2* qrow = (const __half2*)(qt + x * 32);
                float q = __half2float(qt[x * 32 + lane]);
                float e = 0.0f;
#pragma unroll
                for (int kk = 0; kk < 16; kk++) {
                    float2 qq = __half22float2(qrow[kk]);
                    e += qq.x * kvcol[2 * kk] + qq.y * kvcol[2 * kk + 1];
                }

                int n = y * IMG + x;
                g_preh[(size_t)(b * NTOK + n) * NC + head * 32 + lane] =
                    __float2half_rn(scale * e + q * acc);
            }
        }
    }
}

__global__ __launch_bounds__(256, 2) void k_conv_att(const float* __restrict__ w3,
                                                     const float* __restrict__ b3,
                                                     const float* __restrict__ w5,
                                                     const float* __restrict__ b5,
                                                     const float* __restrict__ w7,
                                                     const float* __restrict__ b7) {
    int yt = blockIdx.x;
    int head = blockIdx.y;
    int b = blockIdx.z;
    int lane = threadIdx.x & 31, w = threadIdx.x >> 5;
    int bh = b * 8 + head;
    int tid = threadIdx.x;

    __shared__ float kv_s[1024];
    __shared__ float c_s[32];
    __shared__ float bias_s[32];
    __shared__ __align__(16) __half q_s[8 * 64 * 32];   // 8 rows x 64 px x 32 ch

    int P = (head < 2) ? 1 : (head < 5) ? 2 : 3;
    int nrows = 8 + 2 * P;
    int y0 = yt * 8;

    // fill v halo tile (zero-padded outside image)
    const __half* vglob = g_qkvh + (size_t)b * NTOK * QLD + 512 + head * 32;
    for (int idx = tid; idx < nrows * 64 * 16; idx += 256) {
        int rr = idx >> 10;
        int rem = idx & 1023;
        int xx = rem >> 4;
        int cc2 = (rem & 15) << 1;
        int yy = y0 - P + rr;
        __half2 val = __float2half2_rn(0.0f);
        if ((unsigned)yy < (unsigned)IMG)
            val = *(const __half2*)&vglob[(size_t)(yy * IMG + xx) * QLD + cc2];
        *(__half2*)&s_vt[(rr * 64 + xx) * 32 + cc2] = val;
    }

    // fill q tile: 512 consecutive tokens starting at y0*64
    const __half* qglob = g_qkvh + (size_t)(b * NTOK + y0 * IMG) * QLD + head * 32;
    for (int idx = tid; idx < 8 * 64 * 16; idx += 256) {
        int nloc = idx >> 4;                 // 0..511
        int cc2 = (idx & 15) << 1;
        *(__half2*)&q_s[nloc * 32 + cc2] =
            *(const __half2*)&qglob[(size_t)nloc * QLD + cc2];
    }

    if (tid < 32) {
        float s = 0.0f;
#pragma unroll
        for (int ch = 0; ch < KVCH; ch++)
            s += g_csump[((size_t)ch * 64 + bh) * 32 + tid];
        c_s[tid] = 1.0f / s;
    }
    __syncthreads();

    for (int i = tid; i < 1024; i += 256) {
        float s = 0.0f;
#pragma unroll
        for (int ch = 0; ch < KVCH; ch++) s += g_kvp[((size_t)ch * 64 + bh) * 1024 + i];
        kv_s[i] = s * c_s[i >> 5];
    }

    int chb;
    const float* wp;
    const float* bp;
    if (head < 2)      { wp = w3; bp = b3; chb = head * 32; }
    else if (head < 5) { wp = w5; bp = b5; chb = head * 32 - 64; }
    else               { wp = w7; bp = b7; chb = head * 32 - 160; }
    int ntap = (head < 2) ? 9 : (head < 5) ? 25 : 49;
    if (tid < 32) bias_s[tid] = bp[chb + tid];
    __syncthreads();

    float kvcol[32];
#pragma unroll
    for (int kk = 0; kk < 32; kk++) kvcol[kk] = kv_s[kk * 32 + lane];

    const __half* qt = q_s + (size_t)w * 64 * 32;        // this warp's row
    const __half* vt = s_vt + (size_t)w * 2048 + lane;   // tile row w, this channel
    const float* wsrc = wp + (size_t)(chb + lane) * ntap;
    float biasv = bias_s[lane];
    int y = y0 + w;

    if (head < 2)      conv_head<3>(qt, vt, wsrc, biasv, kvcol, b, head, y, lane);
    else if (head < 5) conv_head<5>(qt, vt, wsrc, biasv, kvcol, b, head, y, lane);
    else               conv_head<7>(qt, vt, wsrc, biasv, kvcol, b, head, y, lane);
}

// ---------------- launch -------------------------------------------------------
extern "C" void kernel_launch(void* const* d_in, const int* in_sizes, int n_in,
                              void* d_out, int out_size) {
    const float* x      = (const float*)d_in[0];
    const float* qkv_w  = (const float*)d_in[1];
    const float* proj_w = (const float*)d_in[2];
    const float* proj_b = (const float*)d_in[3];
    const float* gamma  = (const float*)d_in[4];
    const float* beta   = (const float*)d_in[5];
    const float* w3     = (const float*)d_in[6];
    const float* b3     = (const float*)d_in[7];
    const float* w5     = (const float*)d_in[8];
    const float* b5     = (const float*)d_in[9];
    const float* w7     = (const float*)d_in[10];
    const float* b7     = (const float*)d_in[11];
    float* out = (float*)d_out;

    void *p_xg, *p_qkv, *p_pre, *p_wq, *p_wp;
    cudaGetSymbolAddress(&p_xg, g_xgh);
    cudaGetSymbolAddress(&p_qkv, g_qkvh);
    cudaGetSymbolAddress(&p_pre, g_preh);
    cudaGetSymbolAddress(&p_wq, g_wqh);
    cudaGetSymbolAddress(&p_wp, g_wph);

    static int smem_set = 0;
    const int SMEM_BYTES = NSTG * 2 * BM * SSTH * 2;   // 110592
    const int SMEM_CONV = 14 * 64 * 32 * 2;            // 57344 (dynamic v tile)
    if (!smem_set) {
        cudaFuncSetAttribute(k_gemm_fp16<true>,
                             cudaFuncAttributeMaxDynamicSharedMemorySize, SMEM_BYTES);
        cudaFuncSetAttribute(k_gemm_fp16<false>,
                             cudaFuncAttributeMaxDynamicSharedMemorySize, SMEM_BYTES);
        cudaFuncSetAttribute(k_conv_att,
                             cudaFuncAttributeMaxDynamicSharedMemorySize, SMEM_CONV);
        smem_set = 1;
    }

    // 0. weights -> fp16
    k_cvtw<<<(QLD * NC + 255) / 256, 256>>>(qkv_w, proj_w);

    // 1. BN + hardswish -> fp16
    k_bnhsw<<<(NB * NTOK * NC / 4) / 256, 256>>>(x, gamma, beta);

    // 2. qkv = xg @ qkv_w^T   [32768 x 768], K=256  (fp16 MMA, fp16 out)
    k_gemm_fp16<true><<<dim3(QLD / BN, NB * NTOK / BM), 256, SMEM_BYTES>>>(
        (const __half*)p_xg, (const __half*)p_wq, p_qkv,
        NB * NTOK, QLD, NC, nullptr);

    // 3. kv + sum(exp(k)) fused, 16 chunks, register-tiled
    k_kv<<<dim3(KVCH, 64), 256>>>();

    // 4. conv (smem v+q tiles) + crpe + eff -> pre (fp16 out)
    k_conv_att<<<dim3(8, 8, 8), 256, SMEM_CONV>>>(w3, b3, w5, b5, w7, b7);

    // 5. out = pre @ proj_w^T + proj_b   [32768 x 256]  (fp32 out)
    k_gemm_fp16<false><<<dim3(NC / BN, NB * NTOK / BM), 256, SMEM_BYTES>>>(
        (const __half*)p_pre, (const __half*)p_wp, out,
        NB * NTOK, NC, NC, proj_b);
}

// round 11
// speedup vs baseline: 2.8913x; 1.0503x over previous
#include <cuda_runtime.h>
#include <cuda_fp16.h>
#include <math.h>

#define NB 8
#define NTOK 4096
#define NC 256
#define NH 8
#define CHD 32
#define IMG 64
#define QLD 768   // qkv row stride (3*C), in elements
#define KVCH 16   // kv token chunks (256 tokens each)

// ---------------- scratch (device globals; no allocation allowed) -------------
__device__ __half g_xgh[NB * NTOK * NC];         // fp16 BN+hardswish
__device__ __half g_qkvh[NB * NTOK * 3 * NC];    // fp16 qkv
__device__ float g_csump[KVCH * NB * NH * CHD];  // per-chunk sum(exp(k))
__device__ float g_kvp[KVCH * NB * NH * CHD * CHD];
__device__ __half g_preh[NB * NTOK * NC];        // fp16 pre-proj
__device__ __half g_wqh[QLD * NC];               // fp16 qkv_w
__device__ __half g_wph[NC * NC];                // fp16 proj_w

// ---------------- packed f32x2 helpers (sm_100+) --------------------------------
__device__ __forceinline__ void fma_f32x2(unsigned long long& d,
                                          unsigned long long a,
                                          unsigned long long b) {
    asm("fma.rn.f32x2 %0, %1, %2, %0;" : "+l"(d) : "l"(a), "l"(b));
}
__device__ __forceinline__ unsigned long long pack_ff(float x, float y) {
    unsigned long long r;
    asm("mov.b64 %0, {%1, %2};" : "=l"(r) : "f"(x), "f"(y));
    return r;
}
__device__ __forceinline__ float2 unpack_ff(unsigned long long v) {
    float2 r;
    asm("mov.b64 {%0, %1}, %2;" : "=f"(r.x), "=f"(r.y) : "l"(v));
    return r;
}

// ---------------- K0: BN+hardswish -> fp16  AND  weights -> fp16 (one launch) ---
#define PREP_BN_BLOCKS 8192   // NB*NTOK*NC/4/256
__global__ __launch_bounds__(256) void k_prep(const float* __restrict__ x,
                                              const float* __restrict__ gamma,
                                              const float* __restrict__ beta,
                                              const float* __restrict__ wq,
                                              const float* __restrict__ wp) {
    if (blockIdx.x < PREP_BN_BLOCKS) {
        int i = blockIdx.x * 256 + threadIdx.x;    // float4 index
        float4 v = ((const float4*)x)[i];
        int c0 = (i & 63) * 4;
        const float inv = rsqrtf(1.0f + 1e-5f);
        float* f = (float*)&v;
        __half o[4];
#pragma unroll
        for (int j = 0; j < 4; j++) {
            float xb = f[j] * (gamma[c0 + j] * inv) + beta[c0 + j];
            o[j] = __float2half_rn(xb * fminf(fmaxf(xb + 3.0f, 0.0f), 6.0f) * (1.0f / 6.0f));
        }
        *(uint2*)&g_xgh[(size_t)i * 4] = *(uint2*)o;
    } else {
        int i = (blockIdx.x - PREP_BN_BLOCKS) * 256 + threadIdx.x;
        if (i < QLD * NC) g_wqh[i] = __float2half_rn(wq[i]);
        if (i < NC * NC)  g_wph[i] = __float2half_rn(wp[i]);
    }
}

// ---------------- fp16 tensor-core GEMM, 3-stage pipeline ----------------------
#define BM 128
#define BN 128
#define BK 64     // halves per chunk (128 bytes per row)
#define SSTH 72   // smem row stride (halves): 144B -> 16B-aligned, LDSM conflict-free
#define NSTG 3
#define OST 136   // epilogue smem tile row stride (halves): conflict-free STS

__device__ __forceinline__ void cpa16(void* dst, const void* src) {
    unsigned d = (unsigned)__cvta_generic_to_shared(dst);
    asm volatile("cp.async.cg.shared.global [%0], [%1], 16;\n" :: "r"(d), "l"(src));
}
__device__ __forceinline__ void cp_commit() { asm volatile("cp.async.commit_group;\n"); }

__device__ __forceinline__ void ldsm4(unsigned* r, const __half* p) {
    unsigned a = (unsigned)__cvta_generic_to_shared(p);
    asm volatile("ldmatrix.sync.aligned.m8n8.x4.shared.b16 {%0,%1,%2,%3}, [%4];"
                 : "=r"(r[0]), "=r"(r[1]), "=r"(r[2]), "=r"(r[3]) : "r"(a));
}

__device__ __forceinline__ void mma16(float* c, const unsigned* a, const unsigned* b) {
    asm volatile(
        "mma.sync.aligned.m16n8k16.row.col.f32.f16.f16.f32 "
        "{%0,%1,%2,%3}, {%4,%5,%6,%7}, {%8,%9}, {%0,%1,%2,%3};"
        : "+f"(c[0]), "+f"(c[1]), "+f"(c[2]), "+f"(c[3])
        : "r"(a[0]), "r"(a[1]), "r"(a[2]), "r"(a[3]), "r"(b[0]), "r"(b[1]));
}

extern __shared__ __align__(16) __half smem_h[];

// HOUT=true: fp16 output via smem-staged coalesced stores (bias must be null).
// HOUT=false: fp32 output direct (+bias).
template <bool HOUT>
__global__ __launch_bounds__(256, 2) void k_gemm_fp16(const __half* __restrict__ A,
                                                      const __half* __restrict__ W,
                                                      void* __restrict__ Cv,
                                                      int M, int Nd, int K,
                                                      const float* __restrict__ bias) {
    int tid = threadIdx.x;
    int m0 = blockIdx.y * BM, n0 = blockIdx.x * BN;
    int warp = tid >> 5, lane = tid & 31;
    int g = lane >> 2, t = lane & 3;
    int wm = (warp >> 2) * 64;
    int wn = (warp & 3) * 32;

    int al_row = lane & 15;
    int al_col = (lane >> 4) << 3;
    int bl_row = (lane & 7) + ((lane >> 4) << 3);
    int bl_col = ((lane >> 3) & 1) << 3;

    float acc[4][4][4];
#pragma unroll
    for (int mt = 0; mt < 4; mt++)
#pragma unroll
        for (int nt = 0; nt < 4; nt++)
#pragma unroll
            for (int r = 0; r < 4; r++) acc[mt][nt][r] = 0.0f;

    const int nch = K >> 6;

    auto issue = [&](int c, int stage) {
        if (c < nch) {
            __half* as = smem_h + stage * (2 * BM * SSTH);
            __half* bs = as + BM * SSTH;
            int k0 = c * BK;
#pragma unroll
            for (int j = 0; j < 4; j++) {
                int ci = tid + 256 * j;
                int row = ci >> 3;
                int kc = (ci & 7) << 3;
                cpa16(as + row * SSTH + kc, A + (size_t)(m0 + row) * K + k0 + kc);
                cpa16(bs + row * SSTH + kc, W + (size_t)(n0 + row) * K + k0 + kc);
            }
        }
        cp_commit();
    };

    issue(0, 0);
    issue(1, 1);

    for (int c = 0; c < nch; c++) {
        asm volatile("cp.async.wait_group 1;\n");
        __syncthreads();
        issue(c + 2, (c + 2) % NSTG);

        const __half* as = smem_h + (c % NSTG) * (2 * BM * SSTH);
        const __half* bs = as + BM * SSTH;
#pragma unroll
        for (int ks = 0; ks < 4; ks++) {
            int kb = ks * 16;
            unsigned af[4][4], bfr[2][4];
#pragma unroll
            for (int mt = 0; mt < 4; mt++)
                ldsm4(af[mt], as + (wm + mt * 16 + al_row) * SSTH + kb + al_col);
#pragma unroll
            for (int p = 0; p < 2; p++)
                ldsm4(bfr[p], bs + (wn + p * 16 + bl_row) * SSTH + kb + bl_col);
#pragma unroll
            for (int mt = 0; mt < 4; mt++)
#pragma unroll
                for (int nt = 0; nt < 4; nt++)
                    mma16(acc[mt][nt], af[mt], bfr[nt >> 1] + (nt & 1) * 2);
        }
    }

    if (HOUT) {
        // stage fp16 tile in smem, then fully-coalesced 16B stores
        __syncthreads();                       // all warps done with stage buffers
        __half* os = smem_h;                   // 128 x 128 tile, stride OST
#pragma unroll
        for (int mt = 0; mt < 4; mt++)
#pragma unroll
            for (int nt = 0; nt < 4; nt++) {
                int col = wn + nt * 8 + 2 * t;
                int row = wm + mt * 16 + g;
                *(__half2*)&os[row * OST + col] =
                    __floats2half2_rn(acc[mt][nt][0], acc[mt][nt][1]);
                *(__half2*)&os[(row + 8) * OST + col] =
                    __floats2half2_rn(acc[mt][nt][2], acc[mt][nt][3]);
            }
        __syncthreads();
        __half* Ch = (__half*)Cv;
#pragma unroll
        for (int j = 0; j < 8; j++) {
            int ci = tid + 256 * j;            // 0..2047 16B-chunks
            int row = ci >> 4;                 // 0..127
            int hc = (ci & 15) << 3;           // 0..120 halves
            *(uint4*)&Ch[(size_t)(m0 + row) * Nd + n0 + hc] =
                *(uint4*)&os[row * OST + hc];
        }
    } else {
#pragma unroll
        for (int mt = 0; mt < 4; mt++)
#pragma unroll
            for (int nt = 0; nt < 4; nt++) {
                int col = n0 + wn + nt * 8 + 2 * t;
                float b0 = bias ? bias[col] : 0.0f;
                float b1 = bias ? bias[col + 1] : 0.0f;
                int row0 = m0 + wm + mt * 16 + g;
                float* Cf = (float*)Cv;
                float2 o0 = make_float2(acc[mt][nt][0] + b0, acc[mt][nt][1] + b1);
                float2 o1 = make_float2(acc[mt][nt][2] + b0, acc[mt][nt][3] + b1);
                *(float2*)&Cf[(size_t)row0 * Nd + col] = o0;
                *(float2*)&Cf[(size_t)(row0 + 8) * Nd + col] = o1;
            }
    }
}

// ---------------- K3: kv = exp(k)^T v + sum(exp(k)), f32x2-packed 4x4 ----------
__global__ __launch_bounds__(256) void k_kv() {
    int chunk = blockIdx.x;            // 0..KVCH-1 (256 tokens each)
    int bh = blockIdx.y;
    int b = bh >> 3, head = bh & 7;

    __shared__ __align__(16) float ks[128][32];
    __shared__ __align__(16) float vs[128][32];

    int tid = threadIdx.x;
    int grp = tid >> 6;                // 4 groups of 64 threads
    int t64 = tid & 63;
    int kq = (t64 >> 3) << 2;          // k-channel base
    int vq = (t64 & 7) << 2;           // v-channel base
    int c2 = (tid & 15) << 1;          // fill: fixed channel pair per thread
    int jj = tid >> 4;                 // fill: row-group 0..15

    const __half* base = g_qkvh + (size_t)(b * NTOK + chunk * (NTOK / KVCH)) * QLD + head * 32;

    unsigned long long accp[4][2];
#pragma unroll
    for (int i = 0; i < 4; i++) { accp[i][0] = 0ull; accp[i][1] = 0ull; }
    float sA = 0.0f, sB = 0.0f;

    for (int tch = 0; tch < (NTOK / KVCH) / 128; tch++) {
        const __half* tb = base + (size_t)tch * 128 * QLD;
#pragma unroll
        for (int it = 0; it < 8; it++) {
            int r = jj + it * 16;
            size_t off = (size_t)r * QLD + c2;
            float2 fk = __half22float2(*(const __half2*)&tb[off + 256]);
            float e0 = __expf(fk.x), e1 = __expf(fk.y);
            *(float2*)&ks[r][c2] = make_float2(e0, e1);
            sA += e0; sB += e1;
            float2 fv = __half22float2(*(const __half2*)&tb[off + 512]);
            *(float2*)&vs[r][c2] = fv;
        }
        __syncthreads();

        int rbeg = grp * 32;
#pragma unroll 4
        for (int r = rbeg; r < rbeg + 32; r++) {
            float4 kk = *(const float4*)&ks[r][kq];
            ulonglong2 vvp = *(const ulonglong2*)&vs[r][vq];   // 16B-aligned
            unsigned long long kb;
            kb = pack_ff(kk.x, kk.x);
            fma_f32x2(accp[0][0], kb, vvp.x); fma_f32x2(accp[0][1], kb, vvp.y);
            kb = pack_ff(kk.y, kk.y);
            fma_f32x2(accp[1][0], kb, vvp.x); fma_f32x2(accp[1][1], kb, vvp.y);
            kb = pack_ff(kk.z, kk.z);
            fma_f32x2(accp[2][0], kb, vvp.x); fma_f32x2(accp[2][1], kb, vvp.y);
            kb = pack_ff(kk.w, kk.w);
            fma_f32x2(accp[3][0], kb, vvp.x); fma_f32x2(accp[3][1], kb, vvp.y);
        }
        __syncthreads();
    }

    float* red   = &ks[0][0];
    float* red_s = &vs[0][0];
#pragma unroll
    for (int ki = 0; ki < 4; ki++) {
        float2 a01 = unpack_ff(accp[ki][0]);
        float2 a23 = unpack_ff(accp[ki][1]);
        red[grp * 1024 + (kq + ki) * 32 + vq + 0] = a01.x;
        red[grp * 1024 + (kq + ki) * 32 + vq + 1] = a01.y;
        red[grp * 1024 + (kq + ki) * 32 + vq + 2] = a23.x;
        red[grp * 1024 + (kq + ki) * 32 + vq + 3] = a23.y;
    }
    red_s[c2 * 17 + jj] = sA;
    red_s[(c2 + 1) * 17 + jj] = sB;
    __syncthreads();

    for (int i = tid; i < 1024; i += 256) {
        float s = red[i] + red[1024 + i] + red[2048 + i] + red[3072 + i];
        g_kvp[((size_t)chunk * 64 + bh) * 1024 + i] = s;
    }
    if (tid < 32) {
        float ss = 0.0f;
#pragma unroll
        for (int j = 0; j < 16; j++) ss += red_s[tid * 17 + j];
        g_csump[((size_t)chunk * 64 + bh) * 32 + tid] = ss;
    }
}

// ---------------- K4: depthwise conv (smem v+q tiles) + crpe + eff -> pre ------
extern __shared__ __align__(16) __half s_vt[];   // [nrows][64][32] halves (dynamic)

template <int KSZ>
__device__ __forceinline__ void conv_head(const __half* __restrict__ qt,
                                          const __half* __restrict__ vt,
                                          const float* __restrict__ wsrc,
                                          float biasv, const float* kvcol,
                                          int b, int head, int y, int lane) {
    const int P = KSZ / 2;
    const float scale = 0.1767766952966369f;  // 32^-0.5

    float wreg[KSZ * KSZ];
#pragma unroll
    for (int i = 0; i < KSZ * KSZ; i++) wreg[i] = wsrc[i];

    float win[KSZ][KSZ];
#pragma unroll
    for (int dy = 0; dy < KSZ; dy++)
#pragma unroll
        for (int j = 0; j < KSZ; j++) win[dy][j] = 0.0f;

#pragma unroll
    for (int xx = 0; xx < P; xx++) {
#pragma unroll
        for (int dy = 0; dy < KSZ; dy++)
            win[dy][xx] = __half2float(vt[dy * 2048 + xx * 32]);
    }

    for (int xb = 0; xb < IMG; xb += KSZ) {
#pragma unroll
        for (int xi = 0; xi < KSZ; xi++) {
            int x = xb + xi;
            if (x < IMG) {                       // IMG % KSZ != 0: guard the tail
                const int slot_new = (xi + P) % KSZ;
                int xn = x + P;
                if (xn < IMG) {
#pragma unroll
                    for (int dy = 0; dy < KSZ; dy++)
                        win[dy][slot_new] = __half2float(vt[dy * 2048 + xn * 32]);
                } else {
#pragma unroll
                    for (int dy = 0; dy < KSZ; dy++) win[dy][slot_new] = 0.0f;
                }

                float acc = biasv;
#pragma unroll
                for (int dy = 0; dy < KSZ; dy++)
#pragma unroll
                    for (int dx = 0; dx < KSZ; dx++) {
                        const int slot = (xi + dx + 2 * KSZ - P) % KSZ;
                        acc += win[dy][slot] * wreg[dy * KSZ + dx];
                    }

                const __half2* qrow = (const __half2*)(qt + x * 32);
                float q = __half2float(qt[x * 32 + lane]);
                float e = 0.0f;
#pragma unroll
                for (int kk = 0; kk < 16; kk++) {
                    float2 qq = __half22float2(qrow[kk]);
                    e += qq.x * kvcol[2 * kk] + qq.y * kvcol[2 * kk + 1];
                }

                int n = y * IMG + x;
                g_preh[(size_t)(b * NTOK + n) * NC + head * 32 + lane] =
                    __float2half_rn(scale * e + q * acc);
            }
        }
    }
}

__global__ __launch_bounds__(256, 2) void k_conv_att(const float* __restrict__ w3,
                                                     const float* __restrict__ b3,
                                                     const float* __restrict__ w5,
                                                     const float* __restrict__ b5,
                                                     const float* __restrict__ w7,
                                                     const float* __restrict__ b7) {
    int yt = blockIdx.x;
    int head = blockIdx.y;
    int b = blockIdx.z;
    int lane = threadIdx.x & 31, w = threadIdx.x >> 5;
    int bh = b * 8 + head;
    int tid = threadIdx.x;

    __shared__ float kv_s[1024];
    __shared__ float c_s[32];
    __shared__ float bias_s[32];
    __shared__ __align__(16) __half q_s[8 * 64 * 32];

    int P = (head < 2) ? 1 : (head < 5) ? 2 : 3;
    int nrows = 8 + 2 * P;
    int y0 = yt * 8;

    const __half* vglob = g_qkvh + (size_t)b * NTOK * QLD + 512 + head * 32;
    for (int idx = tid; idx < nrows * 64 * 16; idx += 256) {
        int rr = idx >> 10;
        int rem = idx & 1023;
        int xx = rem >> 4;
        int cc2 = (rem & 15) << 1;
        int yy = y0 - P + rr;
        __half2 val = __float2half2_rn(0.0f);
        if ((unsigned)yy < (unsigned)IMG)
            val = *(const __half2*)&vglob[(size_t)(yy * IMG + xx) * QLD + cc2];
        *(__half2*)&s_vt[(rr * 64 + xx) * 32 + cc2] = val;
    }

    const __half* qglob = g_qkvh + (size_t)(b * NTOK + y0 * IMG) * QLD + head * 32;
    for (int idx = tid; idx < 8 * 64 * 16; idx += 256) {
        int nloc = idx >> 4;
        int cc2 = (idx & 15) << 1;
        *(__half2*)&q_s[nloc * 32 + cc2] =
            *(const __half2*)&qglob[(size_t)nloc * QLD + cc2];
    }

    if (tid < 32) {
        float s = 0.0f;
#pragma unroll
        for (int ch = 0; ch < KVCH; ch++)
            s += g_csump[((size_t)ch * 64 + bh) * 32 + tid];
        c_s[tid] = 1.0f / s;
    }
    __syncthreads();

    for (int i = tid; i < 1024; i += 256) {
        float s = 0.0f;
#pragma unroll
        for (int ch = 0; ch < KVCH; ch++) s += g_kvp[((size_t)ch * 64 + bh) * 1024 + i];
        kv_s[i] = s * c_s[i >> 5];
    }

    int chb;
    const float* wp;
    const float* bp;
    if (head < 2)      { wp = w3; bp = b3; chb = head * 32; }
    else if (head < 5) { wp = w5; bp = b5; chb = head * 32 - 64; }
    else               { wp = w7; bp = b7; chb = head * 32 - 160; }
    int ntap = (head < 2) ? 9 : (head < 5) ? 25 : 49;
    if (tid < 32) bias_s[tid] = bp[chb + tid];
    __syncthreads();

    float kvcol[32];
#pragma unroll
    for (int kk = 0; kk < 32; kk++) kvcol[kk] = kv_s[kk * 32 + lane];

    const __half* qt = q_s + (size_t)w * 64 * 32;
    const __half* vt = s_vt + (size_t)w * 2048 + lane;
    const float* wsrc = wp + (size_t)(chb + lane) * ntap;
    float biasv = bias_s[lane];
    int y = y0 + w;

    if (head < 2)      conv_head<3>(qt, vt, wsrc, biasv, kvcol, b, head, y, lane);
    else if (head < 5) conv_head<5>(qt, vt, wsrc, biasv, kvcol, b, head, y, lane);
    else               conv_head<7>(qt, vt, wsrc, biasv, kvcol, b, head, y, lane);
}

// ---------------- launch -------------------------------------------------------
extern "C" void kernel_launch(void* const* d_in, const int* in_sizes, int n_in,
                              void* d_out, int out_size) {
    const float* x      = (const float*)d_in[0];
    const float* qkv_w  = (const float*)d_in[1];
    const float* proj_w = (const float*)d_in[2];
    const float* proj_b = (const float*)d_in[3];
    const float* gamma  = (const float*)d_in[4];
    const float* beta   = (const float*)d_in[5];
    const float* w3     = (const float*)d_in[6];
    const float* b3     = (const float*)d_in[7];
    const float* w5     = (const float*)d_in[8];
    const float* b5     = (const float*)d_in[9];
    const float* w7     = (const float*)d_in[10];
    const float* b7     = (const float*)d_in[11];
    float* out = (float*)d_out;

    void *p_xg, *p_qkv, *p_pre, *p_wq, *p_wp;
    cudaGetSymbolAddress(&p_xg, g_xgh);
    cudaGetSymbolAddress(&p_qkv, g_qkvh);
    cudaGetSymbolAddress(&p_pre, g_preh);
    cudaGetSymbolAddress(&p_wq, g_wqh);
    cudaGetSymbolAddress(&p_wp, g_wph);

    static int smem_set = 0;
    const int SMEM_BYTES = NSTG * 2 * BM * SSTH * 2;   // 110592
    const int SMEM_CONV = 14 * 64 * 32 * 2;            // 57344 (dynamic v tile)
    if (!smem_set) {
        cudaFuncSetAttribute(k_gemm_fp16<true>,
                             cudaFuncAttributeMaxDynamicSharedMemorySize, SMEM_BYTES);
        cudaFuncSetAttribute(k_gemm_fp16<false>,
                             cudaFuncAttributeMaxDynamicSharedMemorySize, SMEM_BYTES);
        cudaFuncSetAttribute(k_conv_att,
                             cudaFuncAttributeMaxDynamicSharedMemorySize, SMEM_CONV);
        smem_set = 1;
    }

    // 0+1. BN+hardswish -> fp16 AND weights -> fp16, single launch
    k_prep<<<PREP_BN_BLOCKS + (QLD * NC + 255) / 256, 256>>>(x, gamma, beta,
                                                             qkv_w, proj_w);

    // 2. qkv = xg @ qkv_w^T   [32768 x 768], K=256  (fp16 MMA, smem-staged fp16 out)
    k_gemm_fp16<true><<<dim3(QLD / BN, NB * NTOK / BM), 256, SMEM_BYTES>>>(
        (const __half*)p_xg, (const __half*)p_wq, p_qkv,
        NB * NTOK, QLD, NC, nullptr);

    // 3. kv + sum(exp(k)) fused, 16 chunks, f32x2-packed
    k_kv<<<dim3(KVCH, 64), 256>>>();

    // 4. conv (smem v+q tiles) + crpe + eff -> pre (fp16 out)
    k_conv_att<<<dim3(8, 8, 8), 256, SMEM_CONV>>>(w3, b3, w5, b5, w7, b7);

    // 5. out = pre @ proj_w^T + proj_b   [32768 x 256]  (fp32 out)
    k_gemm_fp16<false><<<dim3(NC / BN, NB * NTOK / BM), 256, SMEM_BYTES>>>(
        (const __half*)p_pre, (const __half*)p_wp, out,
        NB * NTOK, NC, NC, proj_b);
}

// round 13
// speedup vs baseline: 3.4945x; 1.2086x over previous
#include <cuda_runtime.h>
#include <cuda_fp16.h>
#include <math.h>

#define NB 8
#define NTOK 4096
#define NC 256
#define NH 8
#define CHD 32
#define IMG 64
#define QLD 768   // qkv row stride (3*C), in elements
#define KVCH 16   // kv token chunks (256 tokens each)

// ---------------- scratch (device globals; no allocation allowed) -------------
__device__ __half g_xgh[NB * NTOK * NC];         // fp16 BN+hardswish
__device__ __half g_qkvh[NB * NTOK * 3 * NC];    // fp16 qkv
__device__ float g_csump[KVCH * NB * NH * CHD];  // per-chunk sum(exp(k))
__device__ float g_kvp[KVCH * NB * NH * CHD * CHD];
__device__ __half g_kvh[NB * NH * CHD * CHD];    // normalized+scaled kv^T fp16
__device__ __half g_preh[NB * NTOK * NC];        // fp16 pre-proj
__device__ __half g_wqh[QLD * NC];               // fp16 qkv_w
__device__ __half g_wph[NC * NC];                // fp16 proj_w

// ---------------- packed f32x2 helpers (sm_100+) --------------------------------
__device__ __forceinline__ void fma_f32x2(unsigned long long& d,
                                          unsigned long long a,
                                          unsigned long long b) {
    asm("fma.rn.f32x2 %0, %1, %2, %0;" : "+l"(d) : "l"(a), "l"(b));
}
__device__ __forceinline__ unsigned long long pack_ff(float x, float y) {
    unsigned long long r;
    asm("mov.b64 %0, {%1, %2};" : "=l"(r) : "f"(x), "f"(y));
    return r;
}
__device__ __forceinline__ float2 unpack_ff(unsigned long long v) {
    float2 r;
    asm("mov.b64 {%0, %1}, %2;" : "=f"(r.x), "=f"(r.y) : "l"(v));
    return r;
}

// ---------------- K0: BN+hardswish -> fp16  AND  weights -> fp16 (one launch) ---
#define PREP_BN_BLOCKS 8192   // NB*NTOK*NC/4/256
__global__ __launch_bounds__(256) void k_prep(const float* __restrict__ x,
                                              const float* __restrict__ gamma,
                                              const float* __restrict__ beta,
                                              const float* __restrict__ wq,
                                              const float* __restrict__ wp) {
    if (blockIdx.x < PREP_BN_BLOCKS) {
        int i = blockIdx.x * 256 + threadIdx.x;    // float4 index
        float4 v = ((const float4*)x)[i];
        int c0 = (i & 63) * 4;
        const float inv = rsqrtf(1.0f + 1e-5f);
        float* f = (float*)&v;
        __half o[4];
#pragma unroll
        for (int j = 0; j < 4; j++) {
            float xb = f[j] * (gamma[c0 + j] * inv) + beta[c0 + j];
            o[j] = __float2half_rn(xb * fminf(fmaxf(xb + 3.0f, 0.0f), 6.0f) * (1.0f / 6.0f));
        }
        *(uint2*)&g_xgh[(size_t)i * 4] = *(uint2*)o;
    } else {
        int i = (blockIdx.x - PREP_BN_BLOCKS) * 256 + threadIdx.x;
        if (i < QLD * NC) g_wqh[i] = __float2half_rn(wq[i]);
        if (i < NC * NC)  g_wph[i] = __float2half_rn(wp[i]);
    }
}

// ---------------- fp16 tensor-core GEMM, 3-stage pipeline ----------------------
#define BM 128
#define BN 128
#define BK 64     // halves per chunk (128 bytes per row)
#define SSTH 72   // smem row stride (halves): 144B -> 16B-aligned, LDSM conflict-free
#define NSTG 3
#define OST 136   // epilogue smem tile row stride (halves): conflict-free STS

__device__ __forceinline__ void cpa16(void* dst, const void* src) {
    unsigned d = (unsigned)__cvta_generic_to_shared(dst);
    asm volatile("cp.async.cg.shared.global [%0], [%1], 16;\n" :: "r"(d), "l"(src));
}
__device__ __forceinline__ void cp_commit() { asm volatile("cp.async.commit_group;\n"); }

__device__ __forceinline__ void ldsm4(unsigned* r, const __half* p) {
    unsigned a = (unsigned)__cvta_generic_to_shared(p);
    asm volatile("ldmatrix.sync.aligned.m8n8.x4.shared.b16 {%0,%1,%2,%3}, [%4];"
                 : "=r"(r[0]), "=r"(r[1]), "=r"(r[2]), "=r"(r[3]) : "r"(a));
}

__device__ __forceinline__ void mma16(float* c, const unsigned* a, const unsigned* b) {
    asm volatile(
        "mma.sync.aligned.m16n8k16.row.col.f32.f16.f16.f32 "
        "{%0,%1,%2,%3}, {%4,%5,%6,%7}, {%8,%9}, {%0,%1,%2,%3};"
        : "+f"(c[0]), "+f"(c[1]), "+f"(c[2]), "+f"(c[3])
        : "r"(a[0]), "r"(a[1]), "r"(a[2]), "r"(a[3]), "r"(b[0]), "r"(b[1]));
}

extern __shared__ __align__(16) __half smem_h[];

// HOUT=true: fp16 output via smem-staged coalesced stores (bias must be null).
// HOUT=false: fp32 output direct (+bias).
template <bool HOUT>
__global__ __launch_bounds__(256, 2) void k_gemm_fp16(const __half* __restrict__ A,
                                                      const __half* __restrict__ W,
                                                      void* __restrict__ Cv,
                                                      int M, int Nd, int K,
                                                      const float* __restrict__ bias) {
    int tid = threadIdx.x;
    int m0 = blockIdx.y * BM, n0 = blockIdx.x * BN;
    int warp = tid >> 5, lane = tid & 31;
    int g = lane >> 2, t = lane & 3;
    int wm = (warp >> 2) * 64;
    int wn = (warp & 3) * 32;

    int al_row = lane & 15;
    int al_col = (lane >> 4) << 3;
    int bl_row = (lane & 7) + ((lane >> 4) << 3);
    int bl_col = ((lane >> 3) & 1) << 3;

    float acc[4][4][4];
#pragma unroll
    for (int mt = 0; mt < 4; mt++)
#pragma unroll
        for (int nt = 0; nt < 4; nt++)
#pragma unroll
            for (int r = 0; r < 4; r++) acc[mt][nt][r] = 0.0f;

    const int nch = K >> 6;

    auto issue = [&](int c, int stage) {
        if (c < nch) {
            __half* as = smem_h + stage * (2 * BM * SSTH);
            __half* bs = as + BM * SSTH;
            int k0 = c * BK;
#pragma unroll
            for (int j = 0; j < 4; j++) {
                int ci = tid + 256 * j;
                int row = ci >> 3;
                int kc = (ci & 7) << 3;
                cpa16(as + row * SSTH + kc, A + (size_t)(m0 + row) * K + k0 + kc);
                cpa16(bs + row * SSTH + kc, W + (size_t)(n0 + row) * K + k0 + kc);
            }
        }
        cp_commit();
    };

    issue(0, 0);
    issue(1, 1);

    for (int c = 0; c < nch; c++) {
        asm volatile("cp.async.wait_group 1;\n");
        __syncthreads();
        issue(c + 2, (c + 2) % NSTG);

        const __half* as = smem_h + (c % NSTG) * (2 * BM * SSTH);
        const __half* bs = as + BM * SSTH;
#pragma unroll
        for (int ks = 0; ks < 4; ks++) {
            int kb = ks * 16;
            unsigned af[4][4], bfr[2][4];
#pragma unroll
            for (int mt = 0; mt < 4; mt++)
                ldsm4(af[mt], as + (wm + mt * 16 + al_row) * SSTH + kb + al_col);
#pragma unroll
            for (int p = 0; p < 2; p++)
                ldsm4(bfr[p], bs + (wn + p * 16 + bl_row) * SSTH + kb + bl_col);
#pragma unroll
            for (int mt = 0; mt < 4; mt++)
#pragma unroll
                for (int nt = 0; nt < 4; nt++)
                    mma16(acc[mt][nt], af[mt], bfr[nt >> 1] + (nt & 1) * 2);
        }
    }

    if (HOUT) {
        __syncthreads();
        __half* os = smem_h;
#pragma unroll
        for (int mt = 0; mt < 4; mt++)
#pragma unroll
            for (int nt = 0; nt < 4; nt++) {
                int col = wn + nt * 8 + 2 * t;
                int row = wm + mt * 16 + g;
                *(__half2*)&os[row * OST + col] =
                    __floats2half2_rn(acc[mt][nt][0], acc[mt][nt][1]);
                *(__half2*)&os[(row + 8) * OST + col] =
                    __floats2half2_rn(acc[mt][nt][2], acc[mt][nt][3]);
            }
        __syncthreads();
        __half* Ch = (__half*)Cv;
#pragma unroll
        for (int j = 0; j < 8; j++) {
            int ci = tid + 256 * j;
            int row = ci >> 4;
            int hc = (ci & 15) << 3;
            *(uint4*)&Ch[(size_t)(m0 + row) * Nd + n0 + hc] =
                *(uint4*)&os[row * OST + hc];
        }
    } else {
#pragma unroll
        for (int mt = 0; mt < 4; mt++)
#pragma unroll
            for (int nt = 0; nt < 4; nt++) {
                int col = n0 + wn + nt * 8 + 2 * t;
                float b0 = bias ? bias[col] : 0.0f;
                float b1 = bias ? bias[col + 1] : 0.0f;
                int row0 = m0 + wm + mt * 16 + g;
                float* Cf = (float*)Cv;
                float2 o0 = make_float2(acc[mt][nt][0] + b0, acc[mt][nt][1] + b1);
                float2 o1 = make_float2(acc[mt][nt][2] + b0, acc[mt][nt][3] + b1);
                *(float2*)&Cf[(size_t)row0 * Nd + col] = o0;
                *(float2*)&Cf[(size_t)(row0 + 8) * Nd + col] = o1;
            }
    }
}

// ---------------- K3: kv = exp(k)^T v + sum(exp(k)), f32x2-packed 4x4 ----------
__global__ __launch_bounds__(256) void k_kv() {
    int chunk = blockIdx.x;
    int bh = blockIdx.y;
    int b = bh >> 3, head = bh & 7;

    __shared__ __align__(16) float ks[128][32];
    __shared__ __align__(16) float vs[128][32];

    int tid = threadIdx.x;
    int grp = tid >> 6;
    int t64 = tid & 63;
    int kq = (t64 >> 3) << 2;
    int vq = (t64 & 7) << 2;
    int c2 = (tid & 15) << 1;
    int jj = tid >> 4;

    const __half* base = g_qkvh + (size_t)(b * NTOK + chunk * (NTOK / KVCH)) * QLD + head * 32;

    unsigned long long accp[4][2];
#pragma unroll
    for (int i = 0; i < 4; i++) { accp[i][0] = 0ull; accp[i][1] = 0ull; }
    float sA = 0.0f, sB = 0.0f;

    for (int tch = 0; tch < (NTOK / KVCH) / 128; tch++) {
        const __half* tb = base + (size_t)tch * 128 * QLD;
#pragma unroll
        for (int it = 0; it < 8; it++) {
            int r = jj + it * 16;
            size_t off = (size_t)r * QLD + c2;
            float2 fk = __half22float2(*(const __half2*)&tb[off + 256]);
            float e0 = __expf(fk.x), e1 = __expf(fk.y);
            *(float2*)&ks[r][c2] = make_float2(e0, e1);
            sA += e0; sB += e1;
            float2 fv = __half22float2(*(const __half2*)&tb[off + 512]);
            *(float2*)&vs[r][c2] = fv;
        }
        __syncthreads();

        int rbeg = grp * 32;
#pragma unroll 4
        for (int r = rbeg; r < rbeg + 32; r++) {
            float4 kk = *(const float4*)&ks[r][kq];
            ulonglong2 vvp = *(const ulonglong2*)&vs[r][vq];
            unsigned long long kb;
            kb = pack_ff(kk.x, kk.x);
            fma_f32x2(accp[0][0], kb, vvp.x); fma_f32x2(accp[0][1], kb, vvp.y);
            kb = pack_ff(kk.y, kk.y);
            fma_f32x2(accp[1][0], kb, vvp.x); fma_f32x2(accp[1][1], kb, vvp.y);
            kb = pack_ff(kk.z, kk.z);
            fma_f32x2(accp[2][0], kb, vvp.x); fma_f32x2(accp[2][1], kb, vvp.y);
            kb = pack_ff(kk.w, kk.w);
            fma_f32x2(accp[3][0], kb, vvp.x); fma_f32x2(accp[3][1], kb, vvp.y);
        }
        __syncthreads();
    }

    float* red   = &ks[0][0];
    float* red_s = &vs[0][0];
#pragma unroll
    for (int ki = 0; ki < 4; ki++) {
        float2 a01 = unpack_ff(accp[ki][0]);
        float2 a23 = unpack_ff(accp[ki][1]);
        red[grp * 1024 + (kq + ki) * 32 + vq + 0] = a01.x;
        red[grp * 1024 + (kq + ki) * 32 + vq + 1] = a01.y;
        red[grp * 1024 + (kq + ki) * 32 + vq + 2] = a23.x;
        red[grp * 1024 + (kq + ki) * 32 + vq + 3] = a23.y;
    }
    red_s[c2 * 17 + jj] = sA;
    red_s[(c2 + 1) * 17 + jj] = sB;
    __syncthreads();

    for (int i = tid; i < 1024; i += 256) {
        float s = red[i] + red[1024 + i] + red[2048 + i] + red[3072 + i];
        g_kvp[((size_t)chunk * 64 + bh) * 1024 + i] = s;
    }
    if (tid < 32) {
        float ss = 0.0f;
#pragma unroll
        for (int j = 0; j < 16; j++) ss += red_s[tid * 17 + j];
        g_csump[((size_t)chunk * 64 + bh) * 32 + tid] = ss;
    }
}

// ---------------- K3b: reduce kv partials, normalize, scale, transpose -> fp16 --
__global__ __launch_bounds__(256) void k_kvred() {
    int bh = blockIdx.x;
    int tid = threadIdx.x;
    __shared__ float cinv[32];
    const float scale = 0.1767766952966369f;   // 32^-0.5, folded in here

    if (tid < 32) {
        float s = 0.0f;
#pragma unroll
        for (int ch = 0; ch < KVCH; ch++)
            s += g_csump[((size_t)ch * 64 + bh) * 32 + tid];
        cinv[tid] = scale / s;
    }
    __syncthreads();

    for (int i = tid; i < 1024; i += 256) {
        float s = 0.0f;
#pragma unroll
        for (int ch = 0; ch < KVCH; ch++) s += g_kvp[((size_t)ch * 64 + bh) * 1024 + i];
        int k = i >> 5, v = i & 31;
        g_kvh[bh * 1024 + v * 32 + k] = __float2half_rn(s * cinv[k]);   // transposed
    }
}

// ---------------- K3c: eff = q @ kvh^T via tensor cores -> g_preh --------------
#define EQS 40    // q smem row stride (halves): r*80 mod 128 hits all 16B groups
__global__ __launch_bounds__(256, 2) void k_eff() {
    int chunk = blockIdx.x;            // 0..7 (512 tokens each)
    int bh = blockIdx.y;
    int b = bh >> 3, head = bh & 7;

    __half* qs = smem_h;               // 512 x EQS
    __half* ks = smem_h + 512 * EQS;   // 32 x EQS (kvh: row=v, col=k)

    int tid = threadIdx.x;
    int warp = tid >> 5, lane = tid & 31;
    int g = lane >> 2, t = lane & 3;

    // stage q: 512 rows x 32 halves = 2048 16B chunks (4 per row)
    const __half* qg = g_qkvh + (size_t)(b * NTOK + chunk * 512) * QLD + head * 32;
#pragma unroll
    for (int j = 0; j < 8; j++) {
        int ci = tid + 256 * j;            // 0..2047
        int row = ci >> 2;                 // 0..511
        int hc = (ci & 3) << 3;            // 0,8,16,24
        cpa16(qs + row * EQS + hc, qg + (size_t)row * QLD + hc);
    }
    // stage kvh: 32 rows x 32 halves = 128 chunks (4 per row)
    if (tid < 128) {
        int row = tid >> 2;                // 0..31
        int hc = (tid & 3) << 3;           // 0,8,16,24
        cpa16(ks + row * EQS + hc, g_kvh + bh * 1024 + row * 32 + hc);
    }
    cp_commit();
    asm volatile("cp.async.wait_group 0;\n");
    __syncthreads();

    int al_row = lane & 15;
    int al_col = (lane >> 4) << 3;
    int bl_row = (lane & 7) + ((lane >> 4) << 3);
    int bl_col = ((lane >> 3) & 1) << 3;

    float acc[4][4][4];
#pragma unroll
    for (int mt = 0; mt < 4; mt++)
#pragma unroll
        for (int nt = 0; nt < 4; nt++)
#pragma unroll
            for (int r = 0; r < 4; r++) acc[mt][nt][r] = 0.0f;

#pragma unroll
    for (int kst = 0; kst < 2; kst++) {
        int kb = kst * 16;
        unsigned af[4][4], bfr[2][4];
#pragma unroll
        for (int mt = 0; mt < 4; mt++)
            ldsm4(af[mt], qs + (warp * 64 + mt * 16 + al_row) * EQS + kb + al_col);
#pragma unroll
        for (int p = 0; p < 2; p++)
            ldsm4(bfr[p], ks + (p * 16 + bl_row) * EQS + kb + bl_col);
#pragma unroll
        for (int mt = 0; mt < 4; mt++)
#pragma unroll
            for (int nt = 0; nt < 4; nt++)
                mma16(acc[mt][nt], af[mt], bfr[nt >> 1] + (nt & 1) * 2);
    }

    // stage output (overwrite q region) then coalesced store
    __syncthreads();
    __half* os = smem_h;               // 512 x 32 compact
#pragma unroll
    for (int mt = 0; mt < 4; mt++)
#pragma unroll
        for (int nt = 0; nt < 4; nt++) {
            int row = warp * 64 + mt * 16 + g;
            int col = nt * 8 + 2 * t;
            *(__half2*)&os[row * 32 + col] =
                __floats2half2_rn(acc[mt][nt][0], acc[mt][nt][1]);
            *(__half2*)&os[(row + 8) * 32 + col] =
                __floats2half2_rn(acc[mt][nt][2], acc[mt][nt][3]);
        }
    __syncthreads();

    __half* pg = g_preh + (size_t)(b * NTOK + chunk * 512) * NC + head * 32;
#pragma unroll
    for (int j = 0; j < 8; j++) {
        int ci = tid + 256 * j;            // 0..2047 chunks
        int row = ci >> 2;
        int hc = (ci & 3) << 3;
        *(uint4*)&pg[(size_t)row * NC + hc] = *(uint4*)&os[row * 32 + hc];
    }
}

// ---------------- K4: depthwise conv (smem v tile) + gating, adds to pre -------
extern __shared__ __align__(16) __half s_vt[];   // [nrows][64][32] halves (dynamic)

template <int KSZ>
__device__ __forceinline__ void conv_head(const __half* __restrict__ qg,   // stride QLD
                                          __half* __restrict__ pg,         // stride NC
                                          const __half* __restrict__ vt,
                                          const float* __restrict__ wsrc,
                                          float biasv) {
    const int P = KSZ / 2;

    float wreg[KSZ * KSZ];
#pragma unroll
    for (int i = 0; i < KSZ * KSZ; i++) wreg[i] = wsrc[i];

    float win[KSZ][KSZ];
#pragma unroll
    for (int dy = 0; dy < KSZ; dy++)
#pragma unroll
        for (int j = 0; j < KSZ; j++) win[dy][j] = 0.0f;

#pragma unroll
    for (int xx = 0; xx < P; xx++) {
#pragma unroll
        for (int dy = 0; dy < KSZ; dy++)
            win[dy][xx] = __half2float(vt[dy * 2048 + xx * 32]);
    }

    for (int xb = 0; xb < IMG; xb += KSZ) {
#pragma unroll
        for (int xi = 0; xi < KSZ; xi++) {
            int x = xb + xi;
            if (x < IMG) {                       // IMG % KSZ != 0: guard the tail
                const int slot_new = (xi + P) % KSZ;
                int xn = x + P;
                if (xn < IMG) {
#pragma unroll
                    for (int dy = 0; dy < KSZ; dy++)
                        win[dy][slot_new] = __half2float(vt[dy * 2048 + xn * 32]);
                } else {
#pragma unroll
                    for (int dy = 0; dy < KSZ; dy++) win[dy][slot_new] = 0.0f;
                }

                float q = __half2float(qg[(size_t)x * QLD]);
                float prev = __half2float(pg[(size_t)x * NC]);

                float acc = biasv;
#pragma unroll
                for (int dy = 0; dy < KSZ; dy++)
#pragma unroll
                    for (int dx = 0; dx < KSZ; dx++) {
                        const int slot = (xi + dx + 2 * KSZ - P) % KSZ;
                        acc += win[dy][slot] * wreg[dy * KSZ + dx];
                    }

                pg[(size_t)x * NC] = __float2half_rn(prev + q * acc);
            }
        }
    }
}

__global__ __launch_bounds__(256, 2) void k_conv_att(const float* __restrict__ w3,
                                                     const float* __restrict__ b3,
                                                     const float* __restrict__ w5,
                                                     const float* __restrict__ b5,
                                                     const float* __restrict__ w7,
                                                     const float* __restrict__ b7) {
    int yt = blockIdx.x;
    int head = blockIdx.y;
    int b = blockIdx.z;
    int lane = threadIdx.x & 31, w = threadIdx.x >> 5;
    int tid = threadIdx.x;

    __shared__ float bias_s[32];

    int P = (head < 2) ? 1 : (head < 5) ? 2 : 3;
    int nrows = 8 + 2 * P;
    int y0 = yt * 8;

    // fill v halo tile (zero-padded outside image)
    const __half* vglob = g_qkvh + (size_t)b * NTOK * QLD + 512 + head * 32;
    for (int idx = tid; idx < nrows * 64 * 16; idx += 256) {
        int rr = idx >> 10;
        int rem = idx & 1023;
        int xx = rem >> 4;
        int cc2 = (rem & 15) << 1;
        int yy = y0 - P + rr;
        __half2 val = __float2half2_rn(0.0f);
        if ((unsigned)yy < (unsigned)IMG)
            val = *(const __half2*)&vglob[(size_t)(yy * IMG + xx) * QLD + cc2];
        *(__half2*)&s_vt[(rr * 64 + xx) * 32 + cc2] = val;
    }

    int chb;
    const float* wp;
    const float* bp;
    if (head < 2)      { wp = w3; bp = b3; chb = head * 32; }
    else if (head < 5) { wp = w5; bp = b5; chb = head * 32 - 64; }
    else               { wp = w7; bp = b7; chb = head * 32 - 160; }
    int ntap = (head < 2) ? 9 : (head < 5) ? 25 : 49;
    if (tid < 32) bias_s[tid] = bp[chb + tid];
    __syncthreads();

    int y = y0 + w;
    const __half* qg = g_qkvh + (size_t)(b * NTOK + y * IMG) * QLD + head * 32 + lane;
    __half* pg = g_preh + (size_t)(b * NTOK + y * IMG) * NC + head * 32 + lane;
    const __half* vt = s_vt + (size_t)w * 2048 + lane;
    const float* wsrc = wp + (size_t)(chb + lane) * ntap;
    float biasv = bias_s[lane];

    if (head < 2)      conv_head<3>(qg, pg, vt, wsrc, biasv);
    else if (head < 5) conv_head<5>(qg, pg, vt, wsrc, biasv);
    else               conv_head<7>(qg, pg, vt, wsrc, biasv);
}

// ---------------- launch -------------------------------------------------------
extern "C" void kernel_launch(void* const* d_in, const int* in_sizes, int n_in,
                              void* d_out, int out_size) {
    const float* x      = (const float*)d_in[0];
    const float* qkv_w  = (const float*)d_in[1];
    const float* proj_w = (const float*)d_in[2];
    const float* proj_b = (const float*)d_in[3];
    const float* gamma  = (const float*)d_in[4];
    const float* beta   = (const float*)d_in[5];
    const float* w3     = (const float*)d_in[6];
    const float* b3     = (const float*)d_in[7];
    const float* w5     = (const float*)d_in[8];
    const float* b5     = (const float*)d_in[9];
    const float* w7     = (const float*)d_in[10];
    const float* b7     = (const float*)d_in[11];
    float* out = (float*)d_out;

    void *p_xg, *p_qkv, *p_pre, *p_wq, *p_wp;
    cudaGetSymbolAddress(&p_xg, g_xgh);
    cudaGetSymbolAddress(&p_qkv, g_qkvh);
    cudaGetSymbolAddress(&p_pre, g_preh);
    cudaGetSymbolAddress(&p_wq, g_wqh);
    cudaGetSymbolAddress(&p_wp, g_wph);

    static int smem_set = 0;
    const int SMEM_BYTES = NSTG * 2 * BM * SSTH * 2;   // 110592
    const int SMEM_CONV = 14 * 64 * 32 * 2;            // 57344 (dynamic v tile)
    const int SMEM_EFF = (512 * EQS + 32 * EQS) * 2;   // 43520
    if (!smem_set) {
        cudaFuncSetAttribute(k_gemm_fp16<true>,
                             cudaFuncAttributeMaxDynamicSharedMemorySize, SMEM_BYTES);
        cudaFuncSetAttribute(k_gemm_fp16<false>,
                             cudaFuncAttributeMaxDynamicSharedMemorySize, SMEM_BYTES);
        cudaFuncSetAttribute(k_conv_att,
                             cudaFuncAttributeMaxDynamicSharedMemorySize, SMEM_CONV);
        cudaFuncSetAttribute(k_eff,
                             cudaFuncAttributeMaxDynamicSharedMemorySize, SMEM_EFF);
        smem_set = 1;
    }

    // 0. BN+hardswish -> fp16 AND weights -> fp16
    k_prep<<<PREP_BN_BLOCKS + (QLD * NC + 255) / 256, 256>>>(x, gamma, beta,
                                                             qkv_w, proj_w);

    // 1. qkv = xg @ qkv_w^T   [32768 x 768], K=256
    k_gemm_fp16<true><<<dim3(QLD / BN, NB * NTOK / BM), 256, SMEM_BYTES>>>(
        (const __half*)p_xg, (const __half*)p_wq, p_qkv,
        NB * NTOK, QLD, NC, nullptr);

    // 2. kv partials + sum(exp(k))
    k_kv<<<dim3(KVCH, 64), 256>>>();

    // 3. reduce + normalize + scale + transpose kv -> fp16
    k_kvred<<<64, 256>>>();

    // 4. eff = q @ kvh^T (tensor cores) -> g_preh
    k_eff<<<dim3(8, 64), 256, SMEM_EFF>>>();

    // 5. conv + gating, accumulate into g_preh
    k_conv_att<<<dim3(8, 8, 8), 256, SMEM_CONV>>>(w3, b3, w5, b5, w7, b7);

    // 6. out = pre @ proj_w^T + proj_b   [32768 x 256]
    k_gemm_fp16<false><<<dim3(NC / BN, NB * NTOK / BM), 256, SMEM_BYTES>>>(
        (const __half*)p_pre, (const __half*)p_wp, out,
        NB * NTOK, NC, NC, proj_b);
}

// round 14
// speedup vs baseline: 3.6212x; 1.0363x over previous
#include <cuda_runtime.h>
#include <cuda_fp16.h>
#include <math.h>

#define NB 8
#define NTOK 4096
#define NC 256
#define NH 8
#define CHD 32
#define IMG 64
#define QLD 768   // qkv row stride (3*C), in elements
#define KVCH 16   // kv token chunks (256 tokens each)

// ---------------- scratch (device globals; no allocation allowed) -------------
__device__ __half g_xgh[NB * NTOK * NC];         // fp16 BN+hardswish
__device__ __half g_qkvh[NB * NTOK * 3 * NC];    // fp16 qkv
__device__ float g_csump[KVCH * NB * NH * CHD];  // per-chunk sum(exp(k))
__device__ float g_kvp[KVCH * NB * NH * CHD * CHD];
__device__ __half g_preh[NB * NTOK * NC];        // fp16 pre-proj
__device__ __half g_wqh[QLD * NC];               // fp16 qkv_w
__device__ __half g_wph[NC * NC];                // fp16 proj_w

// ---------------- packed f32x2 helpers (sm_100+) --------------------------------
__device__ __forceinline__ void fma_f32x2(unsigned long long& d,
                                          unsigned long long a,
                                          unsigned long long b) {
    asm("fma.rn.f32x2 %0, %1, %2, %0;" : "+l"(d) : "l"(a), "l"(b));
}
__device__ __forceinline__ unsigned long long pack_ff(float x, float y) {
    unsigned long long r;
    asm("mov.b64 %0, {%1, %2};" : "=l"(r) : "f"(x), "f"(y));
    return r;
}
__device__ __forceinline__ float2 unpack_ff(unsigned long long v) {
    float2 r;
    asm("mov.b64 {%0, %1}, %2;" : "=f"(r.x), "=f"(r.y) : "l"(v));
    return r;
}

// ---------------- K0: BN+hardswish -> fp16  AND  weights -> fp16 (one launch) ---
#define PREP_BN_BLOCKS 8192   // NB*NTOK*NC/4/256
__global__ __launch_bounds__(256) void k_prep(const float* __restrict__ x,
                                              const float* __restrict__ gamma,
                                              const float* __restrict__ beta,
                                              const float* __restrict__ wq,
                                              const float* __restrict__ wp) {
    if (blockIdx.x < PREP_BN_BLOCKS) {
        int i = blockIdx.x * 256 + threadIdx.x;    // float4 index
        float4 v = ((const float4*)x)[i];
        int c0 = (i & 63) * 4;
        const float inv = rsqrtf(1.0f + 1e-5f);
        float* f = (float*)&v;
        __half o[4];
#pragma unroll
        for (int j = 0; j < 4; j++) {
            float xb = f[j] * (gamma[c0 + j] * inv) + beta[c0 + j];
            o[j] = __float2half_rn(xb * fminf(fmaxf(xb + 3.0f, 0.0f), 6.0f) * (1.0f / 6.0f));
        }
        *(uint2*)&g_xgh[(size_t)i * 4] = *(uint2*)o;
    } else {
        int i = (blockIdx.x - PREP_BN_BLOCKS) * 256 + threadIdx.x;
        if (i < QLD * NC) g_wqh[i] = __float2half_rn(wq[i]);
        if (i < NC * NC)  g_wph[i] = __float2half_rn(wp[i]);
    }
}

// ---------------- fp16 tensor-core GEMM, 3-stage pipeline ----------------------
#define BM 128
#define BN 128
#define BK 64     // halves per chunk (128 bytes per row)
#define SSTH 72   // smem row stride (halves): 144B -> 16B-aligned, LDSM conflict-free
#define NSTG 3
#define OST 136   // epilogue smem tile row stride (halves): conflict-free STS

__device__ __forceinline__ void cpa16(void* dst, const void* src) {
    unsigned d = (unsigned)__cvta_generic_to_shared(dst);
    asm volatile("cp.async.cg.shared.global [%0], [%1], 16;\n" :: "r"(d), "l"(src));
}
__device__ __forceinline__ void cp_commit() { asm volatile("cp.async.commit_group;\n"); }

__device__ __forceinline__ void ldsm4(unsigned* r, const __half* p) {
    unsigned a = (unsigned)__cvta_generic_to_shared(p);
    asm volatile("ldmatrix.sync.aligned.m8n8.x4.shared.b16 {%0,%1,%2,%3}, [%4];"
                 : "=r"(r[0]), "=r"(r[1]), "=r"(r[2]), "=r"(r[3]) : "r"(a));
}

__device__ __forceinline__ void mma16(float* c, const unsigned* a, const unsigned* b) {
    asm volatile(
        "mma.sync.aligned.m16n8k16.row.col.f32.f16.f16.f32 "
        "{%0,%1,%2,%3}, {%4,%5,%6,%7}, {%8,%9}, {%0,%1,%2,%3};"
        : "+f"(c[0]), "+f"(c[1]), "+f"(c[2]), "+f"(c[3])
        : "r"(a[0]), "r"(a[1]), "r"(a[2]), "r"(a[3]), "r"(b[0]), "r"(b[1]));
}

extern __shared__ __align__(16) __half smem_h[];

// HOUT=true: fp16 output via smem-staged coalesced stores (bias must be null).
// HOUT=false: fp32 output direct (+bias).
template <bool HOUT>
__global__ __launch_bounds__(256, 2) void k_gemm_fp16(const __half* __restrict__ A,
                                                      const __half* __restrict__ W,
                                                      void* __restrict__ Cv,
                                                      int M, int Nd, int K,
                                                      const float* __restrict__ bias) {
    int tid = threadIdx.x;
    int m0 = blockIdx.y * BM, n0 = blockIdx.x * BN;
    int warp = tid >> 5, lane = tid & 31;
    int g = lane >> 2, t = lane & 3;
    int wm = (warp >> 2) * 64;
    int wn = (warp & 3) * 32;

    int al_row = lane & 15;
    int al_col = (lane >> 4) << 3;
    int bl_row = (lane & 7) + ((lane >> 4) << 3);
    int bl_col = ((lane >> 3) & 1) << 3;

    float acc[4][4][4];
#pragma unroll
    for (int mt = 0; mt < 4; mt++)
#pragma unroll
        for (int nt = 0; nt < 4; nt++)
#pragma unroll
            for (int r = 0; r < 4; r++) acc[mt][nt][r] = 0.0f;

    const int nch = K >> 6;

    auto issue = [&](int c, int stage) {
        if (c < nch) {
            __half* as = smem_h + stage * (2 * BM * SSTH);
            __half* bs = as + BM * SSTH;
            int k0 = c * BK;
#pragma unroll
            for (int j = 0; j < 4; j++) {
                int ci = tid + 256 * j;
                int row = ci >> 3;
                int kc = (ci & 7) << 3;
                cpa16(as + row * SSTH + kc, A + (size_t)(m0 + row) * K + k0 + kc);
                cpa16(bs + row * SSTH + kc, W + (size_t)(n0 + row) * K + k0 + kc);
            }
        }
        cp_commit();
    };

    issue(0, 0);
    issue(1, 1);

    for (int c = 0; c < nch; c++) {
        asm volatile("cp.async.wait_group 1;\n");
        __syncthreads();
        issue(c + 2, (c + 2) % NSTG);

        const __half* as = smem_h + (c % NSTG) * (2 * BM * SSTH);
        const __half* bs = as + BM * SSTH;
#pragma unroll
        for (int ks = 0; ks < 4; ks++) {
            int kb = ks * 16;
            unsigned af[4][4], bfr[2][4];
#pragma unroll
            for (int mt = 0; mt < 4; mt++)
                ldsm4(af[mt], as + (wm + mt * 16 + al_row) * SSTH + kb + al_col);
#pragma unroll
            for (int p = 0; p < 2; p++)
                ldsm4(bfr[p], bs + (wn + p * 16 + bl_row) * SSTH + kb + bl_col);
#pragma unroll
            for (int mt = 0; mt < 4; mt++)
#pragma unroll
                for (int nt = 0; nt < 4; nt++)
                    mma16(acc[mt][nt], af[mt], bfr[nt >> 1] + (nt & 1) * 2);
        }
    }

    if (HOUT) {
        __syncthreads();
        __half* os = smem_h;
#pragma unroll
        for (int mt = 0; mt < 4; mt++)
#pragma unroll
            for (int nt = 0; nt < 4; nt++) {
                int col = wn + nt * 8 + 2 * t;
                int row = wm + mt * 16 + g;
                *(__half2*)&os[row * OST + col] =
                    __floats2half2_rn(acc[mt][nt][0], acc[mt][nt][1]);
                *(__half2*)&os[(row + 8) * OST + col] =
                    __floats2half2_rn(acc[mt][nt][2], acc[mt][nt][3]);
            }
        __syncthreads();
        __half* Ch = (__half*)Cv;
#pragma unroll
        for (int j = 0; j < 8; j++) {
            int ci = tid + 256 * j;
            int row = ci >> 4;
            int hc = (ci & 15) << 3;
            *(uint4*)&Ch[(size_t)(m0 + row) * Nd + n0 + hc] =
                *(uint4*)&os[row * OST + hc];
        }
    } else {
#pragma unroll
        for (int mt = 0; mt < 4; mt++)
#pragma unroll
            for (int nt = 0; nt < 4; nt++) {
                int col = n0 + wn + nt * 8 + 2 * t;
                float b0 = bias ? bias[col] : 0.0f;
                float b1 = bias ? bias[col + 1] : 0.0f;
                int row0 = m0 + wm + mt * 16 + g;
                float* Cf = (float*)Cv;
                float2 o0 = make_float2(acc[mt][nt][0] + b0, acc[mt][nt][1] + b1);
                float2 o1 = make_float2(acc[mt][nt][2] + b0, acc[mt][nt][3] + b1);
                *(float2*)&Cf[(size_t)row0 * Nd + col] = o0;
                *(float2*)&Cf[(size_t)(row0 + 8) * Nd + col] = o1;
            }
    }
}

// ---------------- K3: kv = exp(k)^T v + sum(exp(k)), 8x4 per-thread tiles ------
// 8 warp-groups; each row read by exactly ONE warp (halves LDS wavefronts).
__global__ __launch_bounds__(256) void k_kv() {
    int chunk = blockIdx.x;            // 0..KVCH-1 (256 tokens each)
    int bh = blockIdx.y;
    int b = bh >> 3, head = bh & 7;

    __shared__ __align__(16) float ksvs[2][128][32];   // k tile / v tile (32 KB)
    __shared__ float sred[32 * 17];                    // sexp partials

    float (*ks)[32] = ksvs[0];
    float (*vs)[32] = ksvs[1];

    int tid = threadIdx.x;
    int lane = tid & 31, grp = tid >> 5;   // 8 warp-groups
    int kb = (lane >> 3) << 3;             // k-channel base: 0,8,16,24
    int vq = (lane & 7) << 2;              // v-channel base: 0,4,...,28
    int c2 = (tid & 15) << 1;              // fill: channel pair
    int jj = tid >> 4;                     // fill: row group 0..15

    const __half* base = g_qkvh + (size_t)(b * NTOK + chunk * (NTOK / KVCH)) * QLD + head * 32;

    unsigned long long accp[8][2];
#pragma unroll
    for (int i = 0; i < 8; i++) { accp[i][0] = 0ull; accp[i][1] = 0ull; }
    float sA = 0.0f, sB = 0.0f;

    for (int tch = 0; tch < (NTOK / KVCH) / 128; tch++) {
        const __half* tb = base + (size_t)tch * 128 * QLD;
#pragma unroll
        for (int it = 0; it < 8; it++) {
            int r = jj + it * 16;
            size_t off = (size_t)r * QLD + c2;
            float2 fk = __half22float2(*(const __half2*)&tb[off + 256]);
            float e0 = __expf(fk.x), e1 = __expf(fk.y);
            *(float2*)&ks[r][c2] = make_float2(e0, e1);
            sA += e0; sB += e1;
            float2 fv = __half22float2(*(const __half2*)&tb[off + 512]);
            *(float2*)&vs[r][c2] = fv;
        }
        __syncthreads();

        int rbeg = grp * 16;               // each warp owns 16 rows
#pragma unroll 4
        for (int r = rbeg; r < rbeg + 16; r++) {
            float4 k0 = *(const float4*)&ks[r][kb];
            float4 k1 = *(const float4*)&ks[r][kb + 4];
            ulonglong2 vvp = *(const ulonglong2*)&vs[r][vq];
            unsigned long long kp;
            kp = pack_ff(k0.x, k0.x);
            fma_f32x2(accp[0][0], kp, vvp.x); fma_f32x2(accp[0][1], kp, vvp.y);
            kp = pack_ff(k0.y, k0.y);
            fma_f32x2(accp[1][0], kp, vvp.x); fma_f32x2(accp[1][1], kp, vvp.y);
            kp = pack_ff(k0.z, k0.z);
            fma_f32x2(accp[2][0], kp, vvp.x); fma_f32x2(accp[2][1], kp, vvp.y);
            kp = pack_ff(k0.w, k0.w);
            fma_f32x2(accp[3][0], kp, vvp.x); fma_f32x2(accp[3][1], kp, vvp.y);
            kp = pack_ff(k1.x, k1.x);
            fma_f32x2(accp[4][0], kp, vvp.x); fma_f32x2(accp[4][1], kp, vvp.y);
            kp = pack_ff(k1.y, k1.y);
            fma_f32x2(accp[5][0], kp, vvp.x); fma_f32x2(accp[5][1], kp, vvp.y);
            kp = pack_ff(k1.z, k1.z);
            fma_f32x2(accp[6][0], kp, vvp.x); fma_f32x2(accp[6][1], kp, vvp.y);
            kp = pack_ff(k1.w, k1.w);
            fma_f32x2(accp[7][0], kp, vvp.x); fma_f32x2(accp[7][1], kp, vvp.y);
        }
        __syncthreads();
    }

    // sexp partials (separate array, safe to write now)
    sred[c2 * 17 + jj] = sA;
    sred[(c2 + 1) * 17 + jj] = sB;

    // group partials: alias freed tiles (8 groups x 1024, exactly 8192 floats)
    float* red = &ksvs[0][0][0];
#pragma unroll
    for (int ki = 0; ki < 8; ki++) {
        float2 a01 = unpack_ff(accp[ki][0]);
        float2 a23 = unpack_ff(accp[ki][1]);
        int o = grp * 1024 + (kb + ki) * 32 + vq;
        red[o + 0] = a01.x;
        red[o + 1] = a01.y;
        red[o + 2] = a23.x;
        red[o + 3] = a23.y;
    }
    __syncthreads();

    for (int i = tid; i < 1024; i += 256) {
        float s = 0.0f;
#pragma unroll
        for (int gg = 0; gg < 8; gg++) s += red[gg * 1024 + i];
        g_kvp[((size_t)chunk * 64 + bh) * 1024 + i] = s;
    }
    if (tid < 32) {
        float ss = 0.0f;
#pragma unroll
        for (int j = 0; j < 16; j++) ss += sred[tid * 17 + j];
        g_csump[((size_t)chunk * 64 + bh) * 32 + tid] = ss;
    }
}

// ---------------- K3b: eff = q @ kv^T via tensor cores (kv reduce fused) -------
#define EQS 40    // q smem row stride (halves): r*80 mod 128 hits all 16B groups
__global__ __launch_bounds__(256, 2) void k_eff() {
    int chunk = blockIdx.x;            // 0..7 (512 tokens each)
    int bh = blockIdx.y;
    int b = bh >> 3, head = bh & 7;

    __half* qs = smem_h;               // 512 x EQS
    __half* ks = smem_h + 512 * EQS;   // 32 x EQS (row=v, col=k)
    __shared__ float cinv[32];

    int tid = threadIdx.x;
    int warp = tid >> 5, lane = tid & 31;
    int g = lane >> 2, t = lane & 3;
    const float scale = 0.1767766952966369f;   // 32^-0.5

    // issue q staging: 512 rows x 32 halves = 2048 16B chunks (4 per row)
    const __half* qg = g_qkvh + (size_t)(b * NTOK + chunk * 512) * QLD + head * 32;
#pragma unroll
    for (int j = 0; j < 8; j++) {
        int ci = tid + 256 * j;            // 0..2047
        int row = ci >> 2;                 // 0..511
        int hc = (ci & 3) << 3;            // 0,8,16,24
        cpa16(qs + row * EQS + hc, qg + (size_t)row * QLD + hc);
    }
    cp_commit();

    // fused kvred phase 1: column inverse sums
    if (tid < 32) {
        float s = 0.0f;
#pragma unroll
        for (int ch = 0; ch < KVCH; ch++)
            s += g_csump[((size_t)ch * 64 + bh) * 32 + tid];
        cinv[tid] = scale / s;
    }
    __syncthreads();

    // fused kvred phase 2: reduce partials, normalize, transpose into ks
#pragma unroll
    for (int j = 0; j < 4; j++) {
        int i = tid + 256 * j;             // 0..1023
        float s = 0.0f;
#pragma unroll
        for (int ch = 0; ch < KVCH; ch++)
            s += g_kvp[((size_t)ch * 64 + bh) * 1024 + i];
        int k = i >> 5, v = i & 31;
        ks[v * EQS + k] = __float2half_rn(s * cinv[k]);
    }

    asm volatile("cp.async.wait_group 0;\n");
    __syncthreads();

    int al_row = lane & 15;
    int al_col = (lane >> 4) << 3;
    int bl_row = (lane & 7) + ((lane >> 4) << 3);
    int bl_col = ((lane >> 3) & 1) << 3;

    float acc[4][4][4];
#pragma unroll
    for (int mt = 0; mt < 4; mt++)
#pragma unroll
        for (int nt = 0; nt < 4; nt++)
#pragma unroll
            for (int r = 0; r < 4; r++) acc[mt][nt][r] = 0.0f;

#pragma unroll
    for (int kst = 0; kst < 2; kst++) {
        int kb = kst * 16;
        unsigned af[4][4], bfr[2][4];
#pragma unroll
        for (int mt = 0; mt < 4; mt++)
            ldsm4(af[mt], qs + (warp * 64 + mt * 16 + al_row) * EQS + kb + al_col);
#pragma unroll
        for (int p = 0; p < 2; p++)
            ldsm4(bfr[p], ks + (p * 16 + bl_row) * EQS + kb + bl_col);
#pragma unroll
        for (int mt = 0; mt < 4; mt++)
#pragma unroll
            for (int nt = 0; nt < 4; nt++)
                mma16(acc[mt][nt], af[mt], bfr[nt >> 1] + (nt & 1) * 2);
    }

    // stage output (overwrite q region) then coalesced store
    __syncthreads();
    __half* os = smem_h;               // 512 x 32 compact
#pragma unroll
    for (int mt = 0; mt < 4; mt++)
#pragma unroll
        for (int nt = 0; nt < 4; nt++) {
            int row = warp * 64 + mt * 16 + g;
            int col = nt * 8 + 2 * t;
            *(__half2*)&os[row * 32 + col] =
                __floats2half2_rn(acc[mt][nt][0], acc[mt][nt][1]);
            *(__half2*)&os[(row + 8) * 32 + col] =
                __floats2half2_rn(acc[mt][nt][2], acc[mt][nt][3]);
        }
    __syncthreads();

    __half* pg = g_preh + (size_t)(b * NTOK + chunk * 512) * NC + head * 32;
#pragma unroll
    for (int j = 0; j < 8; j++) {
        int ci = tid + 256 * j;            // 0..2047 chunks
        int row = ci >> 2;
        int hc = (ci & 3) << 3;
        *(uint4*)&pg[(size_t)row * NC + hc] = *(uint4*)&os[row * 32 + hc];
    }
}

// ---------------- K4: depthwise conv (smem v tile) + gating, adds to pre -------
extern __shared__ __align__(16) __half s_vt[];   // [nrows][64][32] halves (dynamic)

template <int KSZ>
__device__ __forceinline__ void conv_head(const __half* __restrict__ qg,   // stride QLD
                                          __half* __restrict__ pg,         // stride NC
                                          const __half* __restrict__ vt,
                                          const float* __restrict__ wsrc,
                                          float biasv) {
    const int P = KSZ / 2;

    float wreg[KSZ * KSZ];
#pragma unroll
    for (int i = 0; i < KSZ * KSZ; i++) wreg[i] = wsrc[i];

    float win[KSZ][KSZ];
#pragma unroll
    for (int dy = 0; dy < KSZ; dy++)
#pragma unroll
        for (int j = 0; j < KSZ; j++) win[dy][j] = 0.0f;

#pragma unroll
    for (int xx = 0; xx < P; xx++) {
#pragma unroll
        for (int dy = 0; dy < KSZ; dy++)
            win[dy][xx] = __half2float(vt[dy * 2048 + xx * 32]);
    }

    for (int xb = 0; xb < IMG; xb += KSZ) {
#pragma unroll
        for (int xi = 0; xi < KSZ; xi++) {
            int x = xb + xi;
            if (x < IMG) {                       // IMG % KSZ != 0: guard the tail
                const int slot_new = (xi + P) % KSZ;
                int xn = x + P;
                if (xn < IMG) {
#pragma unroll
                    for (int dy = 0; dy < KSZ; dy++)
                        win[dy][slot_new] = __half2float(vt[dy * 2048 + xn * 32]);
                } else {
#pragma unroll
                    for (int dy = 0; dy < KSZ; dy++) win[dy][slot_new] = 0.0f;
                }

                float q = __half2float(qg[(size_t)x * QLD]);
                float prev = __half2float(pg[(size_t)x * NC]);

                float acc = biasv;
#pragma unroll
                for (int dy = 0; dy < KSZ; dy++)
#pragma unroll
                    for (int dx = 0; dx < KSZ; dx++) {
                        const int slot = (xi + dx + 2 * KSZ - P) % KSZ;
                        acc += win[dy][slot] * wreg[dy * KSZ + dx];
                    }

                pg[(size_t)x * NC] = __float2half_rn(prev + q * acc);
            }
        }
    }
}

__global__ __launch_bounds__(256, 2) void k_conv_att(const float* __restrict__ w3,
                                                     const float* __restrict__ b3,
                                                     const float* __restrict__ w5,
                                                     const float* __restrict__ b5,
                                                     const float* __restrict__ w7,
                                                     const float* __restrict__ b7) {
    int yt = blockIdx.x;
    int head = blockIdx.y;
    int b = blockIdx.z;
    int lane = threadIdx.x & 31, w = threadIdx.x >> 5;
    int tid = threadIdx.x;

    __shared__ float bias_s[32];

    int P = (head < 2) ? 1 : (head < 5) ? 2 : 3;
    int nrows = 8 + 2 * P;
    int y0 = yt * 8;

    // fill v halo tile (zero-padded outside image)
    const __half* vglob = g_qkvh + (size_t)b * NTOK * QLD + 512 + head * 32;
    for (int idx = tid; idx < nrows * 64 * 16; idx += 256) {
        int rr = idx >> 10;
        int rem = idx & 1023;
        int xx = rem >> 4;
        int cc2 = (rem & 15) << 1;
        int yy = y0 - P + rr;
        __half2 val = __float2half2_rn(0.0f);
        if ((unsigned)yy < (unsigned)IMG)
            val = *(const __half2*)&vglob[(size_t)(yy * IMG + xx) * QLD + cc2];
        *(__half2*)&s_vt[(rr * 64 + xx) * 32 + cc2] = val;
    }

    int chb;
    const float* wp;
    const float* bp;
    if (head < 2)      { wp = w3; bp = b3; chb = head * 32; }
    else if (head < 5) { wp = w5; bp = b5; chb = head * 32 - 64; }
    else               { wp = w7; bp = b7; chb = head * 32 - 160; }
    int ntap = (head < 2) ? 9 : (head < 5) ? 25 : 49;
    if (tid < 32) bias_s[tid] = bp[chb + tid];
    __syncthreads();

    int y = y0 + w;
    const __half* qg = g_qkvh + (size_t)(b * NTOK + y * IMG) * QLD + head * 32 + lane;
    __half* pg = g_preh + (size_t)(b * NTOK + y * IMG) * NC + head * 32 + lane;
    const __half* vt = s_vt + (size_t)w * 2048 + lane;
    const float* wsrc = wp + (size_t)(chb + lane) * ntap;
    float biasv = bias_s[lane];

    if (head < 2)      conv_head<3>(qg, pg, vt, wsrc, biasv);
    else if (head < 5) conv_head<5>(qg, pg, vt, wsrc, biasv);
    else               conv_head<7>(qg, pg, vt, wsrc, biasv);
}

// ---------------- launch -------------------------------------------------------
extern "C" void kernel_launch(void* const* d_in, const int* in_sizes, int n_in,
                              void* d_out, int out_size) {
    const float* x      = (const float*)d_in[0];
    const float* qkv_w  = (const float*)d_in[1];
    const float* proj_w = (const float*)d_in[2];
    const float* proj_b = (const float*)d_in[3];
    const float* gamma  = (const float*)d_in[4];
    const float* beta   = (const float*)d_in[5];
    const float* w3     = (const float*)d_in[6];
    const float* b3     = (const float*)d_in[7];
    const float* w5     = (const float*)d_in[8];
    const float* b5     = (const float*)d_in[9];
    const float* w7     = (const float*)d_in[10];
    const float* b7     = (const float*)d_in[11];
    float* out = (float*)d_out;

    void *p_xg, *p_qkv, *p_pre, *p_wq, *p_wp;
    cudaGetSymbolAddress(&p_xg, g_xgh);
    cudaGetSymbolAddress(&p_qkv, g_qkvh);
    cudaGetSymbolAddress(&p_pre, g_preh);
    cudaGetSymbolAddress(&p_wq, g_wqh);
    cudaGetSymbolAddress(&p_wp, g_wph);

    static int smem_set = 0;
    const int SMEM_BYTES = NSTG * 2 * BM * SSTH * 2;   // 110592
    const int SMEM_CONV = 14 * 64 * 32 * 2;            // 57344 (dynamic v tile)
    const int SMEM_EFF = (512 * EQS + 32 * EQS) * 2;   // 43520
    if (!smem_set) {
        cudaFuncSetAttribute(k_gemm_fp16<true>,
                             cudaFuncAttributeMaxDynamicSharedMemorySize, SMEM_BYTES);
        cudaFuncSetAttribute(k_gemm_fp16<false>,
                             cudaFuncAttributeMaxDynamicSharedMemorySize, SMEM_BYTES);
        cudaFuncSetAttribute(k_conv_att,
                             cudaFuncAttributeMaxDynamicSharedMemorySize, SMEM_CONV);
        cudaFuncSetAttribute(k_eff,
                             cudaFuncAttributeMaxDynamicSharedMemorySize, SMEM_EFF);
        smem_set = 1;
    }

    // 0. BN+hardswish -> fp16 AND weights -> fp16
    k_prep<<<PREP_BN_BLOCKS + (QLD * NC + 255) / 256, 256>>>(x, gamma, beta,
                                                             qkv_w, proj_w);

    // 1. qkv = xg @ qkv_w^T   [32768 x 768], K=256
    k_gemm_fp16<true><<<dim3(QLD / BN, NB * NTOK / BM), 256, SMEM_BYTES>>>(
        (const __half*)p_xg, (const __half*)p_wq, p_qkv,
        NB * NTOK, QLD, NC, nullptr);

    // 2. kv partials + sum(exp(k))
    k_kv<<<dim3(KVCH, 64), 256>>>();

    // 3. eff = q @ kv^T (tensor cores, kv reduction fused) -> g_preh
    k_eff<<<dim3(8, 64), 256, SMEM_EFF>>>();

    // 4. conv + gating, accumulate into g_preh
    k_conv_att<<<dim3(8, 8, 8), 256, SMEM_CONV>>>(w3, b3, w5, b5, w7, b7);

    // 5. out = pre @ proj_w^T + proj_b   [32768 x 256]
    k_gemm_fp16<false><<<dim3(NC / BN, NB * NTOK / BM), 256, SMEM_BYTES>>>(
        (const __half*)p_pre, (const __half*)p_wp, out,
        NB * NTOK, NC, NC, proj_b);
}

// round 15
// speedup vs baseline: 3.6260x; 1.0013x over previous
#include <cuda_runtime.h>
#include <cuda_fp16.h>
#include <math.h>

#define NB 8
#define NTOK 4096
#define NC 256
#define NH 8
#define CHD 32
#define IMG 64
#define QLD 768   // qkv row stride (3*C), in elements
#define KVCH 16   // kv token chunks (256 tokens each)

// ---------------- scratch (device globals; no allocation allowed) -------------
__device__ __half g_xgh[NB * NTOK * NC];         // fp16 BN+hardswish
__device__ __half g_qkvh[NB * NTOK * 3 * NC];    // fp16 qkv
__device__ float g_csump[KVCH * NB * NH * CHD];  // per-chunk sum(exp(k))
__device__ float g_kvp[KVCH * NB * NH * CHD * CHD];
__device__ __half g_kvh[NB * NH * CHD * CHD];    // normalized+scaled kv^T fp16
__device__ __half g_preh[NB * NTOK * NC];        // fp16 pre-proj
__device__ __half g_wqh[QLD * NC];               // fp16 qkv_w
__device__ __half g_wph[NC * NC];                // fp16 proj_w

// ---------------- K0: BN+hardswish -> fp16  AND  weights -> fp16 (one launch) ---
#define PREP_BN_BLOCKS 8192   // NB*NTOK*NC/4/256
__global__ __launch_bounds__(256) void k_prep(const float* __restrict__ x,
                                              const float* __restrict__ gamma,
                                              const float* __restrict__ beta,
                                              const float* __restrict__ wq,
                                              const float* __restrict__ wp) {
    if (blockIdx.x < PREP_BN_BLOCKS) {
        int i = blockIdx.x * 256 + threadIdx.x;    // float4 index
        float4 v = ((const float4*)x)[i];
        int c0 = (i & 63) * 4;
        const float inv = rsqrtf(1.0f + 1e-5f);
        float* f = (float*)&v;
        __half o[4];
#pragma unroll
        for (int j = 0; j < 4; j++) {
            float xb = f[j] * (gamma[c0 + j] * inv) + beta[c0 + j];
            o[j] = __float2half_rn(xb * fminf(fmaxf(xb + 3.0f, 0.0f), 6.0f) * (1.0f / 6.0f));
        }
        *(uint2*)&g_xgh[(size_t)i * 4] = *(uint2*)o;
    } else {
        int i = (blockIdx.x - PREP_BN_BLOCKS) * 256 + threadIdx.x;
        if (i < QLD * NC) g_wqh[i] = __float2half_rn(wq[i]);
        if (i < NC * NC)  g_wph[i] = __float2half_rn(wp[i]);
    }
}

// ---------------- shared MMA helpers --------------------------------------------
__device__ __forceinline__ void cpa16(void* dst, const void* src) {
    unsigned d = (unsigned)__cvta_generic_to_shared(dst);
    asm volatile("cp.async.cg.shared.global [%0], [%1], 16;\n" :: "r"(d), "l"(src));
}
__device__ __forceinline__ void cp_commit() { asm volatile("cp.async.commit_group;\n"); }

__device__ __forceinline__ void ldsm4(unsigned* r, const __half* p) {
    unsigned a = (unsigned)__cvta_generic_to_shared(p);
    asm volatile("ldmatrix.sync.aligned.m8n8.x4.shared.b16 {%0,%1,%2,%3}, [%4];"
                 : "=r"(r[0]), "=r"(r[1]), "=r"(r[2]), "=r"(r[3]) : "r"(a));
}
__device__ __forceinline__ void ldsm4t(unsigned* r, const __half* p) {
    unsigned a = (unsigned)__cvta_generic_to_shared(p);
    asm volatile("ldmatrix.sync.aligned.m8n8.x4.trans.shared.b16 {%0,%1,%2,%3}, [%4];"
                 : "=r"(r[0]), "=r"(r[1]), "=r"(r[2]), "=r"(r[3]) : "r"(a));
}

__device__ __forceinline__ void mma16(float* c, const unsigned* a, const unsigned* b) {
    asm volatile(
        "mma.sync.aligned.m16n8k16.row.col.f32.f16.f16.f32 "
        "{%0,%1,%2,%3}, {%4,%5,%6,%7}, {%8,%9}, {%0,%1,%2,%3};"
        : "+f"(c[0]), "+f"(c[1]), "+f"(c[2]), "+f"(c[3])
        : "r"(a[0]), "r"(a[1]), "r"(a[2]), "r"(a[3]), "r"(b[0]), "r"(b[1]));
}

// ---------------- fp16 tensor-core GEMM, 3-stage pipeline ----------------------
#define BM 128
#define BN 128
#define BK 64     // halves per chunk (128 bytes per row)
#define SSTH 72   // smem row stride (halves): 144B -> 16B-aligned, LDSM conflict-free
#define NSTG 3
#define OST 136   // epilogue smem tile row stride (halves): conflict-free STS

extern __shared__ __align__(16) __half smem_h[];

// HOUT=true: fp16 output via smem-staged coalesced stores (bias must be null).
// HOUT=false: fp32 output direct (+bias).
template <bool HOUT>
__global__ __launch_bounds__(256, 2) void k_gemm_fp16(const __half* __restrict__ A,
                                                      const __half* __restrict__ W,
                                                      void* __restrict__ Cv,
                                                      int M, int Nd, int K,
                                                      const float* __restrict__ bias) {
    int tid = threadIdx.x;
    int m0 = blockIdx.y * BM, n0 = blockIdx.x * BN;
    int warp = tid >> 5, lane = tid & 31;
    int g = lane >> 2, t = lane & 3;
    int wm = (warp >> 2) * 64;
    int wn = (warp & 3) * 32;

    int al_row = lane & 15;
    int al_col = (lane >> 4) << 3;
    int bl_row = (lane & 7) + ((lane >> 4) << 3);
    int bl_col = ((lane >> 3) & 1) << 3;

    float acc[4][4][4];
#pragma unroll
    for (int mt = 0; mt < 4; mt++)
#pragma unroll
        for (int nt = 0; nt < 4; nt++)
#pragma unroll
            for (int r = 0; r < 4; r++) acc[mt][nt][r] = 0.0f;

    const int nch = K >> 6;

    auto issue = [&](int c, int stage) {
        if (c < nch) {
            __half* as = smem_h + stage * (2 * BM * SSTH);
            __half* bs = as + BM * SSTH;
            int k0 = c * BK;
#pragma unroll
            for (int j = 0; j < 4; j++) {
                int ci = tid + 256 * j;
                int row = ci >> 3;
                int kc = (ci & 7) << 3;
                cpa16(as + row * SSTH + kc, A + (size_t)(m0 + row) * K + k0 + kc);
                cpa16(bs + row * SSTH + kc, W + (size_t)(n0 + row) * K + k0 + kc);
            }
        }
        cp_commit();
    };

    issue(0, 0);
    issue(1, 1);

    for (int c = 0; c < nch; c++) {
        asm volatile("cp.async.wait_group 1;\n");
        __syncthreads();
        issue(c + 2, (c + 2) % NSTG);

        const __half* as = smem_h + (c % NSTG) * (2 * BM * SSTH);
        const __half* bs = as + BM * SSTH;
#pragma unroll
        for (int ks = 0; ks < 4; ks++) {
            int kb = ks * 16;
            unsigned af[4][4], bfr[2][4];
#pragma unroll
            for (int mt = 0; mt < 4; mt++)
                ldsm4(af[mt], as + (wm + mt * 16 + al_row) * SSTH + kb + al_col);
#pragma unroll
            for (int p = 0; p < 2; p++)
                ldsm4(bfr[p], bs + (wn + p * 16 + bl_row) * SSTH + kb + bl_col);
#pragma unroll
            for (int mt = 0; mt < 4; mt++)
#pragma unroll
                for (int nt = 0; nt < 4; nt++)
                    mma16(acc[mt][nt], af[mt], bfr[nt >> 1] + (nt & 1) * 2);
        }
    }

    if (HOUT) {
        __syncthreads();
        __half* os = smem_h;
#pragma unroll
        for (int mt = 0; mt < 4; mt++)
#pragma unroll
            for (int nt = 0; nt < 4; nt++) {
                int col = wn + nt * 8 + 2 * t;
                int row = wm + mt * 16 + g;
                *(__half2*)&os[row * OST + col] =
                    __floats2half2_rn(acc[mt][nt][0], acc[mt][nt][1]);
                *(__half2*)&os[(row + 8) * OST + col] =
                    __floats2half2_rn(acc[mt][nt][2], acc[mt][nt][3]);
            }
        __syncthreads();
        __half* Ch = (__half*)Cv;
#pragma unroll
        for (int j = 0; j < 8; j++) {
            int ci = tid + 256 * j;
            int row = ci >> 4;
            int hc = (ci & 15) << 3;
            *(uint4*)&Ch[(size_t)(m0 + row) * Nd + n0 + hc] =
                *(uint4*)&os[row * OST + hc];
        }
    } else {
#pragma unroll
        for (int mt = 0; mt < 4; mt++)
#pragma unroll
            for (int nt = 0; nt < 4; nt++) {
                int col = n0 + wn + nt * 8 + 2 * t;
                float b0 = bias ? bias[col] : 0.0f;
                float b1 = bias ? bias[col + 1] : 0.0f;
                int row0 = m0 + wm + mt * 16 + g;
                float* Cf = (float*)Cv;
                float2 o0 = make_float2(acc[mt][nt][0] + b0, acc[mt][nt][1] + b1);
                float2 o1 = make_float2(acc[mt][nt][2] + b0, acc[mt][nt][3] + b1);
                *(float2*)&Cf[(size_t)row0 * Nd + col] = o0;
                *(float2*)&Cf[(size_t)(row0 + 8) * Nd + col] = o1;
            }
    }
}

// ---------------- K3: kv = exp(k)^T v via tensor cores (trans ldmatrix) --------
// Both operands token-major -> ldmatrix.x4.trans. M=k-chan 32, N=v-chan 32, K=tokens.
#define EKS 40    // smem row stride (halves): 80B -> all 8 rows in distinct 16B groups
__global__ __launch_bounds__(256) void k_kv() {
    int chunk = blockIdx.x;            // 0..KVCH-1 (256 tokens each)
    int bh = blockIdx.y;
    int b = bh >> 3, head = bh & 7;

    __shared__ __align__(16) float red[8192];     // 32 KB; fp16 tiles aliased inside
    __shared__ float sred[32 * 17];
    __half* ek = (__half*)red;                    // [128][EKS]
    __half* vsm = ek + 128 * EKS;                 // [128][EKS]

    int tid = threadIdx.x;
    int warp = tid >> 5, lane = tid & 31;
    int g = lane >> 2, t = lane & 3;
    int c2 = (tid & 15) << 1;          // fill: channel pair
    int jj = tid >> 4;                 // fill: row group 0..15

    // trans-ldmatrix lane addressing
    int ta_row = (lane & 7) + ((lane >> 4) << 3);   // A(ek^T): token row
    int ta_col = ((lane >> 3) & 1) << 3;            // A: channel offset
    int tb_row = lane & 15;                         // B(v): token row
    int tb_col = (lane >> 4) << 3;                  // B: channel offset

    const __half* base = g_qkvh + (size_t)(b * NTOK + chunk * (NTOK / KVCH)) * QLD + head * 32;

    float acc[2][4][4];
#pragma unroll
    for (int mt = 0; mt < 2; mt++)
#pragma unroll
        for (int nt = 0; nt < 4; nt++)
#pragma unroll
            for (int r = 0; r < 4; r++) acc[mt][nt][r] = 0.0f;
    float sA = 0.0f, sB = 0.0f;

    for (int tch = 0; tch < (NTOK / KVCH) / 128; tch++) {
        const __half* tb = base + (size_t)tch * 128 * QLD;
#pragma unroll
        for (int it = 0; it < 8; it++) {
            int r = jj + it * 16;
            size_t off = (size_t)r * QLD + c2;
            float2 fk = __half22float2(*(const __half2*)&tb[off + 256]);
            float e0 = __expf(fk.x), e1 = __expf(fk.y);
            sA += e0; sB += e1;
            *(__half2*)&ek[r * EKS + c2] = __floats2half2_rn(e0, e1);
            *(__half2*)&vsm[r * EKS + c2] = *(const __half2*)&tb[off + 512];
        }
        __syncthreads();

        // warp w consumes tokens [w*16, w*16+16)
        int kr = warp * 16;
        unsigned af[2][4], bfr[2][4];
#pragma unroll
        for (int mt = 0; mt < 2; mt++)
            ldsm4t(af[mt], ek + (kr + ta_row) * EKS + mt * 16 + ta_col);
#pragma unroll
        for (int p = 0; p < 2; p++)
            ldsm4t(bfr[p], vsm + (kr + tb_row) * EKS + p * 16 + tb_col);
#pragma unroll
        for (int mt = 0; mt < 2; mt++)
#pragma unroll
            for (int nt = 0; nt < 4; nt++)
                mma16(acc[mt][nt], af[mt], bfr[nt >> 1] + (nt & 1) * 2);
        __syncthreads();                 // tiles free after this
    }

    sred[c2 * 17 + jj] = sA;
    sred[(c2 + 1) * 17 + jj] = sB;

    // per-warp 32x32 partials into red (aliases freed tiles)
#pragma unroll
    for (int mt = 0; mt < 2; mt++)
#pragma unroll
        for (int nt = 0; nt < 4; nt++)
#pragma unroll
            for (int r = 0; r < 4; r++) {
                int m = mt * 16 + g + ((r >> 1) << 3);   // k-channel
                int n = nt * 8 + 2 * t + (r & 1);        // v-channel
                red[warp * 1024 + m * 32 + n] = acc[mt][nt][r];
            }
    __syncthreads();

    for (int i = tid; i < 1024; i += 256) {
        float s = 0.0f;
#pragma unroll
        for (int gg = 0; gg < 8; gg++) s += red[gg * 1024 + i];
        g_kvp[((size_t)chunk * 64 + bh) * 1024 + i] = s;
    }
    if (tid < 32) {
        float ss = 0.0f;
#pragma unroll
        for (int j = 0; j < 16; j++) ss += sred[tid * 17 + j];
        g_csump[((size_t)chunk * 64 + bh) * 32 + tid] = ss;
    }
}

// ---------------- K3b: reduce kv partials -> normalized/scaled kv^T fp16 -------
__global__ __launch_bounds__(128) void k_kvred() {
    int s = blockIdx.x;                // 0..7 slice
    int bh = blockIdx.y;
    int tid = threadIdx.x;
    __shared__ float cinv[32];
    const float scale = 0.1767766952966369f;   // 32^-0.5

    if (tid < 32) {
        float ss = 0.0f;
#pragma unroll
        for (int ch = 0; ch < KVCH; ch++)
            ss += g_csump[((size_t)ch * 64 + bh) * 32 + tid];
        cinv[tid] = scale / ss;
    }
    __syncthreads();

    int i = s * 128 + tid;             // 0..1023
    float sum = 0.0f;
#pragma unroll
    for (int ch = 0; ch < KVCH; ch++)
        sum += g_kvp[((size_t)ch * 64 + bh) * 1024 + i];
    int k = i >> 5, v = i & 31;
    g_kvh[bh * 1024 + v * 32 + k] = __float2half_rn(sum * cinv[k]);   // transposed
}

// ---------------- K3c: eff = q @ kvh^T via tensor cores -> g_preh --------------
#define EQS 40    // q smem row stride (halves)
__global__ __launch_bounds__(256, 2) void k_eff() {
    int chunk = blockIdx.x;            // 0..7 (512 tokens each)
    int bh = blockIdx.y;
    int b = bh >> 3, head = bh & 7;

    __half* qs = smem_h;               // 512 x EQS
    __half* ks = smem_h + 512 * EQS;   // 32 x EQS (row=v, col=k)

    int tid = threadIdx.x;
    int warp = tid >> 5, lane = tid & 31;
    int g = lane >> 2, t = lane & 3;

    // stage q: 512 rows x 32 halves = 2048 16B chunks (4 per row)
    const __half* qg = g_qkvh + (size_t)(b * NTOK + chunk * 512) * QLD + head * 32;
#pragma unroll
    for (int j = 0; j < 8; j++) {
        int ci = tid + 256 * j;
        int row = ci >> 2;
        int hc = (ci & 3) << 3;
        cpa16(qs + row * EQS + hc, qg + (size_t)row * QLD + hc);
    }
    // stage kvh: 32 rows x 32 halves = 128 chunks (4 per row)
    if (tid < 128) {
        int row = tid >> 2;
        int hc = (tid & 3) << 3;
        cpa16(ks + row * EQS + hc, g_kvh + bh * 1024 + row * 32 + hc);
    }
    cp_commit();
    asm volatile("cp.async.wait_group 0;\n");
    __syncthreads();

    int al_row = lane & 15;
    int al_col = (lane >> 4) << 3;
    int bl_row = (lane & 7) + ((lane >> 4) << 3);
    int bl_col = ((lane >> 3) & 1) << 3;

    float acc[4][4][4];
#pragma unroll
    for (int mt = 0; mt < 4; mt++)
#pragma unroll
        for (int nt = 0; nt < 4; nt++)
#pragma unroll
            for (int r = 0; r < 4; r++) acc[mt][nt][r] = 0.0f;

#pragma unroll
    for (int kst = 0; kst < 2; kst++) {
        int kb = kst * 16;
        unsigned af[4][4], bfr[2][4];
#pragma unroll
        for (int mt = 0; mt < 4; mt++)
            ldsm4(af[mt], qs + (warp * 64 + mt * 16 + al_row) * EQS + kb + al_col);
#pragma unroll
        for (int p = 0; p < 2; p++)
            ldsm4(bfr[p], ks + (p * 16 + bl_row) * EQS + kb + bl_col);
#pragma unroll
        for (int mt = 0; mt < 4; mt++)
#pragma unroll
            for (int nt = 0; nt < 4; nt++)
                mma16(acc[mt][nt], af[mt], bfr[nt >> 1] + (nt & 1) * 2);
    }

    __syncthreads();
    __half* os = smem_h;               // 512 x 32 compact
#pragma unroll
    for (int mt = 0; mt < 4; mt++)
#pragma unroll
        for (int nt = 0; nt < 4; nt++) {
            int row = warp * 64 + mt * 16 + g;
            int col = nt * 8 + 2 * t;
            *(__half2*)&os[row * 32 + col] =
                __floats2half2_rn(acc[mt][nt][0], acc[mt][nt][1]);
            *(__half2*)&os[(row + 8) * 32 + col] =
                __floats2half2_rn(acc[mt][nt][2], acc[mt][nt][3]);
        }
    __syncthreads();

    __half* pg = g_preh + (size_t)(b * NTOK + chunk * 512) * NC + head * 32;
#pragma unroll
    for (int j = 0; j < 8; j++) {
        int ci = tid + 256 * j;
        int row = ci >> 2;
        int hc = (ci & 3) << 3;
        *(uint4*)&pg[(size_t)row * NC + hc] = *(uint4*)&os[row * 32 + hc];
    }
}

// ---------------- K4: depthwise conv (smem v tile) + gating, adds to pre -------
extern __shared__ __align__(16) __half s_vt[];   // [nrows][64][32] halves (dynamic)

template <int KSZ>
__device__ __forceinline__ void conv_head(const __half* __restrict__ qg,   // stride QLD
                                          __half* __restrict__ pg,         // stride NC
                                          const __half* __restrict__ vt,
                                          const float* __restrict__ wsrc,
                                          float biasv) {
    const int P = KSZ / 2;

    float wreg[KSZ * KSZ];
#pragma unroll
    for (int i = 0; i < KSZ * KSZ; i++) wreg[i] = wsrc[i];

    float win[KSZ][KSZ];
#pragma unroll
    for (int dy = 0; dy < KSZ; dy++)
#pragma unroll
        for (int j = 0; j < KSZ; j++) win[dy][j] = 0.0f;

#pragma unroll
    for (int xx = 0; xx < P; xx++) {
#pragma unroll
        for (int dy = 0; dy < KSZ; dy++)
            win[dy][xx] = __half2float(vt[dy * 2048 + xx * 32]);
    }

    for (int xb = 0; xb < IMG; xb += KSZ) {
#pragma unroll
        for (int xi = 0; xi < KSZ; xi++) {
            int x = xb + xi;
            if (x < IMG) {                       // IMG % KSZ != 0: guard the tail
                const int slot_new = (xi + P) % KSZ;
                int xn = x + P;
                if (xn < IMG) {
#pragma unroll
                    for (int dy = 0; dy < KSZ; dy++)
                        win[dy][slot_new] = __half2float(vt[dy * 2048 + xn * 32]);
                } else {
#pragma unroll
                    for (int dy = 0; dy < KSZ; dy++) win[dy][slot_new] = 0.0f;
                }

                float q = __half2float(qg[(size_t)x * QLD]);
                float prev = __half2float(pg[(size_t)x * NC]);

                float acc = biasv;
#pragma unroll
                for (int dy = 0; dy < KSZ; dy++)
#pragma unroll
                    for (int dx = 0; dx < KSZ; dx++) {
                        const int slot = (xi + dx + 2 * KSZ - P) % KSZ;
                        acc += win[dy][slot] * wreg[dy * KSZ + dx];
                    }

                pg[(size_t)x * NC] = __float2half_rn(prev + q * acc);
            }
        }
    }
}

__global__ __launch_bounds__(256, 2) void k_conv_att(const float* __restrict__ w3,
                                                     const float* __restrict__ b3,
                                                     const float* __restrict__ w5,
                                                     const float* __restrict__ b5,
                                                     const float* __restrict__ w7,
                                                     const float* __restrict__ b7) {
    int yt = blockIdx.x;
    int head = blockIdx.y;
    int b = blockIdx.z;
    int lane = threadIdx.x & 31, w = threadIdx.x >> 5;
    int tid = threadIdx.x;

    __shared__ float bias_s[32];

    int P = (head < 2) ? 1 : (head < 5) ? 2 : 3;
    int nrows = 8 + 2 * P;
    int y0 = yt * 8;

    const __half* vglob = g_qkvh + (size_t)b * NTOK * QLD + 512 + head * 32;
    for (int idx = tid; idx < nrows * 64 * 16; idx += 256) {
        int rr = idx >> 10;
        int rem = idx & 1023;
        int xx = rem >> 4;
        int cc2 = (rem & 15) << 1;
        int yy = y0 - P + rr;
        __half2 val = __float2half2_rn(0.0f);
        if ((unsigned)yy < (unsigned)IMG)
            val = *(const __half2*)&vglob[(size_t)(yy * IMG + xx) * QLD + cc2];
        *(__half2*)&s_vt[(rr * 64 + xx) * 32 + cc2] = val;
    }

    int chb;
    const float* wp;
    const float* bp;
    if (head < 2)      { wp = w3; bp = b3; chb = head * 32; }
    else if (head < 5) { wp = w5; bp = b5; chb = head * 32 - 64; }
    else               { wp = w7; bp = b7; chb = head * 32 - 160; }
    int ntap = (head < 2) ? 9 : (head < 5) ? 25 : 49;
    if (tid < 32) bias_s[tid] = bp[chb + tid];
    __syncthreads();

    int y = y0 + w;
    const __half* qg = g_qkvh + (size_t)(b * NTOK + y * IMG) * QLD + head * 32 + lane;
    __half* pg = g_preh + (size_t)(b * NTOK + y * IMG) * NC + head * 32 + lane;
    const __half* vt = s_vt + (size_t)w * 2048 + lane;
    const float* wsrc = wp + (size_t)(chb + lane) * ntap;
    float biasv = bias_s[lane];

    if (head < 2)      conv_head<3>(qg, pg, vt, wsrc, biasv);
    else if (head < 5) conv_head<5>(qg, pg, vt, wsrc, biasv);
    else               conv_head<7>(qg, pg, vt, wsrc, biasv);
}

// ---------------- launch -------------------------------------------------------
extern "C" void kernel_launch(void* const* d_in, const int* in_sizes, int n_in,
                              void* d_out, int out_size) {
    const float* x      = (const float*)d_in[0];
    const float* qkv_w  = (const float*)d_in[1];
    const float* proj_w = (const float*)d_in[2];
    const float* proj_b = (const float*)d_in[3];
    const float* gamma  = (const float*)d_in[4];
    const float* beta   = (const float*)d_in[5];
    const float* w3     = (const float*)d_in[6];
    const float* b3     = (const float*)d_in[7];
    const float* w5     = (const float*)d_in[8];
    const float* b5     = (const float*)d_in[9];
    const float* w7     = (const float*)d_in[10];
    const float* b7     = (const float*)d_in[11];
    float* out = (float*)d_out;

    void *p_xg, *p_qkv, *p_pre, *p_wq, *p_wp;
    cudaGetSymbolAddress(&p_xg, g_xgh);
    cudaGetSymbolAddress(&p_qkv, g_qkvh);
    cudaGetSymbolAddress(&p_pre, g_preh);
    cudaGetSymbolAddress(&p_wq, g_wqh);
    cudaGetSymbolAddress(&p_wp, g_wph);

    static int smem_set = 0;
    const int SMEM_BYTES = NSTG * 2 * BM * SSTH * 2;   // 110592
    const int SMEM_CONV = 14 * 64 * 32 * 2;            // 57344 (dynamic v tile)
    const int SMEM_EFF = (512 * EQS + 32 * EQS) * 2;   // 43520
    if (!smem_set) {
        cudaFuncSetAttribute(k_gemm_fp16<true>,
                             cudaFuncAttributeMaxDynamicSharedMemorySize, SMEM_BYTES);
        cudaFuncSetAttribute(k_gemm_fp16<false>,
                             cudaFuncAttributeMaxDynamicSharedMemorySize, SMEM_BYTES);
        cudaFuncSetAttribute(k_conv_att,
                             cudaFuncAttributeMaxDynamicSharedMemorySize, SMEM_CONV);
        cudaFuncSetAttribute(k_eff,
                             cudaFuncAttributeMaxDynamicSharedMemorySize, SMEM_EFF);
        smem_set = 1;
    }

    // 0. BN+hardswish -> fp16 AND weights -> fp16
    k_prep<<<PREP_BN_BLOCKS + (QLD * NC + 255) / 256, 256>>>(x, gamma, beta,
                                                             qkv_w, proj_w);

    // 1. qkv = xg @ qkv_w^T   [32768 x 768], K=256
    k_gemm_fp16<true><<<dim3(QLD / BN, NB * NTOK / BM), 256, SMEM_BYTES>>>(
        (const __half*)p_xg, (const __half*)p_wq, p_qkv,
        NB * NTOK, QLD, NC, nullptr);

    // 2. kv partials via tensor cores + sum(exp(k))
    k_kv<<<dim3(KVCH, 64), 256>>>();

    // 3. reduce + normalize + scale + transpose kv -> fp16 (full-chip grid)
    k_kvred<<<dim3(8, 64), 128>>>();

    // 4. eff = q @ kvh^T (tensor cores) -> g_preh
    k_eff<<<dim3(8, 64), 256, SMEM_EFF>>>();

    // 5. conv + gating, accumulate into g_preh
    k_conv_att<<<dim3(8, 8, 8), 256, SMEM_CONV>>>(w3, b3, w5, b5, w7, b7);

    // 6. out = pre @ proj_w^T + proj_b   [32768 x 256]
    k_gemm_fp16<false><<<dim3(NC / BN, NB * NTOK / BM), 256, SMEM_BYTES>>>(
        (const __half*)p_pre, (const __half*)p_wp, out,
        NB * NTOK, NC, NC, proj_b);
}